// round 6
// baseline (speedup 1.0000x reference)
#include <cuda_runtime.h>
#include <cuda_bf16.h>
#include <cstdint>

#define B_  4
#define S_  1024
#define D_  512
#define H_  8
#define DK_ 64
#define MTOT (B_*S_)          // 4096 rows
#define NELE (B_*S_*D_)       // 2,097,152

// Scratch (static device globals — allowed; no cudaMalloc anywhere)
// Q/K/V live as bf16 hi/lo planes (hi + lo == fp32 value to ~2^-17).
__device__ __nv_bfloat16 g_qh[NELE], g_ql[NELE];   // pre-scaled by 1/8
__device__ __nv_bfloat16 g_kh[NELE], g_kl[NELE];
__device__ __nv_bfloat16 g_vh[NELE], g_vl[NELE];
__device__ float g_attn[NELE];
__device__ float g_bias[(size_t)B_*S_*S_];   // bias with mask folded in (-1e9 on masked)
__device__ float g_Ct, g_Cd;
__device__ int   g_bzero;

// ---------------------------------------------------------------------------
// helpers
// ---------------------------------------------------------------------------
__device__ __forceinline__ void mma_bf16(float c[4],
    uint32_t a0, uint32_t a1, uint32_t a2, uint32_t a3,
    uint32_t b0, uint32_t b1)
{
    asm volatile(
        "mma.sync.aligned.m16n8k16.row.col.f32.bf16.bf16.f32 "
        "{%0,%1,%2,%3},{%4,%5,%6,%7},{%8,%9},{%0,%1,%2,%3};"
        : "+f"(c[0]), "+f"(c[1]), "+f"(c[2]), "+f"(c[3])
        : "r"(a0), "r"(a1), "r"(a2), "r"(a3), "r"(b0), "r"(b1));
}

__device__ __forceinline__ void ldsm_x4(uint32_t& r0, uint32_t& r1,
                                        uint32_t& r2, uint32_t& r3, uint32_t addr)
{
    asm volatile("ldmatrix.sync.aligned.m8n8.x4.shared.b16 {%0,%1,%2,%3}, [%4];"
        : "=r"(r0), "=r"(r1), "=r"(r2), "=r"(r3) : "r"(addr));
}

__device__ __forceinline__ void ldsm_x4_t(uint32_t& r0, uint32_t& r1,
                                          uint32_t& r2, uint32_t& r3, uint32_t addr)
{
    asm volatile("ldmatrix.sync.aligned.m8n8.x4.trans.shared.b16 {%0,%1,%2,%3}, [%4];"
        : "=r"(r0), "=r"(r1), "=r"(r2), "=r"(r3) : "r"(addr));
}

__device__ __forceinline__ void ldsm_x2_t(uint32_t& r0, uint32_t& r1, uint32_t addr)
{
    asm volatile("ldmatrix.sync.aligned.m8n8.x2.trans.shared.b16 {%0,%1}, [%2];"
        : "=r"(r0), "=r"(r1) : "r"(addr));
}

__device__ __forceinline__ void cpa16(uint32_t dst, const void* src) {
    asm volatile("cp.async.cg.shared.global [%0], [%1], 16;" :: "r"(dst), "l"(src));
}
__device__ __forceinline__ void cp_commit() {
    asm volatile("cp.async.commit_group;");
}
template<int N> __device__ __forceinline__ void cp_wait() {
    asm volatile("cp.async.wait_group %0;" :: "n"(N));
}

__device__ __forceinline__ void pack_hilo(float x, float y, uint32_t& hi, uint32_t& lo) {
    __nv_bfloat162 h = __floats2bfloat162_rn(x, y);
    float2 f = __bfloat1622float2(h);
    __nv_bfloat162 l = __floats2bfloat162_rn(x - f.x, y - f.y);
    hi = *reinterpret_cast<uint32_t*>(&h);
    lo = *reinterpret_cast<uint32_t*>(&l);
}

// ---------------------------------------------------------------------------
// Fused GEMM (up to 3 problems via blockIdx.z), bf16 TC with hi/lo split:
//   R = (A[M,K] @ W[K,N] + bias[N]) * (z==0 ? scale0 : 1)
//   bf16_out: write R as hi/lo bf16 planes (H,L); else fp32 to C.
// ---------------------------------------------------------------------------
#define AKP 40
#define BNP 136

__global__ __launch_bounds__(256) void gemm_qkv(
    const float* __restrict__ A0, const float* __restrict__ A1, const float* __restrict__ A2,
    const float* __restrict__ W0, const float* __restrict__ W1, const float* __restrict__ W2,
    const float* __restrict__ b0v, const float* __restrict__ b1v, const float* __restrict__ b2v,
    float* __restrict__ C0,
    __nv_bfloat16* __restrict__ H0, __nv_bfloat16* __restrict__ L0,
    __nv_bfloat16* __restrict__ H1, __nv_bfloat16* __restrict__ L1,
    __nv_bfloat16* __restrict__ H2, __nv_bfloat16* __restrict__ L2,
    int M, int N, int K, float scale0, int bf16_out)
{
    __shared__ __nv_bfloat16 Ash[2][128 * AKP];
    __shared__ __nv_bfloat16 Bsh[2][32 * BNP];

    const float* A;  const float* Wm; const float* bias;
    __nv_bfloat16 *Ho, *Lo;
    if (blockIdx.z == 0)      { A = A0; Wm = W0; bias = b0v; Ho = H0; Lo = L0; }
    else if (blockIdx.z == 1) { A = A1; Wm = W1; bias = b1v; Ho = H1; Lo = L1; }
    else                      { A = A2; Wm = W2; bias = b2v; Ho = H2; Lo = L2; }
    const float osc = (blockIdx.z == 0) ? scale0 : 1.f;

    const int t = threadIdx.x;
    const int lane = t & 31, wid = t >> 5;
    const int warp_m = wid & 3, warp_n = wid >> 2;
    const int m_w = warp_m * 32, n_w = warp_n * 64;
    const int bm = blockIdx.y * 128, bn = blockIdx.x * 128;
    const int gid = lane >> 2, tig = lane & 3;

    const int b_n0 = (t & 63) * 2;
    const int b_kq = (t >> 6) * 8;

    float acc[2][8][4];
    #pragma unroll
    for (int mt = 0; mt < 2; mt++)
        #pragma unroll
        for (int nt = 0; nt < 8; nt++)
            #pragma unroll
            for (int e = 0; e < 4; e++) acc[mt][nt][e] = 0.f;

    float4 a_pre[4];
    float2 b_pre[8];
    #pragma unroll
    for (int r = 0; r < 4; r++) {
        int e = t + r * 256;
        int row = e >> 3, col4 = (e & 7) << 2;
        a_pre[r] = *(const float4*)&A[(size_t)(bm + row) * K + col4];
    }
    #pragma unroll
    for (int kk = 0; kk < 8; kk++)
        b_pre[kk] = *(const float2*)&Wm[(size_t)(b_kq + kk) * N + bn + b_n0];

    for (int k0 = 0; k0 < K; k0 += 32) {
        #pragma unroll
        for (int r = 0; r < 4; r++) {
            int e = t + r * 256;
            int row = e >> 3, col4 = (e & 7) << 2;
            float4 v = a_pre[r];
            __nv_bfloat162 h0 = __floats2bfloat162_rn(v.x, v.y);
            __nv_bfloat162 h1 = __floats2bfloat162_rn(v.z, v.w);
            float2 f0 = __bfloat1622float2(h0);
            float2 f1 = __bfloat1622float2(h1);
            __nv_bfloat162 l0 = __floats2bfloat162_rn(v.x - f0.x, v.y - f0.y);
            __nv_bfloat162 l1 = __floats2bfloat162_rn(v.z - f1.x, v.w - f1.y);
            *(__nv_bfloat162*)&Ash[0][row * AKP + col4]     = h0;
            *(__nv_bfloat162*)&Ash[0][row * AKP + col4 + 2] = h1;
            *(__nv_bfloat162*)&Ash[1][row * AKP + col4]     = l0;
            *(__nv_bfloat162*)&Ash[1][row * AKP + col4 + 2] = l1;
        }
        #pragma unroll
        for (int kk = 0; kk < 8; kk++) {
            int k = b_kq + kk;
            float2 v = b_pre[kk];
            __nv_bfloat162 h = __floats2bfloat162_rn(v.x, v.y);
            float2 f = __bfloat1622float2(h);
            __nv_bfloat162 l = __floats2bfloat162_rn(v.x - f.x, v.y - f.y);
            *(__nv_bfloat162*)&Bsh[0][k * BNP + b_n0] = h;
            *(__nv_bfloat162*)&Bsh[1][k * BNP + b_n0] = l;
        }
        __syncthreads();

        if (k0 + 32 < K) {
            #pragma unroll
            for (int r = 0; r < 4; r++) {
                int e = t + r * 256;
                int row = e >> 3, col4 = (e & 7) << 2;
                a_pre[r] = *(const float4*)&A[(size_t)(bm + row) * K + k0 + 32 + col4];
            }
            #pragma unroll
            for (int kk = 0; kk < 8; kk++)
                b_pre[kk] = *(const float2*)&Wm[(size_t)(k0 + 32 + b_kq + kk) * N + bn + b_n0];
        }

        #pragma unroll
        for (int kb = 0; kb < 32; kb += 16) {
            uint32_t af[2][2][4];
            #pragma unroll
            for (int mt = 0; mt < 2; mt++) {
                const int arow = m_w + mt * 16 + (lane & 15);
                const int acol = kb + ((lane >> 4) << 3);
                #pragma unroll
                for (int p = 0; p < 2; p++) {
                    uint32_t addr = (uint32_t)__cvta_generic_to_shared(
                        &Ash[p][arow * AKP + acol]);
                    ldsm_x4(af[mt][p][0], af[mt][p][1], af[mt][p][2], af[mt][p][3], addr);
                }
            }
            #pragma unroll
            for (int nt = 0; nt < 8; nt++) {
                const int brow = kb + (lane & 15);
                const int bcol = n_w + nt * 8;
                uint32_t bh0, bh1, bl0, bl1;
                uint32_t addrh = (uint32_t)__cvta_generic_to_shared(
                    &Bsh[0][brow * BNP + bcol]);
                uint32_t addrl = (uint32_t)__cvta_generic_to_shared(
                    &Bsh[1][brow * BNP + bcol]);
                ldsm_x2_t(bh0, bh1, addrh);
                ldsm_x2_t(bl0, bl1, addrl);
                #pragma unroll
                for (int mt = 0; mt < 2; mt++) {
                    mma_bf16(acc[mt][nt], af[mt][0][0], af[mt][0][1],
                             af[mt][0][2], af[mt][0][3], bh0, bh1);
                    mma_bf16(acc[mt][nt], af[mt][1][0], af[mt][1][1],
                             af[mt][1][2], af[mt][1][3], bh0, bh1);
                    mma_bf16(acc[mt][nt], af[mt][0][0], af[mt][0][1],
                             af[mt][0][2], af[mt][0][3], bl0, bl1);
                }
            }
        }
        __syncthreads();
    }

    // ---- epilogue
    #pragma unroll
    for (int mt = 0; mt < 2; mt++) {
        const int row0 = bm + m_w + mt * 16 + gid;
        #pragma unroll
        for (int nt = 0; nt < 8; nt++) {
            const int col = bn + n_w + nt * 8 + tig * 2;
            float2 bb = *(const float2*)&bias[col];
            float v0 = (acc[mt][nt][0] + bb.x) * osc;
            float v1 = (acc[mt][nt][1] + bb.y) * osc;
            float v2 = (acc[mt][nt][2] + bb.x) * osc;
            float v3 = (acc[mt][nt][3] + bb.y) * osc;
            if (bf16_out) {
                uint32_t h01, l01, h23, l23;
                pack_hilo(v0, v1, h01, l01);
                pack_hilo(v2, v3, h23, l23);
                *(uint32_t*)&Ho[(size_t)row0 * N + col]       = h01;
                *(uint32_t*)&Lo[(size_t)row0 * N + col]       = l01;
                *(uint32_t*)&Ho[(size_t)(row0 + 8) * N + col] = h23;
                *(uint32_t*)&Lo[(size_t)(row0 + 8) * N + col] = l23;
            } else {
                *(float2*)&C0[(size_t)row0 * N + col]       = make_float2(v0, v1);
                *(float2*)&C0[(size_t)(row0 + 8) * N + col] = make_float2(v2, v3);
            }
        }
    }
}

// ---------------------------------------------------------------------------
// Prep: detect all-zero biases; precompute collapsed coefficients
// ---------------------------------------------------------------------------
__global__ void prep_kernel(const float* __restrict__ tm_w, const float* __restrict__ tm_b,
                            const float* __restrict__ dm_w, const float* __restrict__ dm_b,
                            const float* __restrict__ td_w)
{
    const int l = threadIdx.x;   // 32 threads
    float ct = 0.f, cd = 0.f;
    bool z = true;
    #pragma unroll
    for (int m = l; m < 64; m += 32) {
        z = z && (tm_b[m] == 0.f) && (dm_b[m] == 0.f);
        ct += 0.5f * td_w[m] * fmaxf(tm_w[m], 0.f);
        cd += 0.5f * td_w[m] * fmaxf(dm_w[m], 0.f);
    }
    unsigned bz = __ballot_sync(0xffffffffu, z);
    #pragma unroll
    for (int o = 16; o; o >>= 1) {
        ct += __shfl_xor_sync(0xffffffffu, ct, o);
        cd += __shfl_xor_sync(0xffffffffu, cd, o);
    }
    if (l == 0) { g_Ct = ct; g_Cd = cd; g_bzero = (bz == 0xffffffffu); }
}

// ---------------------------------------------------------------------------
// Fused bias + mask. Fast path (biases all zero): 2 FMAs per element.
// ---------------------------------------------------------------------------
__global__ __launch_bounds__(256) void bias_mask_kernel(
    const float* __restrict__ tmat, const float* __restrict__ dmat,
    const int*   __restrict__ mask,
    const float* __restrict__ tm_w, const float* __restrict__ tm_b,
    const float* __restrict__ dm_w, const float* __restrict__ dm_b,
    const float* __restrict__ td_w, const float* __restrict__ td_b)
{
    const int t = threadIdx.x;
    const float tdb = td_b[0];
    const float E = 2.718281828459045f;

    const size_t base = ((size_t)blockIdx.x * 256 + t) * 4;
    float4 u  = *(const float4*)(tmat + base);
    float4 w  = *(const float4*)(dmat + base);
    int4   mk = *(const int4*)(mask + base);

    float tv[4] = { 1.f / __logf(E + u.x), 1.f / __logf(E + u.y),
                    1.f / __logf(E + u.z), 1.f / __logf(E + u.w) };
    float dv[4] = { 1.f / __logf(E + w.x), 1.f / __logf(E + w.y),
                    1.f / __logf(E + w.z), 1.f / __logf(E + w.w) };
    float acc[4];

    if (g_bzero) {
        const float Ct = g_Ct, Cd = g_Cd;
        #pragma unroll
        for (int i = 0; i < 4; i++)
            acc[i] = fmaf(tv[i], Ct, fmaf(dv[i], Cd, tdb));
    } else {
        __shared__ float sp[5][64];
        if (t < 64) {
            sp[0][t] = tm_w[t];
            sp[1][t] = tm_b[t];
            sp[2][t] = dm_w[t];
            sp[3][t] = dm_b[t];
            sp[4][t] = td_w[t] * 0.5f;
        }
        __syncthreads();
        #pragma unroll
        for (int i = 0; i < 4; i++) acc[i] = tdb;
        #pragma unroll 8
        for (int m = 0; m < 64; m++) {
            const float tw = sp[0][m], tb = sp[1][m];
            const float dw = sp[2][m], db = sp[3][m];
            const float ww = sp[4][m];
            #pragma unroll
            for (int i = 0; i < 4; i++) {
                float rt = fmaxf(tv[i] * tw + tb, 0.f);
                float rd = fmaxf(dv[i] * dw + db, 0.f);
                acc[i] += ww * (rt + rd);
            }
        }
    }

    float4 o;
    o.x = (mk.x == 1) ? -1e9f : acc[0];
    o.y = (mk.y == 1) ? -1e9f : acc[1];
    o.z = (mk.z == 1) ? -1e9f : acc[2];
    o.w = (mk.w == 1) ? -1e9f : acc[3];
    *(float4*)(g_bias + base) = o;
}

// ---------------------------------------------------------------------------
// Flash attention, bf16x3 tensor cores, all-ldmatrix operand feeding,
// P kept in registers (score C-frag == PV A-frag layout).
// smem: 10 bf16 planes of 64 x 64 (row stride 72 elems = 144B, conflict-free
// for ldmatrix and 16B-aligned for cp.async). K/V double-buffered.
// ---------------------------------------------------------------------------
#define PS 72
#define PE (64*PS)
#define SMEM_ATTN (10*PE*2)

__global__ __launch_bounds__(128) void attn_bf16()
{
    extern __shared__ __nv_bfloat16 sm[];

    const int qt = blockIdx.x, h = blockIdx.y, b = blockIdx.z;
    const int t = threadIdx.x;
    const int w = t >> 5, lane = t & 31;
    const int gid = lane >> 2, tig = lane & 3;
    const int q0 = qt * 64, hoff = h * DK_;
    const int tr = w * 16 + gid;              // this thread's first q row
    const int m_idx = lane >> 3, rin = lane & 7;

    // ---- prologue: Q planes + K/V tile0 planes
    #pragma unroll
    for (int i = 0; i < 4; i++) {
        int c = t + i * 128;
        int row = c >> 3, col = (c & 7) * 8;
        size_t gq = (size_t)(b * S_ + q0 + row) * D_ + hoff + col;
        size_t gk = (size_t)(b * S_ + row) * D_ + hoff + col;
        uint32_t so = row * PS + col;
        cpa16((uint32_t)__cvta_generic_to_shared(&sm[0*PE + so]), &g_qh[gq]);
        cpa16((uint32_t)__cvta_generic_to_shared(&sm[1*PE + so]), &g_ql[gq]);
        cpa16((uint32_t)__cvta_generic_to_shared(&sm[2*PE + so]), &g_kh[gk]);
        cpa16((uint32_t)__cvta_generic_to_shared(&sm[3*PE + so]), &g_kl[gk]);
        cpa16((uint32_t)__cvta_generic_to_shared(&sm[6*PE + so]), &g_vh[gk]);
        cpa16((uint32_t)__cvta_generic_to_shared(&sm[7*PE + so]), &g_vl[gk]);
    }
    cp_commit();
    cp_wait<0>();
    __syncthreads();

    // ---- Q fragments, loop-invariant, held in registers
    uint32_t qf[4][2][4];   // [d16-step][plane][reg]
    #pragma unroll
    for (int d8 = 0; d8 < 4; d8++)
        #pragma unroll
        for (int p = 0; p < 2; p++) {
            uint32_t a = (uint32_t)__cvta_generic_to_shared(
                &sm[p*PE + (w * 16 + (lane & 15)) * PS + d8 * 16 + ((lane >> 4) << 3)]);
            ldsm_x4(qf[d8][p][0], qf[d8][p][1], qf[d8][p][2], qf[d8][p][3], a);
        }

    float m0 = -1e30f, m1 = -1e30f, l0 = 0.f, l1 = 0.f;
    float oacc[8][4];
    #pragma unroll
    for (int nt = 0; nt < 8; nt++)
        #pragma unroll
        for (int e = 0; e < 4; e++) oacc[nt][e] = 0.f;

    const float* biasA = g_bias + ((size_t)b * S_ + q0 + tr) * S_;
    const float* biasB = biasA + (size_t)8 * S_;

    for (int kt = 0; kt < 16; kt++) {
        const int buf = kt & 1;
        if (kt < 15) {
            const int k1 = (kt + 1) * 64;
            const int KHn = (2 + 2 * (buf ^ 1)) * PE;
            const int VHn = (6 + 2 * (buf ^ 1)) * PE;
            #pragma unroll
            for (int i = 0; i < 4; i++) {
                int c = t + i * 128;
                int row = c >> 3, col = (c & 7) * 8;
                size_t g = (size_t)(b * S_ + k1 + row) * D_ + hoff + col;
                uint32_t so = row * PS + col;
                cpa16((uint32_t)__cvta_generic_to_shared(&sm[KHn + so]),      &g_kh[g]);
                cpa16((uint32_t)__cvta_generic_to_shared(&sm[KHn + PE + so]), &g_kl[g]);
                cpa16((uint32_t)__cvta_generic_to_shared(&sm[VHn + so]),      &g_vh[g]);
                cpa16((uint32_t)__cvta_generic_to_shared(&sm[VHn + PE + so]), &g_vl[g]);
            }
            cp_commit();
            cp_wait<1>();
        } else {
            cp_wait<0>();
        }
        __syncthreads();

        const int KH = (2 + 2 * buf) * PE;
        const int VH = (6 + 2 * buf) * PE;
        const int k0 = kt * 64;

        // ---- scores S = (Q/8) @ K^T : 3-term bf16 split
        float sacc[8][4];
        #pragma unroll
        for (int nt = 0; nt < 8; nt++)
            #pragma unroll
            for (int e = 0; e < 4; e++) sacc[nt][e] = 0.f;

        #pragma unroll
        for (int d8 = 0; d8 < 4; d8++) {
            #pragma unroll
            for (int p = 0; p < 4; p++) {
                uint32_t boff = (p * 16 + ((m_idx & 1) << 3) + rin) * PS
                              + d8 * 16 + ((m_idx >> 1) << 3);
                uint32_t kh0, kh1, kh2, kh3, kl0, kl1, kl2, kl3;
                ldsm_x4(kh0, kh1, kh2, kh3,
                        (uint32_t)__cvta_generic_to_shared(&sm[KH + boff]));
                ldsm_x4(kl0, kl1, kl2, kl3,
                        (uint32_t)__cvta_generic_to_shared(&sm[KH + PE + boff]));
                mma_bf16(sacc[2*p],   qf[d8][0][0], qf[d8][0][1], qf[d8][0][2], qf[d8][0][3], kh0, kh2);
                mma_bf16(sacc[2*p],   qf[d8][1][0], qf[d8][1][1], qf[d8][1][2], qf[d8][1][3], kh0, kh2);
                mma_bf16(sacc[2*p],   qf[d8][0][0], qf[d8][0][1], qf[d8][0][2], qf[d8][0][3], kl0, kl2);
                mma_bf16(sacc[2*p+1], qf[d8][0][0], qf[d8][0][1], qf[d8][0][2], qf[d8][0][3], kh1, kh3);
                mma_bf16(sacc[2*p+1], qf[d8][1][0], qf[d8][1][1], qf[d8][1][2], qf[d8][1][3], kh1, kh3);
                mma_bf16(sacc[2*p+1], qf[d8][0][0], qf[d8][0][1], qf[d8][0][2], qf[d8][0][3], kl1, kl3);
            }
        }

        // ---- + bias (mask folded as -1e9) + row max
        float mx0 = -1e30f, mx1 = -1e30f;
        #pragma unroll
        for (int nt = 0; nt < 8; nt++) {
            float2 ba = *(const float2*)&biasA[k0 + nt * 8 + tig * 2];
            float2 bb = *(const float2*)&biasB[k0 + nt * 8 + tig * 2];
            sacc[nt][0] += ba.x;
            sacc[nt][1] += ba.y;
            sacc[nt][2] += bb.x;
            sacc[nt][3] += bb.y;
            mx0 = fmaxf(mx0, fmaxf(sacc[nt][0], sacc[nt][1]));
            mx1 = fmaxf(mx1, fmaxf(sacc[nt][2], sacc[nt][3]));
        }
        mx0 = fmaxf(mx0, __shfl_xor_sync(0xffffffffu, mx0, 1));
        mx0 = fmaxf(mx0, __shfl_xor_sync(0xffffffffu, mx0, 2));
        mx1 = fmaxf(mx1, __shfl_xor_sync(0xffffffffu, mx1, 1));
        mx1 = fmaxf(mx1, __shfl_xor_sync(0xffffffffu, mx1, 2));

        const float mn0 = fmaxf(m0, mx0), mn1 = fmaxf(m1, mx1);
        const float c0 = __expf(m0 - mn0), c1 = __expf(m1 - mn1);
        m0 = mn0; m1 = mn1;

        float rs0 = 0.f, rs1 = 0.f;
        #pragma unroll
        for (int nt = 0; nt < 8; nt++) {
            sacc[nt][0] = __expf(sacc[nt][0] - mn0);
            sacc[nt][1] = __expf(sacc[nt][1] - mn0);
            sacc[nt][2] = __expf(sacc[nt][2] - mn1);
            sacc[nt][3] = __expf(sacc[nt][3] - mn1);
            rs0 += sacc[nt][0] + sacc[nt][1];
            rs1 += sacc[nt][2] + sacc[nt][3];
        }
        rs0 += __shfl_xor_sync(0xffffffffu, rs0, 1);
        rs0 += __shfl_xor_sync(0xffffffffu, rs0, 2);
        rs1 += __shfl_xor_sync(0xffffffffu, rs1, 1);
        rs1 += __shfl_xor_sync(0xffffffffu, rs1, 2);

        l0 = l0 * c0 + rs0;
        l1 = l1 * c1 + rs1;
        #pragma unroll
        for (int nt = 0; nt < 8; nt++) {
            oacc[nt][0] *= c0; oacc[nt][1] *= c0;
            oacc[nt][2] *= c1; oacc[nt][3] *= c1;
        }

        // ---- pack P into bf16 hi/lo A-fragments (in registers, no smem)
        uint32_t pah[4][4], pal[4][4];   // [j16-step][reg]
        #pragma unroll
        for (int j8 = 0; j8 < 4; j8++) {
            const float* sA = sacc[2 * j8];
            const float* sB = sacc[2 * j8 + 1];
            pack_hilo(sA[0], sA[1], pah[j8][0], pal[j8][0]);
            pack_hilo(sA[2], sA[3], pah[j8][1], pal[j8][1]);
            pack_hilo(sB[0], sB[1], pah[j8][2], pal[j8][2]);
            pack_hilo(sB[2], sB[3], pah[j8][3], pal[j8][3]);
        }

        // ---- O += P @ V : 3-term bf16 split, V via ldmatrix.x4.trans
        #pragma unroll
        for (int j8 = 0; j8 < 4; j8++) {
            #pragma unroll
            for (int p = 0; p < 4; p++) {
                uint32_t boff = (j8 * 16 + ((m_idx & 1) << 3) + rin) * PS
                              + p * 16 + ((m_idx >> 1) << 3);
                uint32_t vh0, vh1, vh2, vh3, vl0, vl1, vl2, vl3;
                ldsm_x4_t(vh0, vh1, vh2, vh3,
                          (uint32_t)__cvta_generic_to_shared(&sm[VH + boff]));
                ldsm_x4_t(vl0, vl1, vl2, vl3,
                          (uint32_t)__cvta_generic_to_shared(&sm[VH + PE + boff]));
                mma_bf16(oacc[2*p],   pah[j8][0], pah[j8][1], pah[j8][2], pah[j8][3], vh0, vh1);
                mma_bf16(oacc[2*p],   pal[j8][0], pal[j8][1], pal[j8][2], pal[j8][3], vh0, vh1);
                mma_bf16(oacc[2*p],   pah[j8][0], pah[j8][1], pah[j8][2], pah[j8][3], vl0, vl1);
                mma_bf16(oacc[2*p+1], pah[j8][0], pah[j8][1], pah[j8][2], pah[j8][3], vh2, vh3);
                mma_bf16(oacc[2*p+1], pal[j8][0], pal[j8][1], pal[j8][2], pal[j8][3], vh2, vh3);
                mma_bf16(oacc[2*p+1], pah[j8][0], pah[j8][1], pah[j8][2], pah[j8][3], vl2, vl3);
            }
        }
        __syncthreads();   // all reads of buf done before it is refilled
    }

    // ---- epilogue: normalize, write [B,S,D]
    const float inv0 = 1.f / l0, inv1 = 1.f / l1;
    float* out0 = &g_attn[(size_t)(b * S_ + q0 + tr) * D_ + hoff];
    float* out1 = out0 + (size_t)8 * D_;
    #pragma unroll
    for (int nt = 0; nt < 8; nt++) {
        float2 o0 = make_float2(oacc[nt][0] * inv0, oacc[nt][1] * inv0);
        float2 o1 = make_float2(oacc[nt][2] * inv1, oacc[nt][3] * inv1);
        *(float2*)&out0[nt * 8 + tig * 2] = o0;
        *(float2*)&out1[nt * 8 + tig * 2] = o1;
    }
}

// ---------------------------------------------------------------------------
extern "C" void kernel_launch(void* const* d_in, const int* in_sizes, int n_in,
                              void* d_out, int out_size)
{
    const float* Q     = (const float*)d_in[0];
    const float* K     = (const float*)d_in[1];
    const float* V     = (const float*)d_in[2];
    const float* tmat  = (const float*)d_in[3];
    const float* dmat  = (const float*)d_in[4];
    const int*   mask  = (const int*)  d_in[5];
    const float* Wq    = (const float*)d_in[6];
    const float* bq    = (const float*)d_in[7];
    const float* Wk    = (const float*)d_in[8];
    const float* bk    = (const float*)d_in[9];
    const float* Wv    = (const float*)d_in[10];
    const float* bv    = (const float*)d_in[11];
    const float* Wo    = (const float*)d_in[12];
    const float* bo    = (const float*)d_in[13];
    const float* tm_w  = (const float*)d_in[14];
    const float* tm_b  = (const float*)d_in[15];
    const float* dm_w  = (const float*)d_in[16];
    const float* dm_b  = (const float*)d_in[17];
    const float* td_w  = (const float*)d_in[18];
    const float* td_b  = (const float*)d_in[19];
    float* out = (float*)d_out;

    float* ab;
    cudaGetSymbolAddress((void**)&ab, g_attn);
    __nv_bfloat16 *qh, *ql, *kh, *kl, *vh, *vl;
    cudaGetSymbolAddress((void**)&qh, g_qh);
    cudaGetSymbolAddress((void**)&ql, g_ql);
    cudaGetSymbolAddress((void**)&kh, g_kh);
    cudaGetSymbolAddress((void**)&kl, g_kl);
    cudaGetSymbolAddress((void**)&vh, g_vh);
    cudaGetSymbolAddress((void**)&vl, g_vl);

    prep_kernel<<<1, 32>>>(tm_w, tm_b, dm_w, dm_b, td_w);

    // fused Q/K/V projections -> bf16 hi/lo planes (Q pre-scaled by 1/8)
    gemm_qkv<<<dim3(D_ / 128, MTOT / 128, 3), 256>>>(
        Q, K, V, Wq, Wk, Wv, bq, bk, bv,
        out /*unused*/, qh, ql, kh, kl, vh, vl,
        MTOT, D_, D_, 0.125f, 1);

    bias_mask_kernel<<<(B_ * S_ * S_) / 1024, 256>>>(
        tmat, dmat, mask, tm_w, tm_b, dm_w, dm_b, td_w, td_b);

    cudaFuncSetAttribute(attn_bf16,
                         cudaFuncAttributeMaxDynamicSharedMemorySize, SMEM_ATTN);
    attn_bf16<<<dim3(S_ / 64, H_, B_), 128, SMEM_ATTN>>>();

    // output projection: fp32 in (g_attn), fp32 out
    gemm_qkv<<<dim3(D_ / 128, MTOT / 128, 1), 256>>>(
        ab, ab, ab, Wo, Wo, Wo, bo, bo, bo,
        out, qh, ql, kh, kl, vh, vl,
        MTOT, D_, D_, 1.f, 0);
}

// round 7
// speedup vs baseline: 1.1252x; 1.1252x over previous
#include <cuda_runtime.h>
#include <cuda_bf16.h>
#include <cuda_fp16.h>
#include <cstdint>

#define B_  4
#define S_  1024
#define D_  512
#define H_  8
#define DK_ 64
#define MTOT (B_*S_)          // 4096 rows
#define NELE (B_*S_*D_)       // 2,097,152

// Scratch (static device globals — allowed; no cudaMalloc anywhere)
// Q/K as fp16 hi/lo planes (hi + lo == fp32 value to ~2^-22); V single fp16.
__device__ __half g_qh[NELE], g_ql[NELE];   // pre-scaled by 1/8
__device__ __half g_kh[NELE], g_kl[NELE];
__device__ __half g_vh[NELE], g_vl[NELE];   // g_vl written but unused
__device__ float g_attn[NELE];
__device__ float g_bias[(size_t)B_*S_*S_];  // bias with mask folded in (-1e9 on masked)
__device__ float g_Ct, g_Cd;
__device__ int   g_bzero;

// ---------------------------------------------------------------------------
// helpers
// ---------------------------------------------------------------------------
__device__ __forceinline__ void mma_bf16(float c[4],
    uint32_t a0, uint32_t a1, uint32_t a2, uint32_t a3,
    uint32_t b0, uint32_t b1)
{
    asm volatile(
        "mma.sync.aligned.m16n8k16.row.col.f32.bf16.bf16.f32 "
        "{%0,%1,%2,%3},{%4,%5,%6,%7},{%8,%9},{%0,%1,%2,%3};"
        : "+f"(c[0]), "+f"(c[1]), "+f"(c[2]), "+f"(c[3])
        : "r"(a0), "r"(a1), "r"(a2), "r"(a3), "r"(b0), "r"(b1));
}

__device__ __forceinline__ void mma_f16(float c[4],
    uint32_t a0, uint32_t a1, uint32_t a2, uint32_t a3,
    uint32_t b0, uint32_t b1)
{
    asm volatile(
        "mma.sync.aligned.m16n8k16.row.col.f32.f16.f16.f32 "
        "{%0,%1,%2,%3},{%4,%5,%6,%7},{%8,%9},{%0,%1,%2,%3};"
        : "+f"(c[0]), "+f"(c[1]), "+f"(c[2]), "+f"(c[3])
        : "r"(a0), "r"(a1), "r"(a2), "r"(a3), "r"(b0), "r"(b1));
}

__device__ __forceinline__ void ldsm_x4(uint32_t& r0, uint32_t& r1,
                                        uint32_t& r2, uint32_t& r3, uint32_t addr)
{
    asm volatile("ldmatrix.sync.aligned.m8n8.x4.shared.b16 {%0,%1,%2,%3}, [%4];"
        : "=r"(r0), "=r"(r1), "=r"(r2), "=r"(r3) : "r"(addr));
}

__device__ __forceinline__ void ldsm_x4_t(uint32_t& r0, uint32_t& r1,
                                          uint32_t& r2, uint32_t& r3, uint32_t addr)
{
    asm volatile("ldmatrix.sync.aligned.m8n8.x4.trans.shared.b16 {%0,%1,%2,%3}, [%4];"
        : "=r"(r0), "=r"(r1), "=r"(r2), "=r"(r3) : "r"(addr));
}

__device__ __forceinline__ void ldsm_x2_t(uint32_t& r0, uint32_t& r1, uint32_t addr)
{
    asm volatile("ldmatrix.sync.aligned.m8n8.x2.trans.shared.b16 {%0,%1}, [%2];"
        : "=r"(r0), "=r"(r1) : "r"(addr));
}

__device__ __forceinline__ void cpa16(uint32_t dst, const void* src) {
    asm volatile("cp.async.cg.shared.global [%0], [%1], 16;" :: "r"(dst), "l"(src));
}
__device__ __forceinline__ void cp_commit() {
    asm volatile("cp.async.commit_group;");
}
template<int N> __device__ __forceinline__ void cp_wait() {
    asm volatile("cp.async.wait_group %0;" :: "n"(N));
}

// fp16 hi/lo split pack of a float pair
__device__ __forceinline__ void pack_hilo_h(float x, float y, uint32_t& hi, uint32_t& lo) {
    __half2 h = __floats2half2_rn(x, y);
    float2 f = __half22float2(h);
    __half2 l = __floats2half2_rn(x - f.x, y - f.y);
    hi = *reinterpret_cast<uint32_t*>(&h);
    lo = *reinterpret_cast<uint32_t*>(&l);
}

// ---------------------------------------------------------------------------
// Fused GEMM (up to 3 problems via blockIdx.z), bf16 TC with hi/lo split:
//   R = (A[M,K] @ W[K,N] + bias[N]) * (z==0 ? scale0 : 1)
//   fp16_out: write R as fp16 hi/lo planes (H,L); else fp32 to C0.
// ---------------------------------------------------------------------------
#define AKP 40
#define BNP 136

__global__ __launch_bounds__(256) void gemm_qkv(
    const float* __restrict__ A0, const float* __restrict__ A1, const float* __restrict__ A2,
    const float* __restrict__ W0, const float* __restrict__ W1, const float* __restrict__ W2,
    const float* __restrict__ b0v, const float* __restrict__ b1v, const float* __restrict__ b2v,
    float* __restrict__ C0,
    __half* __restrict__ H0, __half* __restrict__ L0,
    __half* __restrict__ H1, __half* __restrict__ L1,
    __half* __restrict__ H2, __half* __restrict__ L2,
    int M, int N, int K, float scale0, int fp16_out)
{
    __shared__ __nv_bfloat16 Ash[2][128 * AKP];
    __shared__ __nv_bfloat16 Bsh[2][32 * BNP];

    const float* A;  const float* Wm; const float* bias;
    __half *Ho, *Lo;
    if (blockIdx.z == 0)      { A = A0; Wm = W0; bias = b0v; Ho = H0; Lo = L0; }
    else if (blockIdx.z == 1) { A = A1; Wm = W1; bias = b1v; Ho = H1; Lo = L1; }
    else                      { A = A2; Wm = W2; bias = b2v; Ho = H2; Lo = L2; }
    const float osc = (blockIdx.z == 0) ? scale0 : 1.f;

    const int t = threadIdx.x;
    const int lane = t & 31, wid = t >> 5;
    const int warp_m = wid & 3, warp_n = wid >> 2;
    const int m_w = warp_m * 32, n_w = warp_n * 64;
    const int bm = blockIdx.y * 128, bn = blockIdx.x * 128;
    const int gid = lane >> 2, tig = lane & 3;

    const int b_n0 = (t & 63) * 2;
    const int b_kq = (t >> 6) * 8;

    float acc[2][8][4];
    #pragma unroll
    for (int mt = 0; mt < 2; mt++)
        #pragma unroll
        for (int nt = 0; nt < 8; nt++)
            #pragma unroll
            for (int e = 0; e < 4; e++) acc[mt][nt][e] = 0.f;

    float4 a_pre[4];
    float2 b_pre[8];
    #pragma unroll
    for (int r = 0; r < 4; r++) {
        int e = t + r * 256;
        int row = e >> 3, col4 = (e & 7) << 2;
        a_pre[r] = *(const float4*)&A[(size_t)(bm + row) * K + col4];
    }
    #pragma unroll
    for (int kk = 0; kk < 8; kk++)
        b_pre[kk] = *(const float2*)&Wm[(size_t)(b_kq + kk) * N + bn + b_n0];

    for (int k0 = 0; k0 < K; k0 += 32) {
        #pragma unroll
        for (int r = 0; r < 4; r++) {
            int e = t + r * 256;
            int row = e >> 3, col4 = (e & 7) << 2;
            float4 v = a_pre[r];
            __nv_bfloat162 h0 = __floats2bfloat162_rn(v.x, v.y);
            __nv_bfloat162 h1 = __floats2bfloat162_rn(v.z, v.w);
            float2 f0 = __bfloat1622float2(h0);
            float2 f1 = __bfloat1622float2(h1);
            __nv_bfloat162 l0 = __floats2bfloat162_rn(v.x - f0.x, v.y - f0.y);
            __nv_bfloat162 l1 = __floats2bfloat162_rn(v.z - f1.x, v.w - f1.y);
            *(__nv_bfloat162*)&Ash[0][row * AKP + col4]     = h0;
            *(__nv_bfloat162*)&Ash[0][row * AKP + col4 + 2] = h1;
            *(__nv_bfloat162*)&Ash[1][row * AKP + col4]     = l0;
            *(__nv_bfloat162*)&Ash[1][row * AKP + col4 + 2] = l1;
        }
        #pragma unroll
        for (int kk = 0; kk < 8; kk++) {
            int k = b_kq + kk;
            float2 v = b_pre[kk];
            __nv_bfloat162 h = __floats2bfloat162_rn(v.x, v.y);
            float2 f = __bfloat1622float2(h);
            __nv_bfloat162 l = __floats2bfloat162_rn(v.x - f.x, v.y - f.y);
            *(__nv_bfloat162*)&Bsh[0][k * BNP + b_n0] = h;
            *(__nv_bfloat162*)&Bsh[1][k * BNP + b_n0] = l;
        }
        __syncthreads();

        if (k0 + 32 < K) {
            #pragma unroll
            for (int r = 0; r < 4; r++) {
                int e = t + r * 256;
                int row = e >> 3, col4 = (e & 7) << 2;
                a_pre[r] = *(const float4*)&A[(size_t)(bm + row) * K + k0 + 32 + col4];
            }
            #pragma unroll
            for (int kk = 0; kk < 8; kk++)
                b_pre[kk] = *(const float2*)&Wm[(size_t)(k0 + 32 + b_kq + kk) * N + bn + b_n0];
        }

        #pragma unroll
        for (int kb = 0; kb < 32; kb += 16) {
            uint32_t af[2][2][4];
            #pragma unroll
            for (int mt = 0; mt < 2; mt++) {
                const int arow = m_w + mt * 16 + (lane & 15);
                const int acol = kb + ((lane >> 4) << 3);
                #pragma unroll
                for (int p = 0; p < 2; p++) {
                    uint32_t addr = (uint32_t)__cvta_generic_to_shared(
                        &Ash[p][arow * AKP + acol]);
                    ldsm_x4(af[mt][p][0], af[mt][p][1], af[mt][p][2], af[mt][p][3], addr);
                }
            }
            #pragma unroll
            for (int nt = 0; nt < 8; nt++) {
                const int brow = kb + (lane & 15);
                const int bcol = n_w + nt * 8;
                uint32_t bh0, bh1, bl0, bl1;
                uint32_t addrh = (uint32_t)__cvta_generic_to_shared(
                    &Bsh[0][brow * BNP + bcol]);
                uint32_t addrl = (uint32_t)__cvta_generic_to_shared(
                    &Bsh[1][brow * BNP + bcol]);
                ldsm_x2_t(bh0, bh1, addrh);
                ldsm_x2_t(bl0, bl1, addrl);
                #pragma unroll
                for (int mt = 0; mt < 2; mt++) {
                    mma_bf16(acc[mt][nt], af[mt][0][0], af[mt][0][1],
                             af[mt][0][2], af[mt][0][3], bh0, bh1);
                    mma_bf16(acc[mt][nt], af[mt][1][0], af[mt][1][1],
                             af[mt][1][2], af[mt][1][3], bh0, bh1);
                    mma_bf16(acc[mt][nt], af[mt][0][0], af[mt][0][1],
                             af[mt][0][2], af[mt][0][3], bl0, bl1);
                }
            }
        }
        __syncthreads();
    }

    // ---- epilogue
    #pragma unroll
    for (int mt = 0; mt < 2; mt++) {
        const int row0 = bm + m_w + mt * 16 + gid;
        #pragma unroll
        for (int nt = 0; nt < 8; nt++) {
            const int col = bn + n_w + nt * 8 + tig * 2;
            float2 bb = *(const float2*)&bias[col];
            float v0 = (acc[mt][nt][0] + bb.x) * osc;
            float v1 = (acc[mt][nt][1] + bb.y) * osc;
            float v2 = (acc[mt][nt][2] + bb.x) * osc;
            float v3 = (acc[mt][nt][3] + bb.y) * osc;
            if (fp16_out) {
                uint32_t h01, l01, h23, l23;
                pack_hilo_h(v0, v1, h01, l01);
                pack_hilo_h(v2, v3, h23, l23);
                *(uint32_t*)&Ho[(size_t)row0 * N + col]       = h01;
                *(uint32_t*)&Lo[(size_t)row0 * N + col]       = l01;
                *(uint32_t*)&Ho[(size_t)(row0 + 8) * N + col] = h23;
                *(uint32_t*)&Lo[(size_t)(row0 + 8) * N + col] = l23;
            } else {
                *(float2*)&C0[(size_t)row0 * N + col]       = make_float2(v0, v1);
                *(float2*)&C0[(size_t)(row0 + 8) * N + col] = make_float2(v2, v3);
            }
        }
    }
}

// ---------------------------------------------------------------------------
// Prep: detect all-zero biases; precompute collapsed coefficients
// ---------------------------------------------------------------------------
__global__ void prep_kernel(const float* __restrict__ tm_w, const float* __restrict__ tm_b,
                            const float* __restrict__ dm_w, const float* __restrict__ dm_b,
                            const float* __restrict__ td_w)
{
    const int l = threadIdx.x;   // 32 threads
    float ct = 0.f, cd = 0.f;
    bool z = true;
    #pragma unroll
    for (int m = l; m < 64; m += 32) {
        z = z && (tm_b[m] == 0.f) && (dm_b[m] == 0.f);
        ct += 0.5f * td_w[m] * fmaxf(tm_w[m], 0.f);
        cd += 0.5f * td_w[m] * fmaxf(dm_w[m], 0.f);
    }
    unsigned bz = __ballot_sync(0xffffffffu, z);
    #pragma unroll
    for (int o = 16; o; o >>= 1) {
        ct += __shfl_xor_sync(0xffffffffu, ct, o);
        cd += __shfl_xor_sync(0xffffffffu, cd, o);
    }
    if (l == 0) { g_Ct = ct; g_Cd = cd; g_bzero = (bz == 0xffffffffu); }
}

// ---------------------------------------------------------------------------
// Fused bias + mask. Fast path (biases all zero): 2 FMAs per element.
// ---------------------------------------------------------------------------
__global__ __launch_bounds__(256) void bias_mask_kernel(
    const float* __restrict__ tmat, const float* __restrict__ dmat,
    const int*   __restrict__ mask,
    const float* __restrict__ tm_w, const float* __restrict__ tm_b,
    const float* __restrict__ dm_w, const float* __restrict__ dm_b,
    const float* __restrict__ td_w, const float* __restrict__ td_b)
{
    const int t = threadIdx.x;
    const float tdb = td_b[0];
    const float E = 2.718281828459045f;

    const size_t base = ((size_t)blockIdx.x * 256 + t) * 4;
    float4 u  = *(const float4*)(tmat + base);
    float4 w  = *(const float4*)(dmat + base);
    int4   mk = *(const int4*)(mask + base);

    float tv[4] = { 1.f / __logf(E + u.x), 1.f / __logf(E + u.y),
                    1.f / __logf(E + u.z), 1.f / __logf(E + u.w) };
    float dv[4] = { 1.f / __logf(E + w.x), 1.f / __logf(E + w.y),
                    1.f / __logf(E + w.z), 1.f / __logf(E + w.w) };
    float acc[4];

    if (g_bzero) {
        const float Ct = g_Ct, Cd = g_Cd;
        #pragma unroll
        for (int i = 0; i < 4; i++)
            acc[i] = fmaf(tv[i], Ct, fmaf(dv[i], Cd, tdb));
    } else {
        __shared__ float sp[5][64];
        if (t < 64) {
            sp[0][t] = tm_w[t];
            sp[1][t] = tm_b[t];
            sp[2][t] = dm_w[t];
            sp[3][t] = dm_b[t];
            sp[4][t] = td_w[t] * 0.5f;
        }
        __syncthreads();
        #pragma unroll
        for (int i = 0; i < 4; i++) acc[i] = tdb;
        #pragma unroll 8
        for (int m = 0; m < 64; m++) {
            const float tw = sp[0][m], tb = sp[1][m];
            const float dw = sp[2][m], db = sp[3][m];
            const float ww = sp[4][m];
            #pragma unroll
            for (int i = 0; i < 4; i++) {
                float rt = fmaxf(tv[i] * tw + tb, 0.f);
                float rd = fmaxf(dv[i] * dw + db, 0.f);
                acc[i] += ww * (rt + rd);
            }
        }
    }

    float4 o;
    o.x = (mk.x == 1) ? -1e9f : acc[0];
    o.y = (mk.y == 1) ? -1e9f : acc[1];
    o.z = (mk.z == 1) ? -1e9f : acc[2];
    o.w = (mk.w == 1) ? -1e9f : acc[3];
    *(float4*)(g_bias + base) = o;
}

// ---------------------------------------------------------------------------
// Flash attention, fp16 tensor cores:
//   QK^T: 3-term fp16 hi/lo split (~exact), PV: single-term fp16 (err ~2^-11).
// 8 smem planes of 64x64 fp16 (stride 72): Qh,Ql + 2 x {Kh,Kl,V} double-buffered
// = 72 KB -> 3 CTAs/SM. P stays in registers (C-frag == A-frag layout).
// ---------------------------------------------------------------------------
#define PS 72
#define PE (64*PS)
#define SMEM_ATTN (8*PE*2)

__global__ __launch_bounds__(128) void attn_f16()
{
    extern __shared__ __half sm[];

    const int qt = blockIdx.x, h = blockIdx.y, b = blockIdx.z;
    const int t = threadIdx.x;
    const int w = t >> 5, lane = t & 31;
    const int gid = lane >> 2, tig = lane & 3;
    const int q0 = qt * 64, hoff = h * DK_;
    const int tr = w * 16 + gid;              // this thread's first q row
    const int m_idx = lane >> 3, rin = lane & 7;

    // ---- prologue: Q planes + K/V tile0 planes (buf0 = planes 2,3,4)
    #pragma unroll
    for (int i = 0; i < 4; i++) {
        int c = t + i * 128;
        int row = c >> 3, col = (c & 7) * 8;
        size_t gq = (size_t)(b * S_ + q0 + row) * D_ + hoff + col;
        size_t gk = (size_t)(b * S_ + row) * D_ + hoff + col;
        uint32_t so = row * PS + col;
        cpa16((uint32_t)__cvta_generic_to_shared(&sm[0*PE + so]), &g_qh[gq]);
        cpa16((uint32_t)__cvta_generic_to_shared(&sm[1*PE + so]), &g_ql[gq]);
        cpa16((uint32_t)__cvta_generic_to_shared(&sm[2*PE + so]), &g_kh[gk]);
        cpa16((uint32_t)__cvta_generic_to_shared(&sm[3*PE + so]), &g_kl[gk]);
        cpa16((uint32_t)__cvta_generic_to_shared(&sm[4*PE + so]), &g_vh[gk]);
    }
    cp_commit();
    cp_wait<0>();
    __syncthreads();

    // ---- Q fragments, loop-invariant, held in registers
    uint32_t qf[4][2][4];   // [d16-step][plane][reg]
    #pragma unroll
    for (int d8 = 0; d8 < 4; d8++)
        #pragma unroll
        for (int p = 0; p < 2; p++) {
            uint32_t a = (uint32_t)__cvta_generic_to_shared(
                &sm[p*PE + (w * 16 + (lane & 15)) * PS + d8 * 16 + ((lane >> 4) << 3)]);
            ldsm_x4(qf[d8][p][0], qf[d8][p][1], qf[d8][p][2], qf[d8][p][3], a);
        }

    float m0 = -1e30f, m1 = -1e30f, l0 = 0.f, l1 = 0.f;
    float oacc[8][4];
    #pragma unroll
    for (int nt = 0; nt < 8; nt++)
        #pragma unroll
        for (int e = 0; e < 4; e++) oacc[nt][e] = 0.f;

    const float* biasA = g_bias + ((size_t)b * S_ + q0 + tr) * S_;
    const float* biasB = biasA + (size_t)8 * S_;

    for (int kt = 0; kt < 16; kt++) {
        const int buf = kt & 1;
        if (kt < 15) {
            const int k1 = (kt + 1) * 64;
            const int KHn = (2 + 3 * (buf ^ 1)) * PE;
            #pragma unroll
            for (int i = 0; i < 4; i++) {
                int c = t + i * 128;
                int row = c >> 3, col = (c & 7) * 8;
                size_t g = (size_t)(b * S_ + k1 + row) * D_ + hoff + col;
                uint32_t so = row * PS + col;
                cpa16((uint32_t)__cvta_generic_to_shared(&sm[KHn + so]),          &g_kh[g]);
                cpa16((uint32_t)__cvta_generic_to_shared(&sm[KHn + PE + so]),     &g_kl[g]);
                cpa16((uint32_t)__cvta_generic_to_shared(&sm[KHn + 2 * PE + so]), &g_vh[g]);
            }
            cp_commit();
            cp_wait<1>();
        } else {
            cp_wait<0>();
        }
        __syncthreads();

        const int KH = (2 + 3 * buf) * PE;       // Kh plane; Kl = KH+PE; V = KH+2*PE
        const int k0 = kt * 64;

        // ---- scores S = (Q/8) @ K^T : 3-term fp16 split
        float sacc[8][4];
        #pragma unroll
        for (int nt = 0; nt < 8; nt++)
            #pragma unroll
            for (int e = 0; e < 4; e++) sacc[nt][e] = 0.f;

        #pragma unroll
        for (int d8 = 0; d8 < 4; d8++) {
            #pragma unroll
            for (int p = 0; p < 4; p++) {
                uint32_t boff = (p * 16 + ((m_idx & 1) << 3) + rin) * PS
                              + d8 * 16 + ((m_idx >> 1) << 3);
                uint32_t kh0, kh1, kh2, kh3, kl0, kl1, kl2, kl3;
                ldsm_x4(kh0, kh1, kh2, kh3,
                        (uint32_t)__cvta_generic_to_shared(&sm[KH + boff]));
                ldsm_x4(kl0, kl1, kl2, kl3,
                        (uint32_t)__cvta_generic_to_shared(&sm[KH + PE + boff]));
                mma_f16(sacc[2*p],   qf[d8][0][0], qf[d8][0][1], qf[d8][0][2], qf[d8][0][3], kh0, kh2);
                mma_f16(sacc[2*p],   qf[d8][1][0], qf[d8][1][1], qf[d8][1][2], qf[d8][1][3], kh0, kh2);
                mma_f16(sacc[2*p],   qf[d8][0][0], qf[d8][0][1], qf[d8][0][2], qf[d8][0][3], kl0, kl2);
                mma_f16(sacc[2*p+1], qf[d8][0][0], qf[d8][0][1], qf[d8][0][2], qf[d8][0][3], kh1, kh3);
                mma_f16(sacc[2*p+1], qf[d8][1][0], qf[d8][1][1], qf[d8][1][2], qf[d8][1][3], kh1, kh3);
                mma_f16(sacc[2*p+1], qf[d8][0][0], qf[d8][0][1], qf[d8][0][2], qf[d8][0][3], kl1, kl3);
            }
        }

        // ---- + bias (mask folded as -1e9) + row max
        float mx0 = -1e30f, mx1 = -1e30f;
        #pragma unroll
        for (int nt = 0; nt < 8; nt++) {
            float2 ba = *(const float2*)&biasA[k0 + nt * 8 + tig * 2];
            float2 bb = *(const float2*)&biasB[k0 + nt * 8 + tig * 2];
            sacc[nt][0] += ba.x;
            sacc[nt][1] += ba.y;
            sacc[nt][2] += bb.x;
            sacc[nt][3] += bb.y;
            mx0 = fmaxf(mx0, fmaxf(sacc[nt][0], sacc[nt][1]));
            mx1 = fmaxf(mx1, fmaxf(sacc[nt][2], sacc[nt][3]));
        }
        mx0 = fmaxf(mx0, __shfl_xor_sync(0xffffffffu, mx0, 1));
        mx0 = fmaxf(mx0, __shfl_xor_sync(0xffffffffu, mx0, 2));
        mx1 = fmaxf(mx1, __shfl_xor_sync(0xffffffffu, mx1, 1));
        mx1 = fmaxf(mx1, __shfl_xor_sync(0xffffffffu, mx1, 2));

        const float mn0 = fmaxf(m0, mx0), mn1 = fmaxf(m1, mx1);
        const float c0 = __expf(m0 - mn0), c1 = __expf(m1 - mn1);
        m0 = mn0; m1 = mn1;

        float rs0 = 0.f, rs1 = 0.f;
        #pragma unroll
        for (int nt = 0; nt < 8; nt++) {
            sacc[nt][0] = __expf(sacc[nt][0] - mn0);
            sacc[nt][1] = __expf(sacc[nt][1] - mn0);
            sacc[nt][2] = __expf(sacc[nt][2] - mn1);
            sacc[nt][3] = __expf(sacc[nt][3] - mn1);
            rs0 += sacc[nt][0] + sacc[nt][1];
            rs1 += sacc[nt][2] + sacc[nt][3];
        }
        rs0 += __shfl_xor_sync(0xffffffffu, rs0, 1);
        rs0 += __shfl_xor_sync(0xffffffffu, rs0, 2);
        rs1 += __shfl_xor_sync(0xffffffffu, rs1, 1);
        rs1 += __shfl_xor_sync(0xffffffffu, rs1, 2);

        l0 = l0 * c0 + rs0;
        l1 = l1 * c1 + rs1;
        #pragma unroll
        for (int nt = 0; nt < 8; nt++) {
            oacc[nt][0] *= c0; oacc[nt][1] *= c0;
            oacc[nt][2] *= c1; oacc[nt][3] *= c1;
        }

        // ---- pack P into fp16 A-fragments (registers only)
        uint32_t pa[4][4];   // [j16-step][reg]
        #pragma unroll
        for (int j8 = 0; j8 < 4; j8++) {
            const float* sA = sacc[2 * j8];
            const float* sB = sacc[2 * j8 + 1];
            __half2 h;
            h = __floats2half2_rn(sA[0], sA[1]); pa[j8][0] = *(uint32_t*)&h;
            h = __floats2half2_rn(sA[2], sA[3]); pa[j8][1] = *(uint32_t*)&h;
            h = __floats2half2_rn(sB[0], sB[1]); pa[j8][2] = *(uint32_t*)&h;
            h = __floats2half2_rn(sB[2], sB[3]); pa[j8][3] = *(uint32_t*)&h;
        }

        // ---- O += P @ V : single-term fp16, V via ldmatrix.x4.trans
        #pragma unroll
        for (int j8 = 0; j8 < 4; j8++) {
            #pragma unroll
            for (int p = 0; p < 4; p++) {
                uint32_t boff = (j8 * 16 + ((m_idx & 1) << 3) + rin) * PS
                              + p * 16 + ((m_idx >> 1) << 3);
                uint32_t vh0, vh1, vh2, vh3;
                ldsm_x4_t(vh0, vh1, vh2, vh3,
                          (uint32_t)__cvta_generic_to_shared(&sm[KH + 2 * PE + boff]));
                mma_f16(oacc[2*p],   pa[j8][0], pa[j8][1], pa[j8][2], pa[j8][3], vh0, vh1);
                mma_f16(oacc[2*p+1], pa[j8][0], pa[j8][1], pa[j8][2], pa[j8][3], vh2, vh3);
            }
        }
        __syncthreads();   // all reads of buf done before it is refilled
    }

    // ---- epilogue: normalize, write [B,S,D]
    const float inv0 = 1.f / l0, inv1 = 1.f / l1;
    float* out0 = &g_attn[(size_t)(b * S_ + q0 + tr) * D_ + hoff];
    float* out1 = out0 + (size_t)8 * D_;
    #pragma unroll
    for (int nt = 0; nt < 8; nt++) {
        float2 o0 = make_float2(oacc[nt][0] * inv0, oacc[nt][1] * inv0);
        float2 o1 = make_float2(oacc[nt][2] * inv1, oacc[nt][3] * inv1);
        *(float2*)&out0[nt * 8 + tig * 2] = o0;
        *(float2*)&out1[nt * 8 + tig * 2] = o1;
    }
}

// ---------------------------------------------------------------------------
extern "C" void kernel_launch(void* const* d_in, const int* in_sizes, int n_in,
                              void* d_out, int out_size)
{
    const float* Q     = (const float*)d_in[0];
    const float* K     = (const float*)d_in[1];
    const float* V     = (const float*)d_in[2];
    const float* tmat  = (const float*)d_in[3];
    const float* dmat  = (const float*)d_in[4];
    const int*   mask  = (const int*)  d_in[5];
    const float* Wq    = (const float*)d_in[6];
    const float* bq    = (const float*)d_in[7];
    const float* Wk    = (const float*)d_in[8];
    const float* bk    = (const float*)d_in[9];
    const float* Wv    = (const float*)d_in[10];
    const float* bv    = (const float*)d_in[11];
    const float* Wo    = (const float*)d_in[12];
    const float* bo    = (const float*)d_in[13];
    const float* tm_w  = (const float*)d_in[14];
    const float* tm_b  = (const float*)d_in[15];
    const float* dm_w  = (const float*)d_in[16];
    const float* dm_b  = (const float*)d_in[17];
    const float* td_w  = (const float*)d_in[18];
    const float* td_b  = (const float*)d_in[19];
    float* out = (float*)d_out;

    float* ab;
    cudaGetSymbolAddress((void**)&ab, g_attn);
    __half *qh, *ql, *kh, *kl, *vh, *vl;
    cudaGetSymbolAddress((void**)&qh, g_qh);
    cudaGetSymbolAddress((void**)&ql, g_ql);
    cudaGetSymbolAddress((void**)&kh, g_kh);
    cudaGetSymbolAddress((void**)&kl, g_kl);
    cudaGetSymbolAddress((void**)&vh, g_vh);
    cudaGetSymbolAddress((void**)&vl, g_vl);

    prep_kernel<<<1, 32>>>(tm_w, tm_b, dm_w, dm_b, td_w);

    // fused Q/K/V projections -> fp16 hi/lo planes (Q pre-scaled by 1/8)
    gemm_qkv<<<dim3(D_ / 128, MTOT / 128, 3), 256>>>(
        Q, K, V, Wq, Wk, Wv, bq, bk, bv,
        out /*unused*/, qh, ql, kh, kl, vh, vl,
        MTOT, D_, D_, 0.125f, 1);

    bias_mask_kernel<<<(B_ * S_ * S_) / 1024, 256>>>(
        tmat, dmat, mask, tm_w, tm_b, dm_w, dm_b, td_w, td_b);

    cudaFuncSetAttribute(attn_f16,
                         cudaFuncAttributeMaxDynamicSharedMemorySize, SMEM_ATTN);
    attn_f16<<<dim3(S_ / 64, H_, B_), 128, SMEM_ATTN>>>();

    // output projection: fp32 in (g_attn), fp32 out
    gemm_qkv<<<dim3(D_ / 128, MTOT / 128, 1), 256>>>(
        ab, ab, ab, Wo, Wo, Wo, bo, bo, bo,
        out, qh, ql, kh, kl, vh, vl,
        MTOT, D_, D_, 1.f, 0);
}

// round 8
// speedup vs baseline: 1.2107x; 1.0760x over previous
#include <cuda_runtime.h>
#include <cuda_bf16.h>
#include <cuda_fp16.h>
#include <cstdint>

#define B_  4
#define S_  1024
#define D_  512
#define H_  8
#define DK_ 64
#define MTOT (B_*S_)          // 4096 rows
#define NELE (B_*S_*D_)       // 2,097,152
#define LOG2E 1.4426950408889634f

// Scratch (static device globals — allowed; no cudaMalloc anywhere)
// Q/K as fp16 hi/lo planes; V single fp16. Q pre-scaled by log2(e)/8.
__device__ __half g_qh[NELE], g_ql[NELE];
__device__ __half g_kh[NELE], g_kl[NELE];
__device__ __half g_vh[NELE], g_vl[NELE];   // g_vl unused (not written)
__device__ float g_attn[NELE];
__device__ float g_bias[(size_t)B_*S_*S_];  // bias*log2e, mask folded as -1.5e9
__device__ float g_Ct, g_Cd;
__device__ int   g_bzero;

// ---------------------------------------------------------------------------
// helpers
// ---------------------------------------------------------------------------
__device__ __forceinline__ float ex2f(float x) {
    float r; asm("ex2.approx.f32 %0, %1;" : "=f"(r) : "f"(x)); return r;
}

__device__ __forceinline__ void mma_bf16(float c[4],
    uint32_t a0, uint32_t a1, uint32_t a2, uint32_t a3,
    uint32_t b0, uint32_t b1)
{
    asm volatile(
        "mma.sync.aligned.m16n8k16.row.col.f32.bf16.bf16.f32 "
        "{%0,%1,%2,%3},{%4,%5,%6,%7},{%8,%9},{%0,%1,%2,%3};"
        : "+f"(c[0]), "+f"(c[1]), "+f"(c[2]), "+f"(c[3])
        : "r"(a0), "r"(a1), "r"(a2), "r"(a3), "r"(b0), "r"(b1));
}

__device__ __forceinline__ void mma_f16(float c[4],
    uint32_t a0, uint32_t a1, uint32_t a2, uint32_t a3,
    uint32_t b0, uint32_t b1)
{
    asm volatile(
        "mma.sync.aligned.m16n8k16.row.col.f32.f16.f16.f32 "
        "{%0,%1,%2,%3},{%4,%5,%6,%7},{%8,%9},{%0,%1,%2,%3};"
        : "+f"(c[0]), "+f"(c[1]), "+f"(c[2]), "+f"(c[3])
        : "r"(a0), "r"(a1), "r"(a2), "r"(a3), "r"(b0), "r"(b1));
}

__device__ __forceinline__ void ldsm_x4(uint32_t& r0, uint32_t& r1,
                                        uint32_t& r2, uint32_t& r3, uint32_t addr)
{
    asm volatile("ldmatrix.sync.aligned.m8n8.x4.shared.b16 {%0,%1,%2,%3}, [%4];"
        : "=r"(r0), "=r"(r1), "=r"(r2), "=r"(r3) : "r"(addr));
}

__device__ __forceinline__ void ldsm_x4_t(uint32_t& r0, uint32_t& r1,
                                          uint32_t& r2, uint32_t& r3, uint32_t addr)
{
    asm volatile("ldmatrix.sync.aligned.m8n8.x4.trans.shared.b16 {%0,%1,%2,%3}, [%4];"
        : "=r"(r0), "=r"(r1), "=r"(r2), "=r"(r3) : "r"(addr));
}

__device__ __forceinline__ void ldsm_x2_t(uint32_t& r0, uint32_t& r1, uint32_t addr)
{
    asm volatile("ldmatrix.sync.aligned.m8n8.x2.trans.shared.b16 {%0,%1}, [%2];"
        : "=r"(r0), "=r"(r1) : "r"(addr));
}

__device__ __forceinline__ void cpa16(uint32_t dst, const void* src) {
    asm volatile("cp.async.cg.shared.global [%0], [%1], 16;" :: "r"(dst), "l"(src));
}
__device__ __forceinline__ void cp_commit() {
    asm volatile("cp.async.commit_group;");
}
template<int N> __device__ __forceinline__ void cp_wait() {
    asm volatile("cp.async.wait_group %0;" :: "n"(N));
}

// fp16 hi/lo split pack of a float pair
__device__ __forceinline__ void pack_hilo_h(float x, float y, uint32_t& hi, uint32_t& lo) {
    __half2 h = __floats2half2_rn(x, y);
    float2 f = __half22float2(h);
    __half2 l = __floats2half2_rn(x - f.x, y - f.y);
    hi = *reinterpret_cast<uint32_t*>(&h);
    lo = *reinterpret_cast<uint32_t*>(&l);
}

// ---------------------------------------------------------------------------
// Fused GEMM (up to 3 problems via blockIdx.z), bf16 TC with hi/lo split:
//   R = (A[M,K] @ W[K,N] + bias[N]) * (z==0 ? scale0 : 1)
//   fp16_out: write R as fp16 hi/lo planes (lo skipped for z==2 / V).
// ---------------------------------------------------------------------------
#define AKP 40
#define BNP 136

__global__ __launch_bounds__(256) void gemm_qkv(
    const float* __restrict__ A0, const float* __restrict__ A1, const float* __restrict__ A2,
    const float* __restrict__ W0, const float* __restrict__ W1, const float* __restrict__ W2,
    const float* __restrict__ b0v, const float* __restrict__ b1v, const float* __restrict__ b2v,
    float* __restrict__ C0,
    __half* __restrict__ H0, __half* __restrict__ L0,
    __half* __restrict__ H1, __half* __restrict__ L1,
    __half* __restrict__ H2, __half* __restrict__ L2,
    int M, int N, int K, float scale0, int fp16_out)
{
    __shared__ __nv_bfloat16 Ash[2][128 * AKP];
    __shared__ __nv_bfloat16 Bsh[2][32 * BNP];

    const float* A;  const float* Wm; const float* bias;
    __half *Ho, *Lo;
    if (blockIdx.z == 0)      { A = A0; Wm = W0; bias = b0v; Ho = H0; Lo = L0; }
    else if (blockIdx.z == 1) { A = A1; Wm = W1; bias = b1v; Ho = H1; Lo = L1; }
    else                      { A = A2; Wm = W2; bias = b2v; Ho = H2; Lo = L2; }
    const float osc = (blockIdx.z == 0) ? scale0 : 1.f;
    const bool  wlo = (blockIdx.z != 2);   // V lo-plane never read

    const int t = threadIdx.x;
    const int lane = t & 31, wid = t >> 5;
    const int warp_m = wid & 3, warp_n = wid >> 2;
    const int m_w = warp_m * 32, n_w = warp_n * 64;
    const int bm = blockIdx.y * 128, bn = blockIdx.x * 128;
    const int gid = lane >> 2, tig = lane & 3;

    const int b_n0 = (t & 63) * 2;
    const int b_kq = (t >> 6) * 8;

    float acc[2][8][4];
    #pragma unroll
    for (int mt = 0; mt < 2; mt++)
        #pragma unroll
        for (int nt = 0; nt < 8; nt++)
            #pragma unroll
            for (int e = 0; e < 4; e++) acc[mt][nt][e] = 0.f;

    float4 a_pre[4];
    float2 b_pre[8];
    #pragma unroll
    for (int r = 0; r < 4; r++) {
        int e = t + r * 256;
        int row = e >> 3, col4 = (e & 7) << 2;
        a_pre[r] = *(const float4*)&A[(size_t)(bm + row) * K + col4];
    }
    #pragma unroll
    for (int kk = 0; kk < 8; kk++)
        b_pre[kk] = *(const float2*)&Wm[(size_t)(b_kq + kk) * N + bn + b_n0];

    for (int k0 = 0; k0 < K; k0 += 32) {
        #pragma unroll
        for (int r = 0; r < 4; r++) {
            int e = t + r * 256;
            int row = e >> 3, col4 = (e & 7) << 2;
            float4 v = a_pre[r];
            __nv_bfloat162 h0 = __floats2bfloat162_rn(v.x, v.y);
            __nv_bfloat162 h1 = __floats2bfloat162_rn(v.z, v.w);
            float2 f0 = __bfloat1622float2(h0);
            float2 f1 = __bfloat1622float2(h1);
            __nv_bfloat162 l0 = __floats2bfloat162_rn(v.x - f0.x, v.y - f0.y);
            __nv_bfloat162 l1 = __floats2bfloat162_rn(v.z - f1.x, v.w - f1.y);
            *(__nv_bfloat162*)&Ash[0][row * AKP + col4]     = h0;
            *(__nv_bfloat162*)&Ash[0][row * AKP + col4 + 2] = h1;
            *(__nv_bfloat162*)&Ash[1][row * AKP + col4]     = l0;
            *(__nv_bfloat162*)&Ash[1][row * AKP + col4 + 2] = l1;
        }
        #pragma unroll
        for (int kk = 0; kk < 8; kk++) {
            int k = b_kq + kk;
            float2 v = b_pre[kk];
            __nv_bfloat162 h = __floats2bfloat162_rn(v.x, v.y);
            float2 f = __bfloat1622float2(h);
            __nv_bfloat162 l = __floats2bfloat162_rn(v.x - f.x, v.y - f.y);
            *(__nv_bfloat162*)&Bsh[0][k * BNP + b_n0] = h;
            *(__nv_bfloat162*)&Bsh[1][k * BNP + b_n0] = l;
        }
        __syncthreads();

        if (k0 + 32 < K) {
            #pragma unroll
            for (int r = 0; r < 4; r++) {
                int e = t + r * 256;
                int row = e >> 3, col4 = (e & 7) << 2;
                a_pre[r] = *(const float4*)&A[(size_t)(bm + row) * K + k0 + 32 + col4];
            }
            #pragma unroll
            for (int kk = 0; kk < 8; kk++)
                b_pre[kk] = *(const float2*)&Wm[(size_t)(k0 + 32 + b_kq + kk) * N + bn + b_n0];
        }

        #pragma unroll
        for (int kb = 0; kb < 32; kb += 16) {
            uint32_t af[2][2][4];
            #pragma unroll
            for (int mt = 0; mt < 2; mt++) {
                const int arow = m_w + mt * 16 + (lane & 15);
                const int acol = kb + ((lane >> 4) << 3);
                #pragma unroll
                for (int p = 0; p < 2; p++) {
                    uint32_t addr = (uint32_t)__cvta_generic_to_shared(
                        &Ash[p][arow * AKP + acol]);
                    ldsm_x4(af[mt][p][0], af[mt][p][1], af[mt][p][2], af[mt][p][3], addr);
                }
            }
            #pragma unroll
            for (int nt = 0; nt < 8; nt++) {
                const int brow = kb + (lane & 15);
                const int bcol = n_w + nt * 8;
                uint32_t bh0, bh1, bl0, bl1;
                uint32_t addrh = (uint32_t)__cvta_generic_to_shared(
                    &Bsh[0][brow * BNP + bcol]);
                uint32_t addrl = (uint32_t)__cvta_generic_to_shared(
                    &Bsh[1][brow * BNP + bcol]);
                ldsm_x2_t(bh0, bh1, addrh);
                ldsm_x2_t(bl0, bl1, addrl);
                #pragma unroll
                for (int mt = 0; mt < 2; mt++) {
                    mma_bf16(acc[mt][nt], af[mt][0][0], af[mt][0][1],
                             af[mt][0][2], af[mt][0][3], bh0, bh1);
                    mma_bf16(acc[mt][nt], af[mt][1][0], af[mt][1][1],
                             af[mt][1][2], af[mt][1][3], bh0, bh1);
                    mma_bf16(acc[mt][nt], af[mt][0][0], af[mt][0][1],
                             af[mt][0][2], af[mt][0][3], bl0, bl1);
                }
            }
        }
        __syncthreads();
    }

    // ---- epilogue
    #pragma unroll
    for (int mt = 0; mt < 2; mt++) {
        const int row0 = bm + m_w + mt * 16 + gid;
        #pragma unroll
        for (int nt = 0; nt < 8; nt++) {
            const int col = bn + n_w + nt * 8 + tig * 2;
            float2 bb = *(const float2*)&bias[col];
            float v0 = (acc[mt][nt][0] + bb.x) * osc;
            float v1 = (acc[mt][nt][1] + bb.y) * osc;
            float v2 = (acc[mt][nt][2] + bb.x) * osc;
            float v3 = (acc[mt][nt][3] + bb.y) * osc;
            if (fp16_out) {
                uint32_t h01, l01, h23, l23;
                pack_hilo_h(v0, v1, h01, l01);
                pack_hilo_h(v2, v3, h23, l23);
                *(uint32_t*)&Ho[(size_t)row0 * N + col]       = h01;
                *(uint32_t*)&Ho[(size_t)(row0 + 8) * N + col] = h23;
                if (wlo) {
                    *(uint32_t*)&Lo[(size_t)row0 * N + col]       = l01;
                    *(uint32_t*)&Lo[(size_t)(row0 + 8) * N + col] = l23;
                }
            } else {
                *(float2*)&C0[(size_t)row0 * N + col]       = make_float2(v0, v1);
                *(float2*)&C0[(size_t)(row0 + 8) * N + col] = make_float2(v2, v3);
            }
        }
    }
}

// ---------------------------------------------------------------------------
// Prep: detect all-zero biases; precompute collapsed coefficients (log2 domain)
// ---------------------------------------------------------------------------
__global__ void prep_kernel(const float* __restrict__ tm_w, const float* __restrict__ tm_b,
                            const float* __restrict__ dm_w, const float* __restrict__ dm_b,
                            const float* __restrict__ td_w)
{
    const int l = threadIdx.x;   // 32 threads
    float ct = 0.f, cd = 0.f;
    bool z = true;
    #pragma unroll
    for (int m = l; m < 64; m += 32) {
        z = z && (tm_b[m] == 0.f) && (dm_b[m] == 0.f);
        ct += (0.5f * LOG2E) * td_w[m] * fmaxf(tm_w[m], 0.f);
        cd += (0.5f * LOG2E) * td_w[m] * fmaxf(dm_w[m], 0.f);
    }
    unsigned bz = __ballot_sync(0xffffffffu, z);
    #pragma unroll
    for (int o = 16; o; o >>= 1) {
        ct += __shfl_xor_sync(0xffffffffu, ct, o);
        cd += __shfl_xor_sync(0xffffffffu, cd, o);
    }
    if (l == 0) { g_Ct = ct; g_Cd = cd; g_bzero = (bz == 0xffffffffu); }
}

// ---------------------------------------------------------------------------
// Fused bias + mask (log2 domain). Fast path: 2 FMAs per element.
// ---------------------------------------------------------------------------
__global__ __launch_bounds__(256) void bias_mask_kernel(
    const float* __restrict__ tmat, const float* __restrict__ dmat,
    const int*   __restrict__ mask,
    const float* __restrict__ tm_w, const float* __restrict__ tm_b,
    const float* __restrict__ dm_w, const float* __restrict__ dm_b,
    const float* __restrict__ td_w, const float* __restrict__ td_b)
{
    const int t = threadIdx.x;
    const float tdb = td_b[0] * LOG2E;
    const float E = 2.718281828459045f;

    const size_t base = ((size_t)blockIdx.x * 256 + t) * 4;
    float4 u  = *(const float4*)(tmat + base);
    float4 w  = *(const float4*)(dmat + base);
    int4   mk = *(const int4*)(mask + base);

    float tv[4] = { 1.f / __logf(E + u.x), 1.f / __logf(E + u.y),
                    1.f / __logf(E + u.z), 1.f / __logf(E + u.w) };
    float dv[4] = { 1.f / __logf(E + w.x), 1.f / __logf(E + w.y),
                    1.f / __logf(E + w.z), 1.f / __logf(E + w.w) };
    float acc[4];

    if (g_bzero) {
        const float Ct = g_Ct, Cd = g_Cd;
        #pragma unroll
        for (int i = 0; i < 4; i++)
            acc[i] = fmaf(tv[i], Ct, fmaf(dv[i], Cd, tdb));
    } else {
        __shared__ float sp[5][64];
        if (t < 64) {
            sp[0][t] = tm_w[t];
            sp[1][t] = tm_b[t];
            sp[2][t] = dm_w[t];
            sp[3][t] = dm_b[t];
            sp[4][t] = td_w[t] * 0.5f * LOG2E;
        }
        __syncthreads();
        #pragma unroll
        for (int i = 0; i < 4; i++) acc[i] = tdb;
        #pragma unroll 8
        for (int m = 0; m < 64; m++) {
            const float tw = sp[0][m], tb = sp[1][m];
            const float dw = sp[2][m], db = sp[3][m];
            const float ww = sp[4][m];
            #pragma unroll
            for (int i = 0; i < 4; i++) {
                float rt = fmaxf(tv[i] * tw + tb, 0.f);
                float rd = fmaxf(dv[i] * dw + db, 0.f);
                acc[i] += ww * (rt + rd);
            }
        }
    }

    float4 o;
    o.x = (mk.x == 1) ? -1.5e9f : acc[0];
    o.y = (mk.y == 1) ? -1.5e9f : acc[1];
    o.z = (mk.z == 1) ? -1.5e9f : acc[2];
    o.w = (mk.w == 1) ? -1.5e9f : acc[3];
    *(float4*)(g_bias + base) = o;
}

// ---------------------------------------------------------------------------
// Flash attention, fp16 TC, log2-domain softmax (bare ex2.approx).
// Bias tile staged by cp.async into the retired Q smem planes (single buffer);
// its completion is waited only AFTER the QK^T mma block -> latency hidden.
// ---------------------------------------------------------------------------
#define PS 72
#define PE (64*PS)
#define BSS 68                  // bias smem row stride (floats)
#define SMEM_ATTN (8*PE*2)

__global__ __launch_bounds__(128) void attn_f16()
{
    extern __shared__ __half sm[];
    float* biasS = (float*)sm;   // overlays Q planes 0,1 after prologue

    const int qt = blockIdx.x, h = blockIdx.y, b = blockIdx.z;
    const int t = threadIdx.x;
    const int w = t >> 5, lane = t & 31;
    const int gid = lane >> 2, tig = lane & 3;
    const int q0 = qt * 64, hoff = h * DK_;
    const int tr = w * 16 + gid;              // this thread's first q row (local)
    const int m_idx = lane >> 3, rin = lane & 7;

    // ---- prologue: Q planes + K/V tile0 planes (buf0 = planes 2,3,4)
    #pragma unroll
    for (int i = 0; i < 4; i++) {
        int c = t + i * 128;
        int row = c >> 3, col = (c & 7) * 8;
        size_t gq = (size_t)(b * S_ + q0 + row) * D_ + hoff + col;
        size_t gk = (size_t)(b * S_ + row) * D_ + hoff + col;
        uint32_t so = row * PS + col;
        cpa16((uint32_t)__cvta_generic_to_shared(&sm[0*PE + so]), &g_qh[gq]);
        cpa16((uint32_t)__cvta_generic_to_shared(&sm[1*PE + so]), &g_ql[gq]);
        cpa16((uint32_t)__cvta_generic_to_shared(&sm[2*PE + so]), &g_kh[gk]);
        cpa16((uint32_t)__cvta_generic_to_shared(&sm[3*PE + so]), &g_kl[gk]);
        cpa16((uint32_t)__cvta_generic_to_shared(&sm[4*PE + so]), &g_vh[gk]);
    }
    cp_commit();
    cp_wait<0>();
    __syncthreads();

    // ---- Q fragments, loop-invariant, held in registers
    uint32_t qf[4][2][4];   // [d16-step][plane][reg]
    #pragma unroll
    for (int d8 = 0; d8 < 4; d8++)
        #pragma unroll
        for (int p = 0; p < 2; p++) {
            uint32_t a = (uint32_t)__cvta_generic_to_shared(
                &sm[p*PE + (w * 16 + (lane & 15)) * PS + d8 * 16 + ((lane >> 4) << 3)]);
            ldsm_x4(qf[d8][p][0], qf[d8][p][1], qf[d8][p][2], qf[d8][p][3], a);
        }
    __syncthreads();   // Q planes now dead -> become the bias buffer

    float m0 = -1e30f, m1 = -1e30f, l0 = 0.f, l1 = 0.f;
    float oacc[8][4];
    #pragma unroll
    for (int nt = 0; nt < 8; nt++)
        #pragma unroll
        for (int e = 0; e < 4; e++) oacc[nt][e] = 0.f;

    for (int kt = 0; kt < 16; kt++) {
        const int buf = kt & 1;

        // ---- issue bias(kt) copy into biasS (group B_kt)
        #pragma unroll
        for (int i = 0; i < 8; i++) {
            int idx = t + i * 128;
            int row = idx >> 4, c4 = (idx & 15) << 2;
            cpa16((uint32_t)__cvta_generic_to_shared(&biasS[row * BSS + c4]),
                  &g_bias[((size_t)(b * S_ + q0 + row)) * S_ + kt * 64 + c4]);
        }
        cp_commit();

        // ---- issue KV(kt+1), then wait for KV(kt)
        if (kt < 15) {
            const int k1 = (kt + 1) * 64;
            const int KHn = (2 + 3 * (buf ^ 1)) * PE;
            #pragma unroll
            for (int i = 0; i < 4; i++) {
                int c = t + i * 128;
                int row = c >> 3, col = (c & 7) * 8;
                size_t g = (size_t)(b * S_ + k1 + row) * D_ + hoff + col;
                uint32_t so = row * PS + col;
                cpa16((uint32_t)__cvta_generic_to_shared(&sm[KHn + so]),          &g_kh[g]);
                cpa16((uint32_t)__cvta_generic_to_shared(&sm[KHn + PE + so]),     &g_kl[g]);
                cpa16((uint32_t)__cvta_generic_to_shared(&sm[KHn + 2 * PE + so]), &g_vh[g]);
            }
            cp_commit();
            cp_wait<2>();     // KV(kt) done; B_kt and KV(kt+1) in flight
        } else {
            cp_wait<1>();     // KV(15) done; B_15 in flight
        }
        __syncthreads();

        const int KH = (2 + 3 * buf) * PE;       // Kh plane; Kl = KH+PE; V = KH+2*PE

        // ---- scores S = Q @ K^T (log2-domain) : 3-term fp16 split
        float sacc[8][4];
        #pragma unroll
        for (int nt = 0; nt < 8; nt++)
            #pragma unroll
            for (int e = 0; e < 4; e++) sacc[nt][e] = 0.f;

        #pragma unroll
        for (int d8 = 0; d8 < 4; d8++) {
            #pragma unroll
            for (int p = 0; p < 4; p++) {
                uint32_t boff = (p * 16 + ((m_idx & 1) << 3) + rin) * PS
                              + d8 * 16 + ((m_idx >> 1) << 3);
                uint32_t kh0, kh1, kh2, kh3, kl0, kl1, kl2, kl3;
                ldsm_x4(kh0, kh1, kh2, kh3,
                        (uint32_t)__cvta_generic_to_shared(&sm[KH + boff]));
                ldsm_x4(kl0, kl1, kl2, kl3,
                        (uint32_t)__cvta_generic_to_shared(&sm[KH + PE + boff]));
                mma_f16(sacc[2*p],   qf[d8][0][0], qf[d8][0][1], qf[d8][0][2], qf[d8][0][3], kh0, kh2);
                mma_f16(sacc[2*p],   qf[d8][1][0], qf[d8][1][1], qf[d8][1][2], qf[d8][1][3], kh0, kh2);
                mma_f16(sacc[2*p],   qf[d8][0][0], qf[d8][0][1], qf[d8][0][2], qf[d8][0][3], kl0, kl2);
                mma_f16(sacc[2*p+1], qf[d8][0][0], qf[d8][0][1], qf[d8][0][2], qf[d8][0][3], kh1, kh3);
                mma_f16(sacc[2*p+1], qf[d8][1][0], qf[d8][1][1], qf[d8][1][2], qf[d8][1][3], kh1, kh3);
                mma_f16(sacc[2*p+1], qf[d8][0][0], qf[d8][0][1], qf[d8][0][2], qf[d8][0][3], kl1, kl3);
            }
        }

        // ---- bias now resident in smem
        if (kt < 15) { cp_wait<1>(); } else { cp_wait<0>(); }
        __syncthreads();

        float mx0 = -1e30f, mx1 = -1e30f;
        #pragma unroll
        for (int nt = 0; nt < 8; nt++) {
            float2 ba = *(const float2*)&biasS[tr * BSS + nt * 8 + tig * 2];
            float2 bb = *(const float2*)&biasS[(tr + 8) * BSS + nt * 8 + tig * 2];
            sacc[nt][0] += ba.x;
            sacc[nt][1] += ba.y;
            sacc[nt][2] += bb.x;
            sacc[nt][3] += bb.y;
            mx0 = fmaxf(mx0, fmaxf(sacc[nt][0], sacc[nt][1]));
            mx1 = fmaxf(mx1, fmaxf(sacc[nt][2], sacc[nt][3]));
        }
        mx0 = fmaxf(mx0, __shfl_xor_sync(0xffffffffu, mx0, 1));
        mx0 = fmaxf(mx0, __shfl_xor_sync(0xffffffffu, mx0, 2));
        mx1 = fmaxf(mx1, __shfl_xor_sync(0xffffffffu, mx1, 1));
        mx1 = fmaxf(mx1, __shfl_xor_sync(0xffffffffu, mx1, 2));

        const float mn0 = fmaxf(m0, mx0), mn1 = fmaxf(m1, mx1);
        const float c0 = ex2f(m0 - mn0), c1 = ex2f(m1 - mn1);
        m0 = mn0; m1 = mn1;

        float rs0 = 0.f, rs1 = 0.f;
        #pragma unroll
        for (int nt = 0; nt < 8; nt++) {
            sacc[nt][0] = ex2f(sacc[nt][0] - mn0);
            sacc[nt][1] = ex2f(sacc[nt][1] - mn0);
            sacc[nt][2] = ex2f(sacc[nt][2] - mn1);
            sacc[nt][3] = ex2f(sacc[nt][3] - mn1);
            rs0 += sacc[nt][0] + sacc[nt][1];
            rs1 += sacc[nt][2] + sacc[nt][3];
        }
        rs0 += __shfl_xor_sync(0xffffffffu, rs0, 1);
        rs0 += __shfl_xor_sync(0xffffffffu, rs0, 2);
        rs1 += __shfl_xor_sync(0xffffffffu, rs1, 1);
        rs1 += __shfl_xor_sync(0xffffffffu, rs1, 2);

        l0 = l0 * c0 + rs0;
        l1 = l1 * c1 + rs1;
        #pragma unroll
        for (int nt = 0; nt < 8; nt++) {
            oacc[nt][0] *= c0; oacc[nt][1] *= c0;
            oacc[nt][2] *= c1; oacc[nt][3] *= c1;
        }

        // ---- pack P into fp16 A-fragments (registers only)
        uint32_t pa[4][4];   // [j16-step][reg]
        #pragma unroll
        for (int j8 = 0; j8 < 4; j8++) {
            const float* sA = sacc[2 * j8];
            const float* sB = sacc[2 * j8 + 1];
            __half2 hh;
            hh = __floats2half2_rn(sA[0], sA[1]); pa[j8][0] = *(uint32_t*)&hh;
            hh = __floats2half2_rn(sA[2], sA[3]); pa[j8][1] = *(uint32_t*)&hh;
            hh = __floats2half2_rn(sB[0], sB[1]); pa[j8][2] = *(uint32_t*)&hh;
            hh = __floats2half2_rn(sB[2], sB[3]); pa[j8][3] = *(uint32_t*)&hh;
        }

        // ---- O += P @ V : single-term fp16, V via ldmatrix.x4.trans
        #pragma unroll
        for (int j8 = 0; j8 < 4; j8++) {
            #pragma unroll
            for (int p = 0; p < 4; p++) {
                uint32_t boff = (j8 * 16 + ((m_idx & 1) << 3) + rin) * PS
                              + p * 16 + ((m_idx >> 1) << 3);
                uint32_t vh0, vh1, vh2, vh3;
                ldsm_x4_t(vh0, vh1, vh2, vh3,
                          (uint32_t)__cvta_generic_to_shared(&sm[KH + 2 * PE + boff]));
                mma_f16(oacc[2*p],   pa[j8][0], pa[j8][1], pa[j8][2], pa[j8][3], vh0, vh1);
                mma_f16(oacc[2*p+1], pa[j8][0], pa[j8][1], pa[j8][2], pa[j8][3], vh2, vh3);
            }
        }
        __syncthreads();   // KV buf + bias reads done before next overwrite
    }

    // ---- epilogue: normalize, write [B,S,D]
    const float inv0 = 1.f / l0, inv1 = 1.f / l1;
    float* out0 = &g_attn[(size_t)(b * S_ + q0 + tr) * D_ + hoff];
    float* out1 = out0 + (size_t)8 * D_;
    #pragma unroll
    for (int nt = 0; nt < 8; nt++) {
        float2 o0 = make_float2(oacc[nt][0] * inv0, oacc[nt][1] * inv0);
        float2 o1 = make_float2(oacc[nt][2] * inv1, oacc[nt][3] * inv1);
        *(float2*)&out0[nt * 8 + tig * 2] = o0;
        *(float2*)&out1[nt * 8 + tig * 2] = o1;
    }
}

// ---------------------------------------------------------------------------
extern "C" void kernel_launch(void* const* d_in, const int* in_sizes, int n_in,
                              void* d_out, int out_size)
{
    const float* Q     = (const float*)d_in[0];
    const float* K     = (const float*)d_in[1];
    const float* V     = (const float*)d_in[2];
    const float* tmat  = (const float*)d_in[3];
    const float* dmat  = (const float*)d_in[4];
    const int*   mask  = (const int*)  d_in[5];
    const float* Wq    = (const float*)d_in[6];
    const float* bq    = (const float*)d_in[7];
    const float* Wk    = (const float*)d_in[8];
    const float* bk    = (const float*)d_in[9];
    const float* Wv    = (const float*)d_in[10];
    const float* bv    = (const float*)d_in[11];
    const float* Wo    = (const float*)d_in[12];
    const float* bo    = (const float*)d_in[13];
    const float* tm_w  = (const float*)d_in[14];
    const float* tm_b  = (const float*)d_in[15];
    const float* dm_w  = (const float*)d_in[16];
    const float* dm_b  = (const float*)d_in[17];
    const float* td_w  = (const float*)d_in[18];
    const float* td_b  = (const float*)d_in[19];
    float* out = (float*)d_out;

    float* ab;
    cudaGetSymbolAddress((void**)&ab, g_attn);
    __half *qh, *ql, *kh, *kl, *vh, *vl;
    cudaGetSymbolAddress((void**)&qh, g_qh);
    cudaGetSymbolAddress((void**)&ql, g_ql);
    cudaGetSymbolAddress((void**)&kh, g_kh);
    cudaGetSymbolAddress((void**)&kl, g_kl);
    cudaGetSymbolAddress((void**)&vh, g_vh);
    cudaGetSymbolAddress((void**)&vl, g_vl);

    prep_kernel<<<1, 32>>>(tm_w, tm_b, dm_w, dm_b, td_w);

    // fused Q/K/V projections -> fp16 hi/lo planes (Q pre-scaled by log2e/8)
    gemm_qkv<<<dim3(D_ / 128, MTOT / 128, 3), 256>>>(
        Q, K, V, Wq, Wk, Wv, bq, bk, bv,
        out /*unused*/, qh, ql, kh, kl, vh, vl,
        MTOT, D_, D_, 0.125f * LOG2E, 1);

    bias_mask_kernel<<<(B_ * S_ * S_) / 1024, 256>>>(
        tmat, dmat, mask, tm_w, tm_b, dm_w, dm_b, td_w, td_b);

    cudaFuncSetAttribute(attn_f16,
                         cudaFuncAttributeMaxDynamicSharedMemorySize, SMEM_ATTN);
    attn_f16<<<dim3(S_ / 64, H_, B_), 128, SMEM_ATTN>>>();

    // output projection: fp32 in (g_attn), fp32 out
    gemm_qkv<<<dim3(D_ / 128, MTOT / 128, 1), 256>>>(
        ab, ab, ab, Wo, Wo, Wo, bo, bo, bo,
        out, qh, ql, kh, kl, vh, vl,
        MTOT, D_, D_, 1.f, 0);
}

// round 9
// speedup vs baseline: 1.2112x; 1.0004x over previous
#include <cuda_runtime.h>
#include <cuda_bf16.h>
#include <cuda_fp16.h>
#include <cstdint>

#define B_  4
#define S_  1024
#define D_  512
#define H_  8
#define DK_ 64
#define MTOT (B_*S_)          // 4096 rows
#define NELE (B_*S_*D_)       // 2,097,152
#define DD   (D_*D_)
#define LOG2E 1.4426950408889634f

// Scratch (static device globals — allowed; no cudaMalloc anywhere)
__device__ __nv_bfloat16 g_in_h[(size_t)3*NELE], g_in_l[(size_t)3*NELE]; // Q,K,V inputs split
__device__ __nv_bfloat16 g_w_h[4*DD], g_w_l[4*DD];                        // Wq,Wk,Wv,Wo split
__device__ __nv_bfloat16 g_oh[NELE], g_ol[NELE];                          // attn out split
__device__ __half g_qh[NELE], g_ql[NELE];   // projected Q (pre-scaled by log2e/8)
__device__ __half g_kh[NELE], g_kl[NELE];
__device__ __half g_vh[NELE];
__device__ float g_bias[(size_t)B_*S_*S_];  // bias*log2e, mask folded as -1.5e9
__device__ float g_Ct, g_Cd;
__device__ int   g_bzero;

// ---------------------------------------------------------------------------
// helpers
// ---------------------------------------------------------------------------
__device__ __forceinline__ float ex2f(float x) {
    float r; asm("ex2.approx.f32 %0, %1;" : "=f"(r) : "f"(x)); return r;
}

__device__ __forceinline__ void mma_bf16(float c[4],
    uint32_t a0, uint32_t a1, uint32_t a2, uint32_t a3,
    uint32_t b0, uint32_t b1)
{
    asm volatile(
        "mma.sync.aligned.m16n8k16.row.col.f32.bf16.bf16.f32 "
        "{%0,%1,%2,%3},{%4,%5,%6,%7},{%8,%9},{%0,%1,%2,%3};"
        : "+f"(c[0]), "+f"(c[1]), "+f"(c[2]), "+f"(c[3])
        : "r"(a0), "r"(a1), "r"(a2), "r"(a3), "r"(b0), "r"(b1));
}

__device__ __forceinline__ void mma_f16(float c[4],
    uint32_t a0, uint32_t a1, uint32_t a2, uint32_t a3,
    uint32_t b0, uint32_t b1)
{
    asm volatile(
        "mma.sync.aligned.m16n8k16.row.col.f32.f16.f16.f32 "
        "{%0,%1,%2,%3},{%4,%5,%6,%7},{%8,%9},{%0,%1,%2,%3};"
        : "+f"(c[0]), "+f"(c[1]), "+f"(c[2]), "+f"(c[3])
        : "r"(a0), "r"(a1), "r"(a2), "r"(a3), "r"(b0), "r"(b1));
}

__device__ __forceinline__ void ldsm_x4(uint32_t& r0, uint32_t& r1,
                                        uint32_t& r2, uint32_t& r3, uint32_t addr)
{
    asm volatile("ldmatrix.sync.aligned.m8n8.x4.shared.b16 {%0,%1,%2,%3}, [%4];"
        : "=r"(r0), "=r"(r1), "=r"(r2), "=r"(r3) : "r"(addr));
}

__device__ __forceinline__ void ldsm_x4_t(uint32_t& r0, uint32_t& r1,
                                          uint32_t& r2, uint32_t& r3, uint32_t addr)
{
    asm volatile("ldmatrix.sync.aligned.m8n8.x4.trans.shared.b16 {%0,%1,%2,%3}, [%4];"
        : "=r"(r0), "=r"(r1), "=r"(r2), "=r"(r3) : "r"(addr));
}

__device__ __forceinline__ void ldsm_x2_t(uint32_t& r0, uint32_t& r1, uint32_t addr)
{
    asm volatile("ldmatrix.sync.aligned.m8n8.x2.trans.shared.b16 {%0,%1}, [%2];"
        : "=r"(r0), "=r"(r1) : "r"(addr));
}

__device__ __forceinline__ void cpa16(uint32_t dst, const void* src) {
    asm volatile("cp.async.cg.shared.global [%0], [%1], 16;" :: "r"(dst), "l"(src));
}
__device__ __forceinline__ void cp_commit() {
    asm volatile("cp.async.commit_group;");
}
template<int N> __device__ __forceinline__ void cp_wait() {
    asm volatile("cp.async.wait_group %0;" :: "n"(N));
}

// fp16 hi/lo split pack of a float pair
__device__ __forceinline__ void pack_hilo_h(float x, float y, uint32_t& hi, uint32_t& lo) {
    __half2 h = __floats2half2_rn(x, y);
    float2 f = __half22float2(h);
    __half2 l = __floats2half2_rn(x - f.x, y - f.y);
    hi = *reinterpret_cast<uint32_t*>(&h);
    lo = *reinterpret_cast<uint32_t*>(&l);
}
// bf16 hi/lo split pack
__device__ __forceinline__ void pack_hilo_b(float x, float y, uint32_t& hi, uint32_t& lo) {
    __nv_bfloat162 h = __floats2bfloat162_rn(x, y);
    float2 f = __bfloat1622float2(h);
    __nv_bfloat162 l = __floats2bfloat162_rn(x - f.x, y - f.y);
    hi = *reinterpret_cast<uint32_t*>(&h);
    lo = *reinterpret_cast<uint32_t*>(&l);
}

// ---------------------------------------------------------------------------
// Split fp32 tensor(s) -> bf16 hi/lo planes. Tensor selected by blockIdx.y.
// ---------------------------------------------------------------------------
__global__ __launch_bounds__(256) void split_hilo(
    const float* __restrict__ s0, const float* __restrict__ s1,
    const float* __restrict__ s2, const float* __restrict__ s3,
    __nv_bfloat16* __restrict__ h, __nv_bfloat16* __restrict__ l, int per)
{
    const float* s = (blockIdx.y == 0) ? s0 : (blockIdx.y == 1) ? s1
                    : (blockIdx.y == 2) ? s2 : s3;
    const size_t si = ((size_t)blockIdx.x * 256 + threadIdx.x) * 4;
    float4 v = *(const float4*)&s[si];
    uint32_t h01, l01, h23, l23;
    pack_hilo_b(v.x, v.y, h01, l01);
    pack_hilo_b(v.z, v.w, h23, l23);
    const size_t di = (size_t)blockIdx.y * per + si;
    *(uint2*)&h[di] = make_uint2(h01, h23);
    *(uint2*)&l[di] = make_uint2(l01, l23);
}

// ---------------------------------------------------------------------------
// GEMM on pre-split bf16 hi/lo planes (up to 3 problems via blockIdx.z):
//   R = (A @ W + bias) * (z==0 ? scale0 : 1)
// Pure cp.async double-buffered pipeline; no conversions in the loop.
// ---------------------------------------------------------------------------
#define AKP 40
#define BNP 136
#define AS (128*AKP)
#define BS (32*BNP)
#define GSMEM ((4*AS + 4*BS) * 2)   // bytes (2 stages x 2 planes each side)

__global__ __launch_bounds__(256, 2) void gemm_planes(
    const __nv_bfloat16* __restrict__ Ah_, const __nv_bfloat16* __restrict__ Al_,
    const __nv_bfloat16* __restrict__ Wh_, const __nv_bfloat16* __restrict__ Wl_,
    size_t aStride, size_t wStride,
    const float* __restrict__ b0v, const float* __restrict__ b1v, const float* __restrict__ b2v,
    float* __restrict__ C0,
    __half* __restrict__ H0, __half* __restrict__ L0,
    __half* __restrict__ H1, __half* __restrict__ L1,
    __half* __restrict__ H2, __half* __restrict__ L2,
    int M, int N, int K, float scale0, int fp16_out)
{
    extern __shared__ __nv_bfloat16 gsm[];
    __nv_bfloat16* Ahs = gsm;                 // [2][AS]
    __nv_bfloat16* Als = gsm + 2 * AS;        // [2][AS]
    __nv_bfloat16* Bhs = gsm + 4 * AS;        // [2][BS]
    __nv_bfloat16* Bls = gsm + 4 * AS + 2 * BS;

    const int z = blockIdx.z;
    const __nv_bfloat16* Ah = Ah_ + (size_t)z * aStride;
    const __nv_bfloat16* Al = Al_ + (size_t)z * aStride;
    const __nv_bfloat16* Wh = Wh_ + (size_t)z * wStride;
    const __nv_bfloat16* Wl = Wl_ + (size_t)z * wStride;
    const float* bias = (z == 0) ? b0v : (z == 1) ? b1v : b2v;
    __half* Ho = (z == 0) ? H0 : (z == 1) ? H1 : H2;
    __half* Lo = (z == 0) ? L0 : (z == 1) ? L1 : L2;
    const float osc = (z == 0) ? scale0 : 1.f;
    const bool  wlo = (z != 2);   // V lo-plane never read

    const int t = threadIdx.x;
    const int lane = t & 31, wid = t >> 5;
    const int warp_m = wid & 3, warp_n = wid >> 2;
    const int m_w = warp_m * 32, n_w = warp_n * 64;
    const int bm = blockIdx.y * 128, bn = blockIdx.x * 128;
    const int gid = lane >> 2, tig = lane & 3;

    float acc[2][8][4];
    #pragma unroll
    for (int mt = 0; mt < 2; mt++)
        #pragma unroll
        for (int nt = 0; nt < 8; nt++)
            #pragma unroll
            for (int e = 0; e < 4; e++) acc[mt][nt][e] = 0.f;

    // per-thread copy coordinates (512 chunks per plane, 2 per thread)
    const int c0 = t, c1 = t + 256;

    // ---- issue k-tile 'st' copies
    auto issue = [&](int st, int k0) {
        #pragma unroll
        for (int r = 0; r < 2; r++) {
            int c = (r == 0) ? c0 : c1;
            int arow = c >> 2, ak = (c & 3) * 8;
            size_t ga = (size_t)(bm + arow) * K + k0 + ak;
            cpa16((uint32_t)__cvta_generic_to_shared(&Ahs[st * AS + arow * AKP + ak]), &Ah[ga]);
            cpa16((uint32_t)__cvta_generic_to_shared(&Als[st * AS + arow * AKP + ak]), &Al[ga]);
            int krow = c >> 4, nc = (c & 15) * 8;
            size_t gb = (size_t)(k0 + krow) * N + bn + nc;
            cpa16((uint32_t)__cvta_generic_to_shared(&Bhs[st * BS + krow * BNP + nc]), &Wh[gb]);
            cpa16((uint32_t)__cvta_generic_to_shared(&Bls[st * BS + krow * BNP + nc]), &Wl[gb]);
        }
    };

    issue(0, 0);
    cp_commit();

    const int NIT = K / 32;
    for (int it = 0; it < NIT; it++) {
        const int st = it & 1;
        if (it + 1 < NIT) {
            issue(st ^ 1, (it + 1) * 32);
            cp_commit();
            cp_wait<1>();
        } else {
            cp_wait<0>();
        }
        __syncthreads();

        #pragma unroll
        for (int kb = 0; kb < 32; kb += 16) {
            uint32_t af[2][2][4];
            #pragma unroll
            for (int mt = 0; mt < 2; mt++) {
                const int arow = m_w + mt * 16 + (lane & 15);
                const int acol = kb + ((lane >> 4) << 3);
                ldsm_x4(af[mt][0][0], af[mt][0][1], af[mt][0][2], af[mt][0][3],
                        (uint32_t)__cvta_generic_to_shared(&Ahs[st * AS + arow * AKP + acol]));
                ldsm_x4(af[mt][1][0], af[mt][1][1], af[mt][1][2], af[mt][1][3],
                        (uint32_t)__cvta_generic_to_shared(&Als[st * AS + arow * AKP + acol]));
            }
            #pragma unroll
            for (int nt = 0; nt < 8; nt++) {
                const int brow = kb + (lane & 15);
                const int bcol = n_w + nt * 8;
                uint32_t bh0, bh1, bl0, bl1;
                ldsm_x2_t(bh0, bh1,
                    (uint32_t)__cvta_generic_to_shared(&Bhs[st * BS + brow * BNP + bcol]));
                ldsm_x2_t(bl0, bl1,
                    (uint32_t)__cvta_generic_to_shared(&Bls[st * BS + brow * BNP + bcol]));
                #pragma unroll
                for (int mt = 0; mt < 2; mt++) {
                    mma_bf16(acc[mt][nt], af[mt][0][0], af[mt][0][1],
                             af[mt][0][2], af[mt][0][3], bh0, bh1);
                    mma_bf16(acc[mt][nt], af[mt][1][0], af[mt][1][1],
                             af[mt][1][2], af[mt][1][3], bh0, bh1);
                    mma_bf16(acc[mt][nt], af[mt][0][0], af[mt][0][1],
                             af[mt][0][2], af[mt][0][3], bl0, bl1);
                }
            }
        }
        __syncthreads();
    }

    // ---- epilogue
    #pragma unroll
    for (int mt = 0; mt < 2; mt++) {
        const int row0 = bm + m_w + mt * 16 + gid;
        #pragma unroll
        for (int nt = 0; nt < 8; nt++) {
            const int col = bn + n_w + nt * 8 + tig * 2;
            float2 bb = *(const float2*)&bias[col];
            float v0 = (acc[mt][nt][0] + bb.x) * osc;
            float v1 = (acc[mt][nt][1] + bb.y) * osc;
            float v2 = (acc[mt][nt][2] + bb.x) * osc;
            float v3 = (acc[mt][nt][3] + bb.y) * osc;
            if (fp16_out) {
                uint32_t h01, l01, h23, l23;
                pack_hilo_h(v0, v1, h01, l01);
                pack_hilo_h(v2, v3, h23, l23);
                *(uint32_t*)&Ho[(size_t)row0 * N + col]       = h01;
                *(uint32_t*)&Ho[(size_t)(row0 + 8) * N + col] = h23;
                if (wlo) {
                    *(uint32_t*)&Lo[(size_t)row0 * N + col]       = l01;
                    *(uint32_t*)&Lo[(size_t)(row0 + 8) * N + col] = l23;
                }
            } else {
                *(float2*)&C0[(size_t)row0 * N + col]       = make_float2(v0, v1);
                *(float2*)&C0[(size_t)(row0 + 8) * N + col] = make_float2(v2, v3);
            }
        }
    }
}

// ---------------------------------------------------------------------------
// Prep: detect all-zero biases; precompute collapsed coefficients (log2 domain)
// ---------------------------------------------------------------------------
__global__ void prep_kernel(const float* __restrict__ tm_w, const float* __restrict__ tm_b,
                            const float* __restrict__ dm_w, const float* __restrict__ dm_b,
                            const float* __restrict__ td_w)
{
    const int l = threadIdx.x;   // 32 threads
    float ct = 0.f, cd = 0.f;
    bool z = true;
    #pragma unroll
    for (int m = l; m < 64; m += 32) {
        z = z && (tm_b[m] == 0.f) && (dm_b[m] == 0.f);
        ct += (0.5f * LOG2E) * td_w[m] * fmaxf(tm_w[m], 0.f);
        cd += (0.5f * LOG2E) * td_w[m] * fmaxf(dm_w[m], 0.f);
    }
    unsigned bz = __ballot_sync(0xffffffffu, z);
    #pragma unroll
    for (int o = 16; o; o >>= 1) {
        ct += __shfl_xor_sync(0xffffffffu, ct, o);
        cd += __shfl_xor_sync(0xffffffffu, cd, o);
    }
    if (l == 0) { g_Ct = ct; g_Cd = cd; g_bzero = (bz == 0xffffffffu); }
}

// ---------------------------------------------------------------------------
// Fused bias + mask (log2 domain). Fast path: 2 FMAs per element.
// ---------------------------------------------------------------------------
__global__ __launch_bounds__(256) void bias_mask_kernel(
    const float* __restrict__ tmat, const float* __restrict__ dmat,
    const int*   __restrict__ mask,
    const float* __restrict__ tm_w, const float* __restrict__ tm_b,
    const float* __restrict__ dm_w, const float* __restrict__ dm_b,
    const float* __restrict__ td_w, const float* __restrict__ td_b)
{
    const int t = threadIdx.x;
    const float tdb = td_b[0] * LOG2E;
    const float E = 2.718281828459045f;

    const size_t base = ((size_t)blockIdx.x * 256 + t) * 4;
    float4 u  = *(const float4*)(tmat + base);
    float4 w  = *(const float4*)(dmat + base);
    int4   mk = *(const int4*)(mask + base);

    float tv[4] = { 1.f / __logf(E + u.x), 1.f / __logf(E + u.y),
                    1.f / __logf(E + u.z), 1.f / __logf(E + u.w) };
    float dv[4] = { 1.f / __logf(E + w.x), 1.f / __logf(E + w.y),
                    1.f / __logf(E + w.z), 1.f / __logf(E + w.w) };
    float acc[4];

    if (g_bzero) {
        const float Ct = g_Ct, Cd = g_Cd;
        #pragma unroll
        for (int i = 0; i < 4; i++)
            acc[i] = fmaf(tv[i], Ct, fmaf(dv[i], Cd, tdb));
    } else {
        __shared__ float sp[5][64];
        if (t < 64) {
            sp[0][t] = tm_w[t];
            sp[1][t] = tm_b[t];
            sp[2][t] = dm_w[t];
            sp[3][t] = dm_b[t];
            sp[4][t] = td_w[t] * 0.5f * LOG2E;
        }
        __syncthreads();
        #pragma unroll
        for (int i = 0; i < 4; i++) acc[i] = tdb;
        #pragma unroll 8
        for (int m = 0; m < 64; m++) {
            const float tw = sp[0][m], tb = sp[1][m];
            const float dw = sp[2][m], db = sp[3][m];
            const float ww = sp[4][m];
            #pragma unroll
            for (int i = 0; i < 4; i++) {
                float rt = fmaxf(tv[i] * tw + tb, 0.f);
                float rd = fmaxf(dv[i] * dw + db, 0.f);
                acc[i] += ww * (rt + rd);
            }
        }
    }

    float4 o;
    o.x = (mk.x == 1) ? -1.5e9f : acc[0];
    o.y = (mk.y == 1) ? -1.5e9f : acc[1];
    o.z = (mk.z == 1) ? -1.5e9f : acc[2];
    o.w = (mk.w == 1) ? -1.5e9f : acc[3];
    *(float4*)(g_bias + base) = o;
}

// ---------------------------------------------------------------------------
// Flash attention, fp16 TC, log2-domain softmax, smem-staged bias.
// Output written directly as bf16 hi/lo planes for the O projection.
// ---------------------------------------------------------------------------
#define PS 72
#define PE (64*PS)
#define BSS 68                  // bias smem row stride (floats)
#define SMEM_ATTN (8*PE*2)

__global__ __launch_bounds__(128, 3) void attn_f16()
{
    extern __shared__ __half sm[];
    float* biasS = (float*)sm;   // overlays Q planes 0,1 after prologue

    const int qt = blockIdx.x, h = blockIdx.y, b = blockIdx.z;
    const int t = threadIdx.x;
    const int w = t >> 5, lane = t & 31;
    const int gid = lane >> 2, tig = lane & 3;
    const int q0 = qt * 64, hoff = h * DK_;
    const int tr = w * 16 + gid;              // this thread's first q row (local)
    const int m_idx = lane >> 3, rin = lane & 7;

    // ---- prologue: Q planes + K/V tile0 planes (buf0 = planes 2,3,4)
    #pragma unroll
    for (int i = 0; i < 4; i++) {
        int c = t + i * 128;
        int row = c >> 3, col = (c & 7) * 8;
        size_t gq = (size_t)(b * S_ + q0 + row) * D_ + hoff + col;
        size_t gk = (size_t)(b * S_ + row) * D_ + hoff + col;
        uint32_t so = row * PS + col;
        cpa16((uint32_t)__cvta_generic_to_shared(&sm[0*PE + so]), &g_qh[gq]);
        cpa16((uint32_t)__cvta_generic_to_shared(&sm[1*PE + so]), &g_ql[gq]);
        cpa16((uint32_t)__cvta_generic_to_shared(&sm[2*PE + so]), &g_kh[gk]);
        cpa16((uint32_t)__cvta_generic_to_shared(&sm[3*PE + so]), &g_kl[gk]);
        cpa16((uint32_t)__cvta_generic_to_shared(&sm[4*PE + so]), &g_vh[gk]);
    }
    cp_commit();
    cp_wait<0>();
    __syncthreads();

    // ---- Q fragments, loop-invariant, held in registers
    uint32_t qf[4][2][4];   // [d16-step][plane][reg]
    #pragma unroll
    for (int d8 = 0; d8 < 4; d8++)
        #pragma unroll
        for (int p = 0; p < 2; p++) {
            uint32_t a = (uint32_t)__cvta_generic_to_shared(
                &sm[p*PE + (w * 16 + (lane & 15)) * PS + d8 * 16 + ((lane >> 4) << 3)]);
            ldsm_x4(qf[d8][p][0], qf[d8][p][1], qf[d8][p][2], qf[d8][p][3], a);
        }
    __syncthreads();   // Q planes now dead -> become the bias buffer

    float m0 = -1e30f, m1 = -1e30f, l0 = 0.f, l1 = 0.f;
    float oacc[8][4];
    #pragma unroll
    for (int nt = 0; nt < 8; nt++)
        #pragma unroll
        for (int e = 0; e < 4; e++) oacc[nt][e] = 0.f;

    for (int kt = 0; kt < 16; kt++) {
        const int buf = kt & 1;

        // ---- issue bias(kt) copy into biasS (group B_kt)
        #pragma unroll
        for (int i = 0; i < 8; i++) {
            int idx = t + i * 128;
            int row = idx >> 4, c4 = (idx & 15) << 2;
            cpa16((uint32_t)__cvta_generic_to_shared(&biasS[row * BSS + c4]),
                  &g_bias[((size_t)(b * S_ + q0 + row)) * S_ + kt * 64 + c4]);
        }
        cp_commit();

        // ---- issue KV(kt+1), then wait for KV(kt)
        if (kt < 15) {
            const int k1 = (kt + 1) * 64;
            const int KHn = (2 + 3 * (buf ^ 1)) * PE;
            #pragma unroll
            for (int i = 0; i < 4; i++) {
                int c = t + i * 128;
                int row = c >> 3, col = (c & 7) * 8;
                size_t g = (size_t)(b * S_ + k1 + row) * D_ + hoff + col;
                uint32_t so = row * PS + col;
                cpa16((uint32_t)__cvta_generic_to_shared(&sm[KHn + so]),          &g_kh[g]);
                cpa16((uint32_t)__cvta_generic_to_shared(&sm[KHn + PE + so]),     &g_kl[g]);
                cpa16((uint32_t)__cvta_generic_to_shared(&sm[KHn + 2 * PE + so]), &g_vh[g]);
            }
            cp_commit();
            cp_wait<2>();     // KV(kt) done; B_kt and KV(kt+1) in flight
        } else {
            cp_wait<1>();     // KV(15) done; B_15 in flight
        }
        __syncthreads();

        const int KH = (2 + 3 * buf) * PE;       // Kh plane; Kl = KH+PE; V = KH+2*PE

        // ---- scores S = Q @ K^T (log2-domain) : 3-term fp16 split
        float sacc[8][4];
        #pragma unroll
        for (int nt = 0; nt < 8; nt++)
            #pragma unroll
            for (int e = 0; e < 4; e++) sacc[nt][e] = 0.f;

        #pragma unroll
        for (int d8 = 0; d8 < 4; d8++) {
            #pragma unroll
            for (int p = 0; p < 4; p++) {
                uint32_t boff = (p * 16 + ((m_idx & 1) << 3) + rin) * PS
                              + d8 * 16 + ((m_idx >> 1) << 3);
                uint32_t kh0, kh1, kh2, kh3, kl0, kl1, kl2, kl3;
                ldsm_x4(kh0, kh1, kh2, kh3,
                        (uint32_t)__cvta_generic_to_shared(&sm[KH + boff]));
                ldsm_x4(kl0, kl1, kl2, kl3,
                        (uint32_t)__cvta_generic_to_shared(&sm[KH + PE + boff]));
                mma_f16(sacc[2*p],   qf[d8][0][0], qf[d8][0][1], qf[d8][0][2], qf[d8][0][3], kh0, kh2);
                mma_f16(sacc[2*p],   qf[d8][1][0], qf[d8][1][1], qf[d8][1][2], qf[d8][1][3], kh0, kh2);
                mma_f16(sacc[2*p],   qf[d8][0][0], qf[d8][0][1], qf[d8][0][2], qf[d8][0][3], kl0, kl2);
                mma_f16(sacc[2*p+1], qf[d8][0][0], qf[d8][0][1], qf[d8][0][2], qf[d8][0][3], kh1, kh3);
                mma_f16(sacc[2*p+1], qf[d8][1][0], qf[d8][1][1], qf[d8][1][2], qf[d8][1][3], kh1, kh3);
                mma_f16(sacc[2*p+1], qf[d8][0][0], qf[d8][0][1], qf[d8][0][2], qf[d8][0][3], kl1, kl3);
            }
        }

        // ---- bias now resident in smem
        if (kt < 15) { cp_wait<1>(); } else { cp_wait<0>(); }
        __syncthreads();

        float mx0 = -1e30f, mx1 = -1e30f;
        #pragma unroll
        for (int nt = 0; nt < 8; nt++) {
            float2 ba = *(const float2*)&biasS[tr * BSS + nt * 8 + tig * 2];
            float2 bb = *(const float2*)&biasS[(tr + 8) * BSS + nt * 8 + tig * 2];
            sacc[nt][0] += ba.x;
            sacc[nt][1] += ba.y;
            sacc[nt][2] += bb.x;
            sacc[nt][3] += bb.y;
            mx0 = fmaxf(mx0, fmaxf(sacc[nt][0], sacc[nt][1]));
            mx1 = fmaxf(mx1, fmaxf(sacc[nt][2], sacc[nt][3]));
        }
        mx0 = fmaxf(mx0, __shfl_xor_sync(0xffffffffu, mx0, 1));
        mx0 = fmaxf(mx0, __shfl_xor_sync(0xffffffffu, mx0, 2));
        mx1 = fmaxf(mx1, __shfl_xor_sync(0xffffffffu, mx1, 1));
        mx1 = fmaxf(mx1, __shfl_xor_sync(0xffffffffu, mx1, 2));

        const float mn0 = fmaxf(m0, mx0), mn1 = fmaxf(m1, mx1);
        const float c0 = ex2f(m0 - mn0), c1 = ex2f(m1 - mn1);
        m0 = mn0; m1 = mn1;

        float rs0 = 0.f, rs1 = 0.f;
        #pragma unroll
        for (int nt = 0; nt < 8; nt++) {
            sacc[nt][0] = ex2f(sacc[nt][0] - mn0);
            sacc[nt][1] = ex2f(sacc[nt][1] - mn0);
            sacc[nt][2] = ex2f(sacc[nt][2] - mn1);
            sacc[nt][3] = ex2f(sacc[nt][3] - mn1);
            rs0 += sacc[nt][0] + sacc[nt][1];
            rs1 += sacc[nt][2] + sacc[nt][3];
        }
        rs0 += __shfl_xor_sync(0xffffffffu, rs0, 1);
        rs0 += __shfl_xor_sync(0xffffffffu, rs0, 2);
        rs1 += __shfl_xor_sync(0xffffffffu, rs1, 1);
        rs1 += __shfl_xor_sync(0xffffffffu, rs1, 2);

        l0 = l0 * c0 + rs0;
        l1 = l1 * c1 + rs1;
        #pragma unroll
        for (int nt = 0; nt < 8; nt++) {
            oacc[nt][0] *= c0; oacc[nt][1] *= c0;
            oacc[nt][2] *= c1; oacc[nt][3] *= c1;
        }

        // ---- pack P into fp16 A-fragments (registers only)
        uint32_t pa[4][4];   // [j16-step][reg]
        #pragma unroll
        for (int j8 = 0; j8 < 4; j8++) {
            const float* sA = sacc[2 * j8];
            const float* sB = sacc[2 * j8 + 1];
            __half2 hh;
            hh = __floats2half2_rn(sA[0], sA[1]); pa[j8][0] = *(uint32_t*)&hh;
            hh = __floats2half2_rn(sA[2], sA[3]); pa[j8][1] = *(uint32_t*)&hh;
            hh = __floats2half2_rn(sB[0], sB[1]); pa[j8][2] = *(uint32_t*)&hh;
            hh = __floats2half2_rn(sB[2], sB[3]); pa[j8][3] = *(uint32_t*)&hh;
        }

        // ---- O += P @ V : single-term fp16, V via ldmatrix.x4.trans
        #pragma unroll
        for (int j8 = 0; j8 < 4; j8++) {
            #pragma unroll
            for (int p = 0; p < 4; p++) {
                uint32_t boff = (j8 * 16 + ((m_idx & 1) << 3) + rin) * PS
                              + p * 16 + ((m_idx >> 1) << 3);
                uint32_t vh0, vh1, vh2, vh3;
                ldsm_x4_t(vh0, vh1, vh2, vh3,
                          (uint32_t)__cvta_generic_to_shared(&sm[KH + 2 * PE + boff]));
                mma_f16(oacc[2*p],   pa[j8][0], pa[j8][1], pa[j8][2], pa[j8][3], vh0, vh1);
                mma_f16(oacc[2*p+1], pa[j8][0], pa[j8][1], pa[j8][2], pa[j8][3], vh2, vh3);
            }
        }
        __syncthreads();   // KV buf + bias reads done before next overwrite
    }

    // ---- epilogue: normalize, write bf16 hi/lo planes [B,S,D]
    const float inv0 = 1.f / l0, inv1 = 1.f / l1;
    const size_t o0 = (size_t)(b * S_ + q0 + tr) * D_ + hoff;
    const size_t o1 = o0 + (size_t)8 * D_;
    #pragma unroll
    for (int nt = 0; nt < 8; nt++) {
        const int coff = nt * 8 + tig * 2;
        uint32_t h01, l01, h23, l23;
        pack_hilo_b(oacc[nt][0] * inv0, oacc[nt][1] * inv0, h01, l01);
        pack_hilo_b(oacc[nt][2] * inv1, oacc[nt][3] * inv1, h23, l23);
        *(uint32_t*)&g_oh[o0 + coff] = h01;
        *(uint32_t*)&g_ol[o0 + coff] = l01;
        *(uint32_t*)&g_oh[o1 + coff] = h23;
        *(uint32_t*)&g_ol[o1 + coff] = l23;
    }
}

// ---------------------------------------------------------------------------
extern "C" void kernel_launch(void* const* d_in, const int* in_sizes, int n_in,
                              void* d_out, int out_size)
{
    const float* Q     = (const float*)d_in[0];
    const float* K     = (const float*)d_in[1];
    const float* V     = (const float*)d_in[2];
    const float* tmat  = (const float*)d_in[3];
    const float* dmat  = (const float*)d_in[4];
    const int*   mask  = (const int*)  d_in[5];
    const float* Wq    = (const float*)d_in[6];
    const float* bq    = (const float*)d_in[7];
    const float* Wk    = (const float*)d_in[8];
    const float* bk    = (const float*)d_in[9];
    const float* Wv    = (const float*)d_in[10];
    const float* bv    = (const float*)d_in[11];
    const float* Wo    = (const float*)d_in[12];
    const float* bo    = (const float*)d_in[13];
    const float* tm_w  = (const float*)d_in[14];
    const float* tm_b  = (const float*)d_in[15];
    const float* dm_w  = (const float*)d_in[16];
    const float* dm_b  = (const float*)d_in[17];
    const float* td_w  = (const float*)d_in[18];
    const float* td_b  = (const float*)d_in[19];
    float* out = (float*)d_out;

    __nv_bfloat16 *inh, *inl, *wh, *wl, *oh, *ol;
    cudaGetSymbolAddress((void**)&inh, g_in_h);
    cudaGetSymbolAddress((void**)&inl, g_in_l);
    cudaGetSymbolAddress((void**)&wh,  g_w_h);
    cudaGetSymbolAddress((void**)&wl,  g_w_l);
    cudaGetSymbolAddress((void**)&oh,  g_oh);
    cudaGetSymbolAddress((void**)&ol,  g_ol);
    __half *qh, *ql, *kh, *kl, *vh;
    cudaGetSymbolAddress((void**)&qh, g_qh);
    cudaGetSymbolAddress((void**)&ql, g_ql);
    cudaGetSymbolAddress((void**)&kh, g_kh);
    cudaGetSymbolAddress((void**)&kl, g_kl);
    cudaGetSymbolAddress((void**)&vh, g_vh);

    prep_kernel<<<1, 32>>>(tm_w, tm_b, dm_w, dm_b, td_w);

    // pre-split operands to bf16 hi/lo planes
    split_hilo<<<dim3(NELE / 1024, 3), 256>>>(Q, K, V, Q, inh, inl, NELE);
    split_hilo<<<dim3(DD / 1024, 4), 256>>>(Wq, Wk, Wv, Wo, wh, wl, DD);

    cudaFuncSetAttribute(gemm_planes,
                         cudaFuncAttributeMaxDynamicSharedMemorySize, GSMEM);

    // fused Q/K/V projections -> fp16 hi/lo planes (Q pre-scaled by log2e/8)
    gemm_planes<<<dim3(D_ / 128, MTOT / 128, 3), 256, GSMEM>>>(
        inh, inl, wh, wl, (size_t)NELE, (size_t)DD,
        bq, bk, bv,
        out /*unused*/, qh, ql, kh, kl, vh, vh /*dummy*/,
        MTOT, D_, D_, 0.125f * LOG2E, 1);

    bias_mask_kernel<<<(B_ * S_ * S_) / 1024, 256>>>(
        tmat, dmat, mask, tm_w, tm_b, dm_w, dm_b, td_w, td_b);

    cudaFuncSetAttribute(attn_f16,
                         cudaFuncAttributeMaxDynamicSharedMemorySize, SMEM_ATTN);
    attn_f16<<<dim3(S_ / 64, H_, B_), 128, SMEM_ATTN>>>();

    // output projection: bf16 planes in (attn output), fp32 out
    gemm_planes<<<dim3(D_ / 128, MTOT / 128, 1), 256, GSMEM>>>(
        oh, ol, wh + (size_t)3 * DD, wl + (size_t)3 * DD, 0, 0,
        bo, bo, bo,
        out, qh, ql, kh, kl, vh, vh,
        MTOT, D_, D_, 1.f, 0);
}

// round 10
// speedup vs baseline: 1.2932x; 1.0677x over previous
#include <cuda_runtime.h>
#include <cuda_bf16.h>
#include <cuda_fp16.h>
#include <cstdint>

#define B_  4
#define S_  1024
#define D_  512
#define H_  8
#define DK_ 64
#define MTOT (B_*S_)          // 4096 rows
#define NELE (B_*S_*D_)       // 2,097,152
#define DD   (D_*D_)
#define LOG2E 1.4426950408889634f

// Scratch (static device globals — allowed; no cudaMalloc anywhere)
__device__ __nv_bfloat16 g_in_h[(size_t)3*NELE], g_in_l[(size_t)3*NELE]; // Q,K,V inputs split
__device__ __nv_bfloat16 g_w_h[4*DD], g_w_l[4*DD];                        // Wq,Wk,Wv,Wo split
__device__ __nv_bfloat16 g_oh[NELE], g_ol[NELE];                          // attn out split
__device__ __half g_qh[NELE], g_ql[NELE];   // projected Q (pre-scaled by log2e/8)
__device__ __half g_kh[NELE], g_kl[NELE];
__device__ __half g_vh[NELE];
__device__ float g_bias[(size_t)B_*S_*S_];  // bias*log2e, mask folded as -1.5e9
__device__ float g_Ct, g_Cd;
__device__ int   g_bzero;

// ---------------------------------------------------------------------------
// helpers
// ---------------------------------------------------------------------------
__device__ __forceinline__ float ex2f(float x) {
    float r; asm("ex2.approx.f32 %0, %1;" : "=f"(r) : "f"(x)); return r;
}

__device__ __forceinline__ void mma_bf16(float c[4],
    uint32_t a0, uint32_t a1, uint32_t a2, uint32_t a3,
    uint32_t b0, uint32_t b1)
{
    asm volatile(
        "mma.sync.aligned.m16n8k16.row.col.f32.bf16.bf16.f32 "
        "{%0,%1,%2,%3},{%4,%5,%6,%7},{%8,%9},{%0,%1,%2,%3};"
        : "+f"(c[0]), "+f"(c[1]), "+f"(c[2]), "+f"(c[3])
        : "r"(a0), "r"(a1), "r"(a2), "r"(a3), "r"(b0), "r"(b1));
}

__device__ __forceinline__ void mma_f16(float c[4],
    uint32_t a0, uint32_t a1, uint32_t a2, uint32_t a3,
    uint32_t b0, uint32_t b1)
{
    asm volatile(
        "mma.sync.aligned.m16n8k16.row.col.f32.f16.f16.f32 "
        "{%0,%1,%2,%3},{%4,%5,%6,%7},{%8,%9},{%0,%1,%2,%3};"
        : "+f"(c[0]), "+f"(c[1]), "+f"(c[2]), "+f"(c[3])
        : "r"(a0), "r"(a1), "r"(a2), "r"(a3), "r"(b0), "r"(b1));
}

__device__ __forceinline__ void ldsm_x4(uint32_t& r0, uint32_t& r1,
                                        uint32_t& r2, uint32_t& r3, uint32_t addr)
{
    asm volatile("ldmatrix.sync.aligned.m8n8.x4.shared.b16 {%0,%1,%2,%3}, [%4];"
        : "=r"(r0), "=r"(r1), "=r"(r2), "=r"(r3) : "r"(addr));
}

__device__ __forceinline__ void ldsm_x4_t(uint32_t& r0, uint32_t& r1,
                                          uint32_t& r2, uint32_t& r3, uint32_t addr)
{
    asm volatile("ldmatrix.sync.aligned.m8n8.x4.trans.shared.b16 {%0,%1,%2,%3}, [%4];"
        : "=r"(r0), "=r"(r1), "=r"(r2), "=r"(r3) : "r"(addr));
}

__device__ __forceinline__ void cpa16(uint32_t dst, const void* src) {
    asm volatile("cp.async.cg.shared.global [%0], [%1], 16;" :: "r"(dst), "l"(src));
}
__device__ __forceinline__ void cp_commit() {
    asm volatile("cp.async.commit_group;");
}
template<int N> __device__ __forceinline__ void cp_wait() {
    asm volatile("cp.async.wait_group %0;" :: "n"(N));
}

// fp16 hi/lo split pack of a float pair
__device__ __forceinline__ void pack_hilo_h(float x, float y, uint32_t& hi, uint32_t& lo) {
    __half2 h = __floats2half2_rn(x, y);
    float2 f = __half22float2(h);
    __half2 l = __floats2half2_rn(x - f.x, y - f.y);
    hi = *reinterpret_cast<uint32_t*>(&h);
    lo = *reinterpret_cast<uint32_t*>(&l);
}
// bf16 hi/lo split pack
__device__ __forceinline__ void pack_hilo_b(float x, float y, uint32_t& hi, uint32_t& lo) {
    __nv_bfloat162 h = __floats2bfloat162_rn(x, y);
    float2 f = __bfloat1622float2(h);
    __nv_bfloat162 l = __floats2bfloat162_rn(x - f.x, y - f.y);
    hi = *reinterpret_cast<uint32_t*>(&h);
    lo = *reinterpret_cast<uint32_t*>(&l);
}

// ---------------------------------------------------------------------------
// Split fp32 tensors -> bf16 hi/lo planes. One launch covers inputs + weights.
// Blocks [0, 3*2048): inputs (Q,K,V); blocks [6144, 6144+4*256): weights.
// ---------------------------------------------------------------------------
#define IN_BLKS (NELE/1024)      // 2048 per tensor
#define W_BLKS  (DD/1024)        // 256 per tensor

__global__ __launch_bounds__(256) void split_all(
    const float* __restrict__ Q, const float* __restrict__ K, const float* __restrict__ V,
    const float* __restrict__ Wq, const float* __restrict__ Wk,
    const float* __restrict__ Wv, const float* __restrict__ Wo,
    __nv_bfloat16* __restrict__ inh, __nv_bfloat16* __restrict__ inl,
    __nv_bfloat16* __restrict__ wh,  __nv_bfloat16* __restrict__ wl)
{
    const int bx = blockIdx.x;
    const float* s;
    __nv_bfloat16 *h, *l;
    size_t off;
    if (bx < 3 * IN_BLKS) {
        int ten = bx / IN_BLKS, rel = bx % IN_BLKS;
        s = (ten == 0) ? Q : (ten == 1) ? K : V;
        off = (size_t)ten * NELE + (size_t)rel * 1024;
        s += (size_t)rel * 1024;
        h = inh; l = inl;
    } else {
        int id = bx - 3 * IN_BLKS;
        int ten = id / W_BLKS, rel = id % W_BLKS;
        s = (ten == 0) ? Wq : (ten == 1) ? Wk : (ten == 2) ? Wv : Wo;
        off = (size_t)ten * DD + (size_t)rel * 1024;
        s += (size_t)rel * 1024;
        h = wh; l = wl;
    }
    const size_t si = (size_t)threadIdx.x * 4;
    float4 v = *(const float4*)&s[si];
    uint32_t h01, l01, h23, l23;
    pack_hilo_b(v.x, v.y, h01, l01);
    pack_hilo_b(v.z, v.w, h23, l23);
    *(uint2*)&h[off + si] = make_uint2(h01, h23);
    *(uint2*)&l[off + si] = make_uint2(l01, l23);
}

// ---------------------------------------------------------------------------
// GEMM on pre-split bf16 hi/lo planes. blockIdx.z: 0..2 = GEMM problems,
// 3..6 = bias+mask CTAs (512 total), co-scheduled so the MUFU-bound bias work
// overlaps the tensor-bound GEMM work inside one launch.
// ---------------------------------------------------------------------------
#define AKP 40
#define BNP 136
#define AS (128*AKP)
#define BS (32*BNP)
#define GSMEM ((4*AS + 4*BS) * 2)   // bytes

__global__ __launch_bounds__(256, 2) void gemm_planes(
    const __nv_bfloat16* __restrict__ Ah_, const __nv_bfloat16* __restrict__ Al_,
    const __nv_bfloat16* __restrict__ Wh_, const __nv_bfloat16* __restrict__ Wl_,
    size_t aStride, size_t wStride,
    const float* __restrict__ b0v, const float* __restrict__ b1v, const float* __restrict__ b2v,
    float* __restrict__ C0,
    __half* __restrict__ H0, __half* __restrict__ L0,
    __half* __restrict__ H1, __half* __restrict__ L1,
    __half* __restrict__ H2, __half* __restrict__ L2,
    int M, int N, int K, float scale0, int fp16_out,
    const float* __restrict__ tmat, const float* __restrict__ dmat,
    const int*   __restrict__ mask,
    const float* __restrict__ tm_w, const float* __restrict__ tm_b,
    const float* __restrict__ dm_w, const float* __restrict__ dm_b,
    const float* __restrict__ td_w, const float* __restrict__ td_b)
{
    extern __shared__ __nv_bfloat16 gsm[];

    const int t = threadIdx.x;

    // =================== bias + mask CTAs (z >= 3) ===================
    if (blockIdx.z >= 3) {
        const int cta = (blockIdx.z - 3) * 128 + blockIdx.y * 4 + blockIdx.x; // 0..511
        const float tdb = td_b[0] * LOG2E;
        const float E = 2.718281828459045f;
        const int bz = g_bzero;
        const float Ct = g_Ct, Cd = g_Cd;

        float* sp = (float*)gsm;   // [5][64] for the fallback path
        if (!bz) {
            if (t < 64) {
                sp[0*64 + t] = tm_w[t];
                sp[1*64 + t] = tm_b[t];
                sp[2*64 + t] = dm_w[t];
                sp[3*64 + t] = dm_b[t];
                sp[4*64 + t] = td_w[t] * 0.5f * LOG2E;
            }
            __syncthreads();
        }

        #pragma unroll 2
        for (int i = 0; i < 8; i++) {
            const size_t base = (((size_t)cta * 8 + i) * 256 + t) * 4;
            float4 u  = *(const float4*)(tmat + base);
            float4 w4 = *(const float4*)(dmat + base);
            int4   mk = *(const int4*)(mask + base);

            float tv[4] = { 1.f / __logf(E + u.x), 1.f / __logf(E + u.y),
                            1.f / __logf(E + u.z), 1.f / __logf(E + u.w) };
            float dv[4] = { 1.f / __logf(E + w4.x), 1.f / __logf(E + w4.y),
                            1.f / __logf(E + w4.z), 1.f / __logf(E + w4.w) };
            float acc[4];
            if (bz) {
                #pragma unroll
                for (int e = 0; e < 4; e++)
                    acc[e] = fmaf(tv[e], Ct, fmaf(dv[e], Cd, tdb));
            } else {
                #pragma unroll
                for (int e = 0; e < 4; e++) acc[e] = tdb;
                #pragma unroll 8
                for (int m = 0; m < 64; m++) {
                    const float tw = sp[0*64 + m], tb = sp[1*64 + m];
                    const float dw = sp[2*64 + m], db = sp[3*64 + m];
                    const float ww = sp[4*64 + m];
                    #pragma unroll
                    for (int e = 0; e < 4; e++) {
                        float rt = fmaxf(tv[e] * tw + tb, 0.f);
                        float rd = fmaxf(dv[e] * dw + db, 0.f);
                        acc[e] += ww * (rt + rd);
                    }
                }
            }
            float4 o;
            o.x = (mk.x == 1) ? -1.5e9f : acc[0];
            o.y = (mk.y == 1) ? -1.5e9f : acc[1];
            o.z = (mk.z == 1) ? -1.5e9f : acc[2];
            o.w = (mk.w == 1) ? -1.5e9f : acc[3];
            *(float4*)(g_bias + base) = o;
        }
        return;
    }

    // =================== GEMM CTAs (z < 3) ===================
    __nv_bfloat16* Ahs = gsm;                 // [2][AS]
    __nv_bfloat16* Als = gsm + 2 * AS;        // [2][AS]
    __nv_bfloat16* Bhs = gsm + 4 * AS;        // [2][BS]
    __nv_bfloat16* Bls = gsm + 4 * AS + 2 * BS;

    const int z = blockIdx.z;
    const __nv_bfloat16* Ah = Ah_ + (size_t)z * aStride;
    const __nv_bfloat16* Al = Al_ + (size_t)z * aStride;
    const __nv_bfloat16* Wh = Wh_ + (size_t)z * wStride;
    const __nv_bfloat16* Wl = Wl_ + (size_t)z * wStride;
    const float* bias = (z == 0) ? b0v : (z == 1) ? b1v : b2v;
    __half* Ho = (z == 0) ? H0 : (z == 1) ? H1 : H2;
    __half* Lo = (z == 0) ? L0 : (z == 1) ? L1 : L2;
    const float osc = (z == 0) ? scale0 : 1.f;
    const bool  wlo = (z != 2);   // V lo-plane never read

    const int lane = t & 31, wid = t >> 5;
    const int warp_m = wid & 3, warp_n = wid >> 2;
    const int m_w = warp_m * 32, n_w = warp_n * 64;
    const int bm = blockIdx.y * 128, bn = blockIdx.x * 128;
    const int gid = lane >> 2, tig = lane & 3;
    const int m_idx = lane >> 3, rin = lane & 7;

    float acc[2][8][4];
    #pragma unroll
    for (int mt = 0; mt < 2; mt++)
        #pragma unroll
        for (int nt = 0; nt < 8; nt++)
            #pragma unroll
            for (int e = 0; e < 4; e++) acc[mt][nt][e] = 0.f;

    const int c0 = t, c1 = t + 256;

    auto issue = [&](int st, int k0) {
        #pragma unroll
        for (int r = 0; r < 2; r++) {
            int c = (r == 0) ? c0 : c1;
            int arow = c >> 2, ak = (c & 3) * 8;
            size_t ga = (size_t)(bm + arow) * K + k0 + ak;
            cpa16((uint32_t)__cvta_generic_to_shared(&Ahs[st * AS + arow * AKP + ak]), &Ah[ga]);
            cpa16((uint32_t)__cvta_generic_to_shared(&Als[st * AS + arow * AKP + ak]), &Al[ga]);
            int krow = c >> 4, nc = (c & 15) * 8;
            size_t gb = (size_t)(k0 + krow) * N + bn + nc;
            cpa16((uint32_t)__cvta_generic_to_shared(&Bhs[st * BS + krow * BNP + nc]), &Wh[gb]);
            cpa16((uint32_t)__cvta_generic_to_shared(&Bls[st * BS + krow * BNP + nc]), &Wl[gb]);
        }
    };

    issue(0, 0);
    cp_commit();

    const int NIT = K / 32;
    for (int it = 0; it < NIT; it++) {
        const int st = it & 1;
        if (it + 1 < NIT) {
            issue(st ^ 1, (it + 1) * 32);
            cp_commit();
            cp_wait<1>();
        } else {
            cp_wait<0>();
        }
        __syncthreads();

        #pragma unroll
        for (int kb = 0; kb < 32; kb += 16) {
            uint32_t af[2][2][4];
            #pragma unroll
            for (int mt = 0; mt < 2; mt++) {
                const int arow = m_w + mt * 16 + (lane & 15);
                const int acol = kb + ((lane >> 4) << 3);
                ldsm_x4(af[mt][0][0], af[mt][0][1], af[mt][0][2], af[mt][0][3],
                        (uint32_t)__cvta_generic_to_shared(&Ahs[st * AS + arow * AKP + acol]));
                ldsm_x4(af[mt][1][0], af[mt][1][1], af[mt][1][2], af[mt][1][3],
                        (uint32_t)__cvta_generic_to_shared(&Als[st * AS + arow * AKP + acol]));
            }
            #pragma unroll
            for (int p = 0; p < 4; p++) {
                const int brow = kb + ((m_idx & 1) << 3) + rin;
                const int bcol = n_w + p * 16 + ((m_idx >> 1) << 3);
                uint32_t bh0, bh1, bh2, bh3, bl0, bl1, bl2, bl3;
                ldsm_x4_t(bh0, bh1, bh2, bh3,
                    (uint32_t)__cvta_generic_to_shared(&Bhs[st * BS + brow * BNP + bcol]));
                ldsm_x4_t(bl0, bl1, bl2, bl3,
                    (uint32_t)__cvta_generic_to_shared(&Bls[st * BS + brow * BNP + bcol]));
                #pragma unroll
                for (int mt = 0; mt < 2; mt++) {
                    mma_bf16(acc[mt][2*p], af[mt][0][0], af[mt][0][1],
                             af[mt][0][2], af[mt][0][3], bh0, bh1);
                    mma_bf16(acc[mt][2*p], af[mt][1][0], af[mt][1][1],
                             af[mt][1][2], af[mt][1][3], bh0, bh1);
                    mma_bf16(acc[mt][2*p], af[mt][0][0], af[mt][0][1],
                             af[mt][0][2], af[mt][0][3], bl0, bl1);
                    mma_bf16(acc[mt][2*p+1], af[mt][0][0], af[mt][0][1],
                             af[mt][0][2], af[mt][0][3], bh2, bh3);
                    mma_bf16(acc[mt][2*p+1], af[mt][1][0], af[mt][1][1],
                             af[mt][1][2], af[mt][1][3], bh2, bh3);
                    mma_bf16(acc[mt][2*p+1], af[mt][0][0], af[mt][0][1],
                             af[mt][0][2], af[mt][0][3], bl2, bl3);
                }
            }
        }
        __syncthreads();
    }

    // ---- epilogue
    #pragma unroll
    for (int mt = 0; mt < 2; mt++) {
        const int row0 = bm + m_w + mt * 16 + gid;
        #pragma unroll
        for (int nt = 0; nt < 8; nt++) {
            const int col = bn + n_w + nt * 8 + tig * 2;
            float2 bb = *(const float2*)&bias[col];
            float v0 = (acc[mt][nt][0] + bb.x) * osc;
            float v1 = (acc[mt][nt][1] + bb.y) * osc;
            float v2 = (acc[mt][nt][2] + bb.x) * osc;
            float v3 = (acc[mt][nt][3] + bb.y) * osc;
            if (fp16_out) {
                uint32_t h01, l01, h23, l23;
                pack_hilo_h(v0, v1, h01, l01);
                pack_hilo_h(v2, v3, h23, l23);
                *(uint32_t*)&Ho[(size_t)row0 * N + col]       = h01;
                *(uint32_t*)&Ho[(size_t)(row0 + 8) * N + col] = h23;
                if (wlo) {
                    *(uint32_t*)&Lo[(size_t)row0 * N + col]       = l01;
                    *(uint32_t*)&Lo[(size_t)(row0 + 8) * N + col] = l23;
                }
            } else {
                *(float2*)&C0[(size_t)row0 * N + col]       = make_float2(v0, v1);
                *(float2*)&C0[(size_t)(row0 + 8) * N + col] = make_float2(v2, v3);
            }
        }
    }
}

// ---------------------------------------------------------------------------
// Prep: detect all-zero biases; precompute collapsed coefficients (log2 domain)
// ---------------------------------------------------------------------------
__global__ void prep_kernel(const float* __restrict__ tm_w, const float* __restrict__ tm_b,
                            const float* __restrict__ dm_w, const float* __restrict__ dm_b,
                            const float* __restrict__ td_w)
{
    const int l = threadIdx.x;   // 32 threads
    float ct = 0.f, cd = 0.f;
    bool z = true;
    #pragma unroll
    for (int m = l; m < 64; m += 32) {
        z = z && (tm_b[m] == 0.f) && (dm_b[m] == 0.f);
        ct += (0.5f * LOG2E) * td_w[m] * fmaxf(tm_w[m], 0.f);
        cd += (0.5f * LOG2E) * td_w[m] * fmaxf(dm_w[m], 0.f);
    }
    unsigned bz = __ballot_sync(0xffffffffu, z);
    #pragma unroll
    for (int o = 16; o; o >>= 1) {
        ct += __shfl_xor_sync(0xffffffffu, ct, o);
        cd += __shfl_xor_sync(0xffffffffu, cd, o);
    }
    if (l == 0) { g_Ct = ct; g_Cd = cd; g_bzero = (bz == 0xffffffffu); }
}

// ---------------------------------------------------------------------------
// Flash attention, fp16 TC, log2-domain softmax, smem-staged bias (unchanged).
// ---------------------------------------------------------------------------
#define PS 72
#define PE (64*PS)
#define BSS 68                  // bias smem row stride (floats)
#define SMEM_ATTN (8*PE*2)

__global__ __launch_bounds__(128, 3) void attn_f16()
{
    extern __shared__ __half sm[];
    float* biasS = (float*)sm;   // overlays Q planes 0,1 after prologue

    const int qt = blockIdx.x, h = blockIdx.y, b = blockIdx.z;
    const int t = threadIdx.x;
    const int w = t >> 5, lane = t & 31;
    const int gid = lane >> 2, tig = lane & 3;
    const int q0 = qt * 64, hoff = h * DK_;
    const int tr = w * 16 + gid;
    const int m_idx = lane >> 3, rin = lane & 7;

    #pragma unroll
    for (int i = 0; i < 4; i++) {
        int c = t + i * 128;
        int row = c >> 3, col = (c & 7) * 8;
        size_t gq = (size_t)(b * S_ + q0 + row) * D_ + hoff + col;
        size_t gk = (size_t)(b * S_ + row) * D_ + hoff + col;
        uint32_t so = row * PS + col;
        cpa16((uint32_t)__cvta_generic_to_shared(&sm[0*PE + so]), &g_qh[gq]);
        cpa16((uint32_t)__cvta_generic_to_shared(&sm[1*PE + so]), &g_ql[gq]);
        cpa16((uint32_t)__cvta_generic_to_shared(&sm[2*PE + so]), &g_kh[gk]);
        cpa16((uint32_t)__cvta_generic_to_shared(&sm[3*PE + so]), &g_kl[gk]);
        cpa16((uint32_t)__cvta_generic_to_shared(&sm[4*PE + so]), &g_vh[gk]);
    }
    cp_commit();
    cp_wait<0>();
    __syncthreads();

    uint32_t qf[4][2][4];
    #pragma unroll
    for (int d8 = 0; d8 < 4; d8++)
        #pragma unroll
        for (int p = 0; p < 2; p++) {
            uint32_t a = (uint32_t)__cvta_generic_to_shared(
                &sm[p*PE + (w * 16 + (lane & 15)) * PS + d8 * 16 + ((lane >> 4) << 3)]);
            ldsm_x4(qf[d8][p][0], qf[d8][p][1], qf[d8][p][2], qf[d8][p][3], a);
        }
    __syncthreads();   // Q planes now dead -> become the bias buffer

    float m0 = -1e30f, m1 = -1e30f, l0 = 0.f, l1 = 0.f;
    float oacc[8][4];
    #pragma unroll
    for (int nt = 0; nt < 8; nt++)
        #pragma unroll
        for (int e = 0; e < 4; e++) oacc[nt][e] = 0.f;

    for (int kt = 0; kt < 16; kt++) {
        const int buf = kt & 1;

        #pragma unroll
        for (int i = 0; i < 8; i++) {
            int idx = t + i * 128;
            int row = idx >> 4, c4 = (idx & 15) << 2;
            cpa16((uint32_t)__cvta_generic_to_shared(&biasS[row * BSS + c4]),
                  &g_bias[((size_t)(b * S_ + q0 + row)) * S_ + kt * 64 + c4]);
        }
        cp_commit();

        if (kt < 15) {
            const int k1 = (kt + 1) * 64;
            const int KHn = (2 + 3 * (buf ^ 1)) * PE;
            #pragma unroll
            for (int i = 0; i < 4; i++) {
                int c = t + i * 128;
                int row = c >> 3, col = (c & 7) * 8;
                size_t g = (size_t)(b * S_ + k1 + row) * D_ + hoff + col;
                uint32_t so = row * PS + col;
                cpa16((uint32_t)__cvta_generic_to_shared(&sm[KHn + so]),          &g_kh[g]);
                cpa16((uint32_t)__cvta_generic_to_shared(&sm[KHn + PE + so]),     &g_kl[g]);
                cpa16((uint32_t)__cvta_generic_to_shared(&sm[KHn + 2 * PE + so]), &g_vh[g]);
            }
            cp_commit();
            cp_wait<2>();
        } else {
            cp_wait<1>();
        }
        __syncthreads();

        const int KH = (2 + 3 * buf) * PE;

        float sacc[8][4];
        #pragma unroll
        for (int nt = 0; nt < 8; nt++)
            #pragma unroll
            for (int e = 0; e < 4; e++) sacc[nt][e] = 0.f;

        #pragma unroll
        for (int d8 = 0; d8 < 4; d8++) {
            #pragma unroll
            for (int p = 0; p < 4; p++) {
                uint32_t boff = (p * 16 + ((m_idx & 1) << 3) + rin) * PS
                              + d8 * 16 + ((m_idx >> 1) << 3);
                uint32_t kh0, kh1, kh2, kh3, kl0, kl1, kl2, kl3;
                ldsm_x4(kh0, kh1, kh2, kh3,
                        (uint32_t)__cvta_generic_to_shared(&sm[KH + boff]));
                ldsm_x4(kl0, kl1, kl2, kl3,
                        (uint32_t)__cvta_generic_to_shared(&sm[KH + PE + boff]));
                mma_f16(sacc[2*p],   qf[d8][0][0], qf[d8][0][1], qf[d8][0][2], qf[d8][0][3], kh0, kh2);
                mma_f16(sacc[2*p],   qf[d8][1][0], qf[d8][1][1], qf[d8][1][2], qf[d8][1][3], kh0, kh2);
                mma_f16(sacc[2*p],   qf[d8][0][0], qf[d8][0][1], qf[d8][0][2], qf[d8][0][3], kl0, kl2);
                mma_f16(sacc[2*p+1], qf[d8][0][0], qf[d8][0][1], qf[d8][0][2], qf[d8][0][3], kh1, kh3);
                mma_f16(sacc[2*p+1], qf[d8][1][0], qf[d8][1][1], qf[d8][1][2], qf[d8][1][3], kh1, kh3);
                mma_f16(sacc[2*p+1], qf[d8][0][0], qf[d8][0][1], qf[d8][0][2], qf[d8][0][3], kl1, kl3);
            }
        }

        if (kt < 15) { cp_wait<1>(); } else { cp_wait<0>(); }
        __syncthreads();

        float mx0 = -1e30f, mx1 = -1e30f;
        #pragma unroll
        for (int nt = 0; nt < 8; nt++) {
            float2 ba = *(const float2*)&biasS[tr * BSS + nt * 8 + tig * 2];
            float2 bb = *(const float2*)&biasS[(tr + 8) * BSS + nt * 8 + tig * 2];
            sacc[nt][0] += ba.x;
            sacc[nt][1] += ba.y;
            sacc[nt][2] += bb.x;
            sacc[nt][3] += bb.y;
            mx0 = fmaxf(mx0, fmaxf(sacc[nt][0], sacc[nt][1]));
            mx1 = fmaxf(mx1, fmaxf(sacc[nt][2], sacc[nt][3]));
        }
        mx0 = fmaxf(mx0, __shfl_xor_sync(0xffffffffu, mx0, 1));
        mx0 = fmaxf(mx0, __shfl_xor_sync(0xffffffffu, mx0, 2));
        mx1 = fmaxf(mx1, __shfl_xor_sync(0xffffffffu, mx1, 1));
        mx1 = fmaxf(mx1, __shfl_xor_sync(0xffffffffu, mx1, 2));

        const float mn0 = fmaxf(m0, mx0), mn1 = fmaxf(m1, mx1);
        const float c0 = ex2f(m0 - mn0), c1 = ex2f(m1 - mn1);
        m0 = mn0; m1 = mn1;

        float rs0 = 0.f, rs1 = 0.f;
        #pragma unroll
        for (int nt = 0; nt < 8; nt++) {
            sacc[nt][0] = ex2f(sacc[nt][0] - mn0);
            sacc[nt][1] = ex2f(sacc[nt][1] - mn0);
            sacc[nt][2] = ex2f(sacc[nt][2] - mn1);
            sacc[nt][3] = ex2f(sacc[nt][3] - mn1);
            rs0 += sacc[nt][0] + sacc[nt][1];
            rs1 += sacc[nt][2] + sacc[nt][3];
        }
        rs0 += __shfl_xor_sync(0xffffffffu, rs0, 1);
        rs0 += __shfl_xor_sync(0xffffffffu, rs0, 2);
        rs1 += __shfl_xor_sync(0xffffffffu, rs1, 1);
        rs1 += __shfl_xor_sync(0xffffffffu, rs1, 2);

        l0 = l0 * c0 + rs0;
        l1 = l1 * c1 + rs1;
        #pragma unroll
        for (int nt = 0; nt < 8; nt++) {
            oacc[nt][0] *= c0; oacc[nt][1] *= c0;
            oacc[nt][2] *= c1; oacc[nt][3] *= c1;
        }

        uint32_t pa[4][4];
        #pragma unroll
        for (int j8 = 0; j8 < 4; j8++) {
            const float* sA = sacc[2 * j8];
            const float* sB = sacc[2 * j8 + 1];
            __half2 hh;
            hh = __floats2half2_rn(sA[0], sA[1]); pa[j8][0] = *(uint32_t*)&hh;
            hh = __floats2half2_rn(sA[2], sA[3]); pa[j8][1] = *(uint32_t*)&hh;
            hh = __floats2half2_rn(sB[0], sB[1]); pa[j8][2] = *(uint32_t*)&hh;
            hh = __floats2half2_rn(sB[2], sB[3]); pa[j8][3] = *(uint32_t*)&hh;
        }

        #pragma unroll
        for (int j8 = 0; j8 < 4; j8++) {
            #pragma unroll
            for (int p = 0; p < 4; p++) {
                uint32_t boff = (j8 * 16 + ((m_idx & 1) << 3) + rin) * PS
                              + p * 16 + ((m_idx >> 1) << 3);
                uint32_t vh0, vh1, vh2, vh3;
                ldsm_x4_t(vh0, vh1, vh2, vh3,
                          (uint32_t)__cvta_generic_to_shared(&sm[KH + 2 * PE + boff]));
                mma_f16(oacc[2*p],   pa[j8][0], pa[j8][1], pa[j8][2], pa[j8][3], vh0, vh1);
                mma_f16(oacc[2*p+1], pa[j8][0], pa[j8][1], pa[j8][2], pa[j8][3], vh2, vh3);
            }
        }
        __syncthreads();
    }

    const float inv0 = 1.f / l0, inv1 = 1.f / l1;
    const size_t o0 = (size_t)(b * S_ + q0 + tr) * D_ + hoff;
    const size_t o1 = o0 + (size_t)8 * D_;
    #pragma unroll
    for (int nt = 0; nt < 8; nt++) {
        const int coff = nt * 8 + tig * 2;
        uint32_t h01, l01, h23, l23;
        pack_hilo_b(oacc[nt][0] * inv0, oacc[nt][1] * inv0, h01, l01);
        pack_hilo_b(oacc[nt][2] * inv1, oacc[nt][3] * inv1, h23, l23);
        *(uint32_t*)&g_oh[o0 + coff] = h01;
        *(uint32_t*)&g_ol[o0 + coff] = l01;
        *(uint32_t*)&g_oh[o1 + coff] = h23;
        *(uint32_t*)&g_ol[o1 + coff] = l23;
    }
}

// ---------------------------------------------------------------------------
extern "C" void kernel_launch(void* const* d_in, const int* in_sizes, int n_in,
                              void* d_out, int out_size)
{
    const float* Q     = (const float*)d_in[0];
    const float* K     = (const float*)d_in[1];
    const float* V     = (const float*)d_in[2];
    const float* tmat  = (const float*)d_in[3];
    const float* dmat  = (const float*)d_in[4];
    const int*   mask  = (const int*)  d_in[5];
    const float* Wq    = (const float*)d_in[6];
    const float* bq    = (const float*)d_in[7];
    const float* Wk    = (const float*)d_in[8];
    const float* bk    = (const float*)d_in[9];
    const float* Wv    = (const float*)d_in[10];
    const float* bv    = (const float*)d_in[11];
    const float* Wo    = (const float*)d_in[12];
    const float* bo    = (const float*)d_in[13];
    const float* tm_w  = (const float*)d_in[14];
    const float* tm_b  = (const float*)d_in[15];
    const float* dm_w  = (const float*)d_in[16];
    const float* dm_b  = (const float*)d_in[17];
    const float* td_w  = (const float*)d_in[18];
    const float* td_b  = (const float*)d_in[19];
    float* out = (float*)d_out;

    __nv_bfloat16 *inh, *inl, *wh, *wl, *oh, *ol;
    cudaGetSymbolAddress((void**)&inh, g_in_h);
    cudaGetSymbolAddress((void**)&inl, g_in_l);
    cudaGetSymbolAddress((void**)&wh,  g_w_h);
    cudaGetSymbolAddress((void**)&wl,  g_w_l);
    cudaGetSymbolAddress((void**)&oh,  g_oh);
    cudaGetSymbolAddress((void**)&ol,  g_ol);
    __half *qh, *ql, *kh, *kl, *vh;
    cudaGetSymbolAddress((void**)&qh, g_qh);
    cudaGetSymbolAddress((void**)&ql, g_ql);
    cudaGetSymbolAddress((void**)&kh, g_kh);
    cudaGetSymbolAddress((void**)&kl, g_kl);
    cudaGetSymbolAddress((void**)&vh, g_vh);

    prep_kernel<<<1, 32>>>(tm_w, tm_b, dm_w, dm_b, td_w);

    // one launch: split inputs + weights to bf16 hi/lo planes
    split_all<<<3 * IN_BLKS + 4 * W_BLKS, 256>>>(
        Q, K, V, Wq, Wk, Wv, Wo, inh, inl, wh, wl);

    cudaFuncSetAttribute(gemm_planes,
                         cudaFuncAttributeMaxDynamicSharedMemorySize, GSMEM);

    // fused Q/K/V projections (z=0..2) + bias/mask CTAs (z=3..6) in ONE launch
    gemm_planes<<<dim3(D_ / 128, MTOT / 128, 7), 256, GSMEM>>>(
        inh, inl, wh, wl, (size_t)NELE, (size_t)DD,
        bq, bk, bv,
        out /*unused*/, qh, ql, kh, kl, vh, vh /*dummy*/,
        MTOT, D_, D_, 0.125f * LOG2E, 1,
        tmat, dmat, mask, tm_w, tm_b, dm_w, dm_b, td_w, td_b);

    cudaFuncSetAttribute(attn_f16,
                         cudaFuncAttributeMaxDynamicSharedMemorySize, SMEM_ATTN);
    attn_f16<<<dim3(S_ / 64, H_, B_), 128, SMEM_ATTN>>>();

    // output projection: bf16 planes in (attn output), fp32 out
    gemm_planes<<<dim3(D_ / 128, MTOT / 128, 1), 256, GSMEM>>>(
        oh, ol, wh + (size_t)3 * DD, wl + (size_t)3 * DD, 0, 0,
        bo, bo, bo,
        out, qh, ql, kh, kl, vh, vh,
        MTOT, D_, D_, 1.f, 0,
        tmat, dmat, mask, tm_w, tm_b, dm_w, dm_b, td_w, td_b);
}

// round 11
// speedup vs baseline: 1.5859x; 1.2263x over previous
#include <cuda_runtime.h>
#include <cuda_bf16.h>
#include <cuda_fp16.h>
#include <cstdint>

#define B_  4
#define S_  1024
#define D_  512
#define H_  8
#define DK_ 64
#define MTOT (B_*S_)          // 4096 rows
#define NELE (B_*S_*D_)       // 2,097,152
#define DD   (D_*D_)
#define LOG2E 1.4426950408889634f

// Scratch (static device globals — allowed; no cudaMalloc anywhere)
__device__ __nv_bfloat16 g_in_h[(size_t)3*NELE], g_in_l[(size_t)3*NELE]; // Q,K,V inputs split
__device__ __nv_bfloat16 g_w_h[4*DD], g_w_l[4*DD];                        // Wq,Wk,Wv,Wo split
__device__ __nv_bfloat16 g_oh[NELE], g_ol[NELE];                          // attn out split
__device__ __half g_qh[NELE];   // projected Q (pre-scaled by log2e/8), fp16
__device__ __half g_kh[NELE];   // projected K, fp16
__device__ __half g_vh[NELE];   // projected V, fp16
__device__ float g_bias[(size_t)B_*S_*S_];  // bias*log2e, mask folded as -1.5e9
__device__ float g_Ct, g_Cd;
__device__ int   g_bzero;

// ---------------------------------------------------------------------------
// helpers
// ---------------------------------------------------------------------------
__device__ __forceinline__ float ex2f(float x) {
    float r; asm("ex2.approx.f32 %0, %1;" : "=f"(r) : "f"(x)); return r;
}

__device__ __forceinline__ void mma_bf16(float c[4],
    uint32_t a0, uint32_t a1, uint32_t a2, uint32_t a3,
    uint32_t b0, uint32_t b1)
{
    asm volatile(
        "mma.sync.aligned.m16n8k16.row.col.f32.bf16.bf16.f32 "
        "{%0,%1,%2,%3},{%4,%5,%6,%7},{%8,%9},{%0,%1,%2,%3};"
        : "+f"(c[0]), "+f"(c[1]), "+f"(c[2]), "+f"(c[3])
        : "r"(a0), "r"(a1), "r"(a2), "r"(a3), "r"(b0), "r"(b1));
}

__device__ __forceinline__ void mma_f16(float c[4],
    uint32_t a0, uint32_t a1, uint32_t a2, uint32_t a3,
    uint32_t b0, uint32_t b1)
{
    asm volatile(
        "mma.sync.aligned.m16n8k16.row.col.f32.f16.f16.f32 "
        "{%0,%1,%2,%3},{%4,%5,%6,%7},{%8,%9},{%0,%1,%2,%3};"
        : "+f"(c[0]), "+f"(c[1]), "+f"(c[2]), "+f"(c[3])
        : "r"(a0), "r"(a1), "r"(a2), "r"(a3), "r"(b0), "r"(b1));
}

__device__ __forceinline__ void ldsm_x4(uint32_t& r0, uint32_t& r1,
                                        uint32_t& r2, uint32_t& r3, uint32_t addr)
{
    asm volatile("ldmatrix.sync.aligned.m8n8.x4.shared.b16 {%0,%1,%2,%3}, [%4];"
        : "=r"(r0), "=r"(r1), "=r"(r2), "=r"(r3) : "r"(addr));
}

__device__ __forceinline__ void ldsm_x4_t(uint32_t& r0, uint32_t& r1,
                                          uint32_t& r2, uint32_t& r3, uint32_t addr)
{
    asm volatile("ldmatrix.sync.aligned.m8n8.x4.trans.shared.b16 {%0,%1,%2,%3}, [%4];"
        : "=r"(r0), "=r"(r1), "=r"(r2), "=r"(r3) : "r"(addr));
}

__device__ __forceinline__ void cpa16(uint32_t dst, const void* src) {
    asm volatile("cp.async.cg.shared.global [%0], [%1], 16;" :: "r"(dst), "l"(src));
}
__device__ __forceinline__ void cp_commit() {
    asm volatile("cp.async.commit_group;");
}
template<int N> __device__ __forceinline__ void cp_wait() {
    asm volatile("cp.async.wait_group %0;" :: "n"(N));
}

// bf16 hi/lo split pack
__device__ __forceinline__ void pack_hilo_b(float x, float y, uint32_t& hi, uint32_t& lo) {
    __nv_bfloat162 h = __floats2bfloat162_rn(x, y);
    float2 f = __bfloat1622float2(h);
    __nv_bfloat162 l = __floats2bfloat162_rn(x - f.x, y - f.y);
    hi = *reinterpret_cast<uint32_t*>(&h);
    lo = *reinterpret_cast<uint32_t*>(&l);
}

// ---------------------------------------------------------------------------
// Split fp32 tensors -> bf16 hi/lo planes. One launch covers inputs + weights.
// ---------------------------------------------------------------------------
#define IN_BLKS (NELE/1024)      // 2048 per tensor
#define W_BLKS  (DD/1024)        // 256 per tensor

__global__ __launch_bounds__(256) void split_all(
    const float* __restrict__ Q, const float* __restrict__ K, const float* __restrict__ V,
    const float* __restrict__ Wq, const float* __restrict__ Wk,
    const float* __restrict__ Wv, const float* __restrict__ Wo,
    __nv_bfloat16* __restrict__ inh, __nv_bfloat16* __restrict__ inl,
    __nv_bfloat16* __restrict__ wh,  __nv_bfloat16* __restrict__ wl)
{
    const int bx = blockIdx.x;
    const float* s;
    __nv_bfloat16 *h, *l;
    size_t off;
    if (bx < 3 * IN_BLKS) {
        int ten = bx / IN_BLKS, rel = bx % IN_BLKS;
        s = (ten == 0) ? Q : (ten == 1) ? K : V;
        off = (size_t)ten * NELE + (size_t)rel * 1024;
        s += (size_t)rel * 1024;
        h = inh; l = inl;
    } else {
        int id = bx - 3 * IN_BLKS;
        int ten = id / W_BLKS, rel = id % W_BLKS;
        s = (ten == 0) ? Wq : (ten == 1) ? Wk : (ten == 2) ? Wv : Wo;
        off = (size_t)ten * DD + (size_t)rel * 1024;
        s += (size_t)rel * 1024;
        h = wh; l = wl;
    }
    const size_t si = (size_t)threadIdx.x * 4;
    float4 v = *(const float4*)&s[si];
    uint32_t h01, l01, h23, l23;
    pack_hilo_b(v.x, v.y, h01, l01);
    pack_hilo_b(v.z, v.w, h23, l23);
    *(uint2*)&h[off + si] = make_uint2(h01, h23);
    *(uint2*)&l[off + si] = make_uint2(l01, l23);
}

// ---------------------------------------------------------------------------
// GEMM on pre-split bf16 hi/lo planes. blockIdx.z: 0..2 = GEMM problems,
// 3..6 = bias+mask CTAs (512 total), co-scheduled with the GEMM work.
// fp16_out: write single fp16 plane (attention operands are now pure fp16).
// ---------------------------------------------------------------------------
#define AKP 40
#define BNP 136
#define AS (128*AKP)
#define BS (32*BNP)
#define GSMEM ((4*AS + 4*BS) * 2)   // bytes

__global__ __launch_bounds__(256, 2) void gemm_planes(
    const __nv_bfloat16* __restrict__ Ah_, const __nv_bfloat16* __restrict__ Al_,
    const __nv_bfloat16* __restrict__ Wh_, const __nv_bfloat16* __restrict__ Wl_,
    size_t aStride, size_t wStride,
    const float* __restrict__ b0v, const float* __restrict__ b1v, const float* __restrict__ b2v,
    float* __restrict__ C0,
    __half* __restrict__ H0, __half* __restrict__ H1, __half* __restrict__ H2,
    int M, int N, int K, float scale0, int fp16_out,
    const float* __restrict__ tmat, const float* __restrict__ dmat,
    const int*   __restrict__ mask,
    const float* __restrict__ tm_w, const float* __restrict__ tm_b,
    const float* __restrict__ dm_w, const float* __restrict__ dm_b,
    const float* __restrict__ td_w, const float* __restrict__ td_b)
{
    extern __shared__ __nv_bfloat16 gsm[];

    const int t = threadIdx.x;

    // =================== bias + mask CTAs (z >= 3) ===================
    if (blockIdx.z >= 3) {
        const int cta = (blockIdx.z - 3) * 128 + blockIdx.y * 4 + blockIdx.x; // 0..511
        const float tdb = td_b[0] * LOG2E;
        const float E = 2.718281828459045f;
        const int bz = g_bzero;
        const float Ct = g_Ct, Cd = g_Cd;

        float* sp = (float*)gsm;   // [5][64] for the fallback path
        if (!bz) {
            if (t < 64) {
                sp[0*64 + t] = tm_w[t];
                sp[1*64 + t] = tm_b[t];
                sp[2*64 + t] = dm_w[t];
                sp[3*64 + t] = dm_b[t];
                sp[4*64 + t] = td_w[t] * 0.5f * LOG2E;
            }
            __syncthreads();
        }

        #pragma unroll 2
        for (int i = 0; i < 8; i++) {
            const size_t base = (((size_t)cta * 8 + i) * 256 + t) * 4;
            float4 u  = *(const float4*)(tmat + base);
            float4 w4 = *(const float4*)(dmat + base);
            int4   mk = *(const int4*)(mask + base);

            float tv[4] = { 1.f / __logf(E + u.x), 1.f / __logf(E + u.y),
                            1.f / __logf(E + u.z), 1.f / __logf(E + u.w) };
            float dv[4] = { 1.f / __logf(E + w4.x), 1.f / __logf(E + w4.y),
                            1.f / __logf(E + w4.z), 1.f / __logf(E + w4.w) };
            float acc[4];
            if (bz) {
                #pragma unroll
                for (int e = 0; e < 4; e++)
                    acc[e] = fmaf(tv[e], Ct, fmaf(dv[e], Cd, tdb));
            } else {
                #pragma unroll
                for (int e = 0; e < 4; e++) acc[e] = tdb;
                #pragma unroll 8
                for (int m = 0; m < 64; m++) {
                    const float tw = sp[0*64 + m], tb = sp[1*64 + m];
                    const float dw = sp[2*64 + m], db = sp[3*64 + m];
                    const float ww = sp[4*64 + m];
                    #pragma unroll
                    for (int e = 0; e < 4; e++) {
                        float rt = fmaxf(tv[e] * tw + tb, 0.f);
                        float rd = fmaxf(dv[e] * dw + db, 0.f);
                        acc[e] += ww * (rt + rd);
                    }
                }
            }
            float4 o;
            o.x = (mk.x == 1) ? -1.5e9f : acc[0];
            o.y = (mk.y == 1) ? -1.5e9f : acc[1];
            o.z = (mk.z == 1) ? -1.5e9f : acc[2];
            o.w = (mk.w == 1) ? -1.5e9f : acc[3];
            *(float4*)(g_bias + base) = o;
        }
        return;
    }

    // =================== GEMM CTAs (z < 3) ===================
    __nv_bfloat16* Ahs = gsm;                 // [2][AS]
    __nv_bfloat16* Als = gsm + 2 * AS;        // [2][AS]
    __nv_bfloat16* Bhs = gsm + 4 * AS;        // [2][BS]
    __nv_bfloat16* Bls = gsm + 4 * AS + 2 * BS;

    const int z = blockIdx.z;
    const __nv_bfloat16* Ah = Ah_ + (size_t)z * aStride;
    const __nv_bfloat16* Al = Al_ + (size_t)z * aStride;
    const __nv_bfloat16* Wh = Wh_ + (size_t)z * wStride;
    const __nv_bfloat16* Wl = Wl_ + (size_t)z * wStride;
    const float* bias = (z == 0) ? b0v : (z == 1) ? b1v : b2v;
    __half* Ho = (z == 0) ? H0 : (z == 1) ? H1 : H2;
    const float osc = (z == 0) ? scale0 : 1.f;

    const int lane = t & 31, wid = t >> 5;
    const int warp_m = wid & 3, warp_n = wid >> 2;
    const int m_w = warp_m * 32, n_w = warp_n * 64;
    const int bm = blockIdx.y * 128, bn = blockIdx.x * 128;
    const int gid = lane >> 2, tig = lane & 3;
    const int m_idx = lane >> 3, rin = lane & 7;

    float acc[2][8][4];
    #pragma unroll
    for (int mt = 0; mt < 2; mt++)
        #pragma unroll
        for (int nt = 0; nt < 8; nt++)
            #pragma unroll
            for (int e = 0; e < 4; e++) acc[mt][nt][e] = 0.f;

    const int c0 = t, c1 = t + 256;

    auto issue = [&](int st, int k0) {
        #pragma unroll
        for (int r = 0; r < 2; r++) {
            int c = (r == 0) ? c0 : c1;
            int arow = c >> 2, ak = (c & 3) * 8;
            size_t ga = (size_t)(bm + arow) * K + k0 + ak;
            cpa16((uint32_t)__cvta_generic_to_shared(&Ahs[st * AS + arow * AKP + ak]), &Ah[ga]);
            cpa16((uint32_t)__cvta_generic_to_shared(&Als[st * AS + arow * AKP + ak]), &Al[ga]);
            int krow = c >> 4, nc = (c & 15) * 8;
            size_t gb = (size_t)(k0 + krow) * N + bn + nc;
            cpa16((uint32_t)__cvta_generic_to_shared(&Bhs[st * BS + krow * BNP + nc]), &Wh[gb]);
            cpa16((uint32_t)__cvta_generic_to_shared(&Bls[st * BS + krow * BNP + nc]), &Wl[gb]);
        }
    };

    issue(0, 0);
    cp_commit();

    const int NIT = K / 32;
    for (int it = 0; it < NIT; it++) {
        const int st = it & 1;
        if (it + 1 < NIT) {
            issue(st ^ 1, (it + 1) * 32);
            cp_commit();
            cp_wait<1>();
        } else {
            cp_wait<0>();
        }
        __syncthreads();

        #pragma unroll
        for (int kb = 0; kb < 32; kb += 16) {
            uint32_t af[2][2][4];
            #pragma unroll
            for (int mt = 0; mt < 2; mt++) {
                const int arow = m_w + mt * 16 + (lane & 15);
                const int acol = kb + ((lane >> 4) << 3);
                ldsm_x4(af[mt][0][0], af[mt][0][1], af[mt][0][2], af[mt][0][3],
                        (uint32_t)__cvta_generic_to_shared(&Ahs[st * AS + arow * AKP + acol]));
                ldsm_x4(af[mt][1][0], af[mt][1][1], af[mt][1][2], af[mt][1][3],
                        (uint32_t)__cvta_generic_to_shared(&Als[st * AS + arow * AKP + acol]));
            }
            #pragma unroll
            for (int p = 0; p < 4; p++) {
                const int brow = kb + ((m_idx & 1) << 3) + rin;
                const int bcol = n_w + p * 16 + ((m_idx >> 1) << 3);
                uint32_t bh0, bh1, bh2, bh3, bl0, bl1, bl2, bl3;
                ldsm_x4_t(bh0, bh1, bh2, bh3,
                    (uint32_t)__cvta_generic_to_shared(&Bhs[st * BS + brow * BNP + bcol]));
                ldsm_x4_t(bl0, bl1, bl2, bl3,
                    (uint32_t)__cvta_generic_to_shared(&Bls[st * BS + brow * BNP + bcol]));
                #pragma unroll
                for (int mt = 0; mt < 2; mt++) {
                    mma_bf16(acc[mt][2*p], af[mt][0][0], af[mt][0][1],
                             af[mt][0][2], af[mt][0][3], bh0, bh1);
                    mma_bf16(acc[mt][2*p], af[mt][1][0], af[mt][1][1],
                             af[mt][1][2], af[mt][1][3], bh0, bh1);
                    mma_bf16(acc[mt][2*p], af[mt][0][0], af[mt][0][1],
                             af[mt][0][2], af[mt][0][3], bl0, bl1);
                    mma_bf16(acc[mt][2*p+1], af[mt][0][0], af[mt][0][1],
                             af[mt][0][2], af[mt][0][3], bh2, bh3);
                    mma_bf16(acc[mt][2*p+1], af[mt][1][0], af[mt][1][1],
                             af[mt][1][2], af[mt][1][3], bh2, bh3);
                    mma_bf16(acc[mt][2*p+1], af[mt][0][0], af[mt][0][1],
                             af[mt][0][2], af[mt][0][3], bl2, bl3);
                }
            }
        }
        __syncthreads();
    }

    // ---- epilogue
    #pragma unroll
    for (int mt = 0; mt < 2; mt++) {
        const int row0 = bm + m_w + mt * 16 + gid;
        #pragma unroll
        for (int nt = 0; nt < 8; nt++) {
            const int col = bn + n_w + nt * 8 + tig * 2;
            float2 bb = *(const float2*)&bias[col];
            float v0 = (acc[mt][nt][0] + bb.x) * osc;
            float v1 = (acc[mt][nt][1] + bb.y) * osc;
            float v2 = (acc[mt][nt][2] + bb.x) * osc;
            float v3 = (acc[mt][nt][3] + bb.y) * osc;
            if (fp16_out) {
                __half2 h01 = __floats2half2_rn(v0, v1);
                __half2 h23 = __floats2half2_rn(v2, v3);
                *(__half2*)&Ho[(size_t)row0 * N + col]       = h01;
                *(__half2*)&Ho[(size_t)(row0 + 8) * N + col] = h23;
            } else {
                *(float2*)&C0[(size_t)row0 * N + col]       = make_float2(v0, v1);
                *(float2*)&C0[(size_t)(row0 + 8) * N + col] = make_float2(v2, v3);
            }
        }
    }
}

// ---------------------------------------------------------------------------
// Prep: detect all-zero biases; precompute collapsed coefficients (log2 domain)
// ---------------------------------------------------------------------------
__global__ void prep_kernel(const float* __restrict__ tm_w, const float* __restrict__ tm_b,
                            const float* __restrict__ dm_w, const float* __restrict__ dm_b,
                            const float* __restrict__ td_w)
{
    const int l = threadIdx.x;   // 32 threads
    float ct = 0.f, cd = 0.f;
    bool z = true;
    #pragma unroll
    for (int m = l; m < 64; m += 32) {
        z = z && (tm_b[m] == 0.f) && (dm_b[m] == 0.f);
        ct += (0.5f * LOG2E) * td_w[m] * fmaxf(tm_w[m], 0.f);
        cd += (0.5f * LOG2E) * td_w[m] * fmaxf(dm_w[m], 0.f);
    }
    unsigned bz = __ballot_sync(0xffffffffu, z);
    #pragma unroll
    for (int o = 16; o; o >>= 1) {
        ct += __shfl_xor_sync(0xffffffffu, ct, o);
        cd += __shfl_xor_sync(0xffffffffu, cd, o);
    }
    if (l == 0) { g_Ct = ct; g_Cd = cd; g_bzero = (bz == 0xffffffffu); }
}

// ---------------------------------------------------------------------------
// Flash attention, pure fp16 tensor cores (single-term QK^T and PV),
// log2-domain softmax, smem-staged bias. 5 effective planes -> 54 KB/CTA,
// 4 CTAs/SM. Q plane overlays the bias buffer (dead after fragment hoist).
// ---------------------------------------------------------------------------
#define PS 72
#define PE (64*PS)             // 4608 halves per plane
#define BSS 68                 // bias smem row stride (floats)
#define KV0 8704               // halves; bias buffer = 64*68 floats = 8704 halves
#define SMEM_ATTN ((KV0 + 4*PE)*2)   // 54272 bytes

__global__ __launch_bounds__(128, 4) void attn_f16()
{
    extern __shared__ __half sm[];
    float* biasS = (float*)sm;   // overlays Q plane after prologue

    const int qt = blockIdx.x, h = blockIdx.y, b = blockIdx.z;
    const int t = threadIdx.x;
    const int w = t >> 5, lane = t & 31;
    const int gid = lane >> 2, tig = lane & 3;
    const int q0 = qt * 64, hoff = h * DK_;
    const int tr = w * 16 + gid;
    const int m_idx = lane >> 3, rin = lane & 7;

    // ---- prologue: Q plane (offset 0) + K/V tile0 (buf0 at KV0, KV0+PE)
    #pragma unroll
    for (int i = 0; i < 4; i++) {
        int c = t + i * 128;
        int row = c >> 3, col = (c & 7) * 8;
        size_t gq = (size_t)(b * S_ + q0 + row) * D_ + hoff + col;
        size_t gk = (size_t)(b * S_ + row) * D_ + hoff + col;
        uint32_t so = row * PS + col;
        cpa16((uint32_t)__cvta_generic_to_shared(&sm[so]),            &g_qh[gq]);
        cpa16((uint32_t)__cvta_generic_to_shared(&sm[KV0 + so]),      &g_kh[gk]);
        cpa16((uint32_t)__cvta_generic_to_shared(&sm[KV0 + PE + so]), &g_vh[gk]);
    }
    cp_commit();
    cp_wait<0>();
    __syncthreads();

    // ---- Q fragments, loop-invariant
    uint32_t qf[4][4];
    #pragma unroll
    for (int d8 = 0; d8 < 4; d8++) {
        uint32_t a = (uint32_t)__cvta_generic_to_shared(
            &sm[(w * 16 + (lane & 15)) * PS + d8 * 16 + ((lane >> 4) << 3)]);
        ldsm_x4(qf[d8][0], qf[d8][1], qf[d8][2], qf[d8][3], a);
    }
    __syncthreads();   // Q plane now dead -> becomes the bias buffer

    float m0 = -1e30f, m1 = -1e30f, l0 = 0.f, l1 = 0.f;
    float oacc[8][4];
    #pragma unroll
    for (int nt = 0; nt < 8; nt++)
        #pragma unroll
        for (int e = 0; e < 4; e++) oacc[nt][e] = 0.f;

    for (int kt = 0; kt < 16; kt++) {
        const int buf = kt & 1;

        // ---- issue bias(kt) copy (group B_kt)
        #pragma unroll
        for (int i = 0; i < 8; i++) {
            int idx = t + i * 128;
            int row = idx >> 4, c4 = (idx & 15) << 2;
            cpa16((uint32_t)__cvta_generic_to_shared(&biasS[row * BSS + c4]),
                  &g_bias[((size_t)(b * S_ + q0 + row)) * S_ + kt * 64 + c4]);
        }
        cp_commit();

        // ---- issue KV(kt+1), wait KV(kt)
        if (kt < 15) {
            const int k1 = (kt + 1) * 64;
            const int KBn = KV0 + (buf ^ 1) * 2 * PE;
            #pragma unroll
            for (int i = 0; i < 4; i++) {
                int c = t + i * 128;
                int row = c >> 3, col = (c & 7) * 8;
                size_t g = (size_t)(b * S_ + k1 + row) * D_ + hoff + col;
                uint32_t so = row * PS + col;
                cpa16((uint32_t)__cvta_generic_to_shared(&sm[KBn + so]),      &g_kh[g]);
                cpa16((uint32_t)__cvta_generic_to_shared(&sm[KBn + PE + so]), &g_vh[g]);
            }
            cp_commit();
            cp_wait<2>();
        } else {
            cp_wait<1>();
        }
        __syncthreads();

        const int KB = KV0 + buf * 2 * PE;   // Kh plane; V = KB + PE

        // ---- scores S = Q @ K^T (log2-domain), single-term fp16
        float sacc[8][4];
        #pragma unroll
        for (int nt = 0; nt < 8; nt++)
            #pragma unroll
            for (int e = 0; e < 4; e++) sacc[nt][e] = 0.f;

        #pragma unroll
        for (int d8 = 0; d8 < 4; d8++) {
            #pragma unroll
            for (int p = 0; p < 4; p++) {
                uint32_t boff = (p * 16 + ((m_idx & 1) << 3) + rin) * PS
                              + d8 * 16 + ((m_idx >> 1) << 3);
                uint32_t kh0, kh1, kh2, kh3;
                ldsm_x4(kh0, kh1, kh2, kh3,
                        (uint32_t)__cvta_generic_to_shared(&sm[KB + boff]));
                mma_f16(sacc[2*p],   qf[d8][0], qf[d8][1], qf[d8][2], qf[d8][3], kh0, kh2);
                mma_f16(sacc[2*p+1], qf[d8][0], qf[d8][1], qf[d8][2], qf[d8][3], kh1, kh3);
            }
        }

        // ---- bias now resident in smem
        if (kt < 15) { cp_wait<1>(); } else { cp_wait<0>(); }
        __syncthreads();

        float mx0 = -1e30f, mx1 = -1e30f;
        #pragma unroll
        for (int nt = 0; nt < 8; nt++) {
            float2 ba = *(const float2*)&biasS[tr * BSS + nt * 8 + tig * 2];
            float2 bb = *(const float2*)&biasS[(tr + 8) * BSS + nt * 8 + tig * 2];
            sacc[nt][0] += ba.x;
            sacc[nt][1] += ba.y;
            sacc[nt][2] += bb.x;
            sacc[nt][3] += bb.y;
            mx0 = fmaxf(mx0, fmaxf(sacc[nt][0], sacc[nt][1]));
            mx1 = fmaxf(mx1, fmaxf(sacc[nt][2], sacc[nt][3]));
        }
        mx0 = fmaxf(mx0, __shfl_xor_sync(0xffffffffu, mx0, 1));
        mx0 = fmaxf(mx0, __shfl_xor_sync(0xffffffffu, mx0, 2));
        mx1 = fmaxf(mx1, __shfl_xor_sync(0xffffffffu, mx1, 1));
        mx1 = fmaxf(mx1, __shfl_xor_sync(0xffffffffu, mx1, 2));

        const float mn0 = fmaxf(m0, mx0), mn1 = fmaxf(m1, mx1);
        const float c0 = ex2f(m0 - mn0), c1 = ex2f(m1 - mn1);
        m0 = mn0; m1 = mn1;

        float rs0 = 0.f, rs1 = 0.f;
        #pragma unroll
        for (int nt = 0; nt < 8; nt++) {
            sacc[nt][0] = ex2f(sacc[nt][0] - mn0);
            sacc[nt][1] = ex2f(sacc[nt][1] - mn0);
            sacc[nt][2] = ex2f(sacc[nt][2] - mn1);
            sacc[nt][3] = ex2f(sacc[nt][3] - mn1);
            rs0 += sacc[nt][0] + sacc[nt][1];
            rs1 += sacc[nt][2] + sacc[nt][3];
        }
        rs0 += __shfl_xor_sync(0xffffffffu, rs0, 1);
        rs0 += __shfl_xor_sync(0xffffffffu, rs0, 2);
        rs1 += __shfl_xor_sync(0xffffffffu, rs1, 1);
        rs1 += __shfl_xor_sync(0xffffffffu, rs1, 2);

        l0 = l0 * c0 + rs0;
        l1 = l1 * c1 + rs1;
        #pragma unroll
        for (int nt = 0; nt < 8; nt++) {
            oacc[nt][0] *= c0; oacc[nt][1] *= c0;
            oacc[nt][2] *= c1; oacc[nt][3] *= c1;
        }

        // ---- pack P into fp16 A-fragments (registers only)
        uint32_t pa[4][4];
        #pragma unroll
        for (int j8 = 0; j8 < 4; j8++) {
            const float* sA = sacc[2 * j8];
            const float* sB = sacc[2 * j8 + 1];
            __half2 hh;
            hh = __floats2half2_rn(sA[0], sA[1]); pa[j8][0] = *(uint32_t*)&hh;
            hh = __floats2half2_rn(sA[2], sA[3]); pa[j8][1] = *(uint32_t*)&hh;
            hh = __floats2half2_rn(sB[0], sB[1]); pa[j8][2] = *(uint32_t*)&hh;
            hh = __floats2half2_rn(sB[2], sB[3]); pa[j8][3] = *(uint32_t*)&hh;
        }

        // ---- O += P @ V : single-term fp16, V via ldmatrix.x4.trans
        #pragma unroll
        for (int j8 = 0; j8 < 4; j8++) {
            #pragma unroll
            for (int p = 0; p < 4; p++) {
                uint32_t boff = (j8 * 16 + ((m_idx & 1) << 3) + rin) * PS
                              + p * 16 + ((m_idx >> 1) << 3);
                uint32_t vh0, vh1, vh2, vh3;
                ldsm_x4_t(vh0, vh1, vh2, vh3,
                          (uint32_t)__cvta_generic_to_shared(&sm[KB + PE + boff]));
                mma_f16(oacc[2*p],   pa[j8][0], pa[j8][1], pa[j8][2], pa[j8][3], vh0, vh1);
                mma_f16(oacc[2*p+1], pa[j8][0], pa[j8][1], pa[j8][2], pa[j8][3], vh2, vh3);
            }
        }
        __syncthreads();
    }

    // ---- epilogue: normalize, write bf16 hi/lo planes [B,S,D]
    const float inv0 = 1.f / l0, inv1 = 1.f / l1;
    const size_t o0 = (size_t)(b * S_ + q0 + tr) * D_ + hoff;
    const size_t o1 = o0 + (size_t)8 * D_;
    #pragma unroll
    for (int nt = 0; nt < 8; nt++) {
        const int coff = nt * 8 + tig * 2;
        uint32_t h01, l01, h23, l23;
        pack_hilo_b(oacc[nt][0] * inv0, oacc[nt][1] * inv0, h01, l01);
        pack_hilo_b(oacc[nt][2] * inv1, oacc[nt][3] * inv1, h23, l23);
        *(uint32_t*)&g_oh[o0 + coff] = h01;
        *(uint32_t*)&g_ol[o0 + coff] = l01;
        *(uint32_t*)&g_oh[o1 + coff] = h23;
        *(uint32_t*)&g_ol[o1 + coff] = l23;
    }
}

// ---------------------------------------------------------------------------
extern "C" void kernel_launch(void* const* d_in, const int* in_sizes, int n_in,
                              void* d_out, int out_size)
{
    const float* Q     = (const float*)d_in[0];
    const float* K     = (const float*)d_in[1];
    const float* V     = (const float*)d_in[2];
    const float* tmat  = (const float*)d_in[3];
    const float* dmat  = (const float*)d_in[4];
    const int*   mask  = (const int*)  d_in[5];
    const float* Wq    = (const float*)d_in[6];
    const float* bq    = (const float*)d_in[7];
    const float* Wk    = (const float*)d_in[8];
    const float* bk    = (const float*)d_in[9];
    const float* Wv    = (const float*)d_in[10];
    const float* bv    = (const float*)d_in[11];
    const float* Wo    = (const float*)d_in[12];
    const float* bo    = (const float*)d_in[13];
    const float* tm_w  = (const float*)d_in[14];
    const float* tm_b  = (const float*)d_in[15];
    const float* dm_w  = (const float*)d_in[16];
    const float* dm_b  = (const float*)d_in[17];
    const float* td_w  = (const float*)d_in[18];
    const float* td_b  = (const float*)d_in[19];
    float* out = (float*)d_out;

    __nv_bfloat16 *inh, *inl, *wh, *wl, *oh, *ol;
    cudaGetSymbolAddress((void**)&inh, g_in_h);
    cudaGetSymbolAddress((void**)&inl, g_in_l);
    cudaGetSymbolAddress((void**)&wh,  g_w_h);
    cudaGetSymbolAddress((void**)&wl,  g_w_l);
    cudaGetSymbolAddress((void**)&oh,  g_oh);
    cudaGetSymbolAddress((void**)&ol,  g_ol);
    __half *qh, *kh, *vh;
    cudaGetSymbolAddress((void**)&qh, g_qh);
    cudaGetSymbolAddress((void**)&kh, g_kh);
    cudaGetSymbolAddress((void**)&vh, g_vh);

    prep_kernel<<<1, 32>>>(tm_w, tm_b, dm_w, dm_b, td_w);

    // one launch: split inputs + weights to bf16 hi/lo planes
    split_all<<<3 * IN_BLKS + 4 * W_BLKS, 256>>>(
        Q, K, V, Wq, Wk, Wv, Wo, inh, inl, wh, wl);

    cudaFuncSetAttribute(gemm_planes,
                         cudaFuncAttributeMaxDynamicSharedMemorySize, GSMEM);

    // fused Q/K/V projections (z=0..2) + bias/mask CTAs (z=3..6) in ONE launch
    gemm_planes<<<dim3(D_ / 128, MTOT / 128, 7), 256, GSMEM>>>(
        inh, inl, wh, wl, (size_t)NELE, (size_t)DD,
        bq, bk, bv,
        out /*unused*/, qh, kh, vh,
        MTOT, D_, D_, 0.125f * LOG2E, 1,
        tmat, dmat, mask, tm_w, tm_b, dm_w, dm_b, td_w, td_b);

    cudaFuncSetAttribute(attn_f16,
                         cudaFuncAttributeMaxDynamicSharedMemorySize, SMEM_ATTN);
    attn_f16<<<dim3(S_ / 64, H_, B_), 128, SMEM_ATTN>>>();

    // output projection: bf16 planes in (attn output), fp32 out
    gemm_planes<<<dim3(D_ / 128, MTOT / 128, 1), 256, GSMEM>>>(
        oh, ol, wh + (size_t)3 * DD, wl + (size_t)3 * DD, 0, 0,
        bo, bo, bo,
        out, qh, kh, vh,
        MTOT, D_, D_, 1.f, 0,
        tmat, dmat, mask, tm_w, tm_b, dm_w, dm_b, td_w, td_b);
}

// round 12
// speedup vs baseline: 1.7582x; 1.1086x over previous
#include <cuda_runtime.h>
#include <cuda_bf16.h>
#include <cuda_fp16.h>
#include <cstdint>

#define B_  4
#define S_  1024
#define D_  512
#define H_  8
#define DK_ 64
#define MTOT (B_*S_)          // 4096 rows
#define NELE (B_*S_*D_)       // 2,097,152
#define DD   (D_*D_)
#define LOG2E 1.4426950408889634f

// Scratch (static device globals — allowed; no cudaMalloc anywhere)
__device__ __half g_in_h[(size_t)3*NELE], g_in_l[(size_t)3*NELE]; // Q,K,V inputs fp16 hi/lo
__device__ __half g_w_h[4*DD];                                    // Wq,Wk,Wv,Wo fp16
__device__ __half g_oh[NELE], g_ol[NELE];                         // attn out fp16 hi/lo
__device__ __half g_qh[NELE];   // projected Q (pre-scaled by log2e/8), fp16
__device__ __half g_kh[NELE];   // projected K, fp16
__device__ __half g_vh[NELE];   // projected V, fp16
__device__ float g_bias[(size_t)B_*S_*S_];  // bias*log2e, mask folded as -1.5e9
__device__ float g_Ct, g_Cd;
__device__ int   g_bzero;

// ---------------------------------------------------------------------------
// helpers
// ---------------------------------------------------------------------------
__device__ __forceinline__ float ex2f(float x) {
    float r; asm("ex2.approx.f32 %0, %1;" : "=f"(r) : "f"(x)); return r;
}

__device__ __forceinline__ void mma_f16(float c[4],
    uint32_t a0, uint32_t a1, uint32_t a2, uint32_t a3,
    uint32_t b0, uint32_t b1)
{
    asm volatile(
        "mma.sync.aligned.m16n8k16.row.col.f32.f16.f16.f32 "
        "{%0,%1,%2,%3},{%4,%5,%6,%7},{%8,%9},{%0,%1,%2,%3};"
        : "+f"(c[0]), "+f"(c[1]), "+f"(c[2]), "+f"(c[3])
        : "r"(a0), "r"(a1), "r"(a2), "r"(a3), "r"(b0), "r"(b1));
}

__device__ __forceinline__ void ldsm_x4(uint32_t& r0, uint32_t& r1,
                                        uint32_t& r2, uint32_t& r3, uint32_t addr)
{
    asm volatile("ldmatrix.sync.aligned.m8n8.x4.shared.b16 {%0,%1,%2,%3}, [%4];"
        : "=r"(r0), "=r"(r1), "=r"(r2), "=r"(r3) : "r"(addr));
}

__device__ __forceinline__ void ldsm_x4_t(uint32_t& r0, uint32_t& r1,
                                          uint32_t& r2, uint32_t& r3, uint32_t addr)
{
    asm volatile("ldmatrix.sync.aligned.m8n8.x4.trans.shared.b16 {%0,%1,%2,%3}, [%4];"
        : "=r"(r0), "=r"(r1), "=r"(r2), "=r"(r3) : "r"(addr));
}

__device__ __forceinline__ void cpa16(uint32_t dst, const void* src) {
    asm volatile("cp.async.cg.shared.global [%0], [%1], 16;" :: "r"(dst), "l"(src));
}
__device__ __forceinline__ void cp_commit() {
    asm volatile("cp.async.commit_group;");
}
template<int N> __device__ __forceinline__ void cp_wait() {
    asm volatile("cp.async.wait_group %0;" :: "n"(N));
}

// fp16 hi/lo split pack of a float pair
__device__ __forceinline__ void pack_hilo_h(float x, float y, uint32_t& hi, uint32_t& lo) {
    __half2 h = __floats2half2_rn(x, y);
    float2 f = __half22float2(h);
    __half2 l = __floats2half2_rn(x - f.x, y - f.y);
    hi = *reinterpret_cast<uint32_t*>(&h);
    lo = *reinterpret_cast<uint32_t*>(&l);
}

// ---------------------------------------------------------------------------
// Split fp32 tensors -> fp16 planes. Inputs: hi/lo pair. Weights: single fp16.
// ---------------------------------------------------------------------------
#define IN_BLKS (NELE/1024)      // 2048 per tensor
#define W_BLKS  (DD/1024)        // 256 per tensor

__global__ __launch_bounds__(256) void split_all(
    const float* __restrict__ Q, const float* __restrict__ K, const float* __restrict__ V,
    const float* __restrict__ Wq, const float* __restrict__ Wk,
    const float* __restrict__ Wv, const float* __restrict__ Wo,
    __half* __restrict__ inh, __half* __restrict__ inl,
    __half* __restrict__ wh)
{
    const int bx = blockIdx.x;
    if (bx < 3 * IN_BLKS) {
        int ten = bx / IN_BLKS, rel = bx % IN_BLKS;
        const float* s = ((ten == 0) ? Q : (ten == 1) ? K : V) + (size_t)rel * 1024;
        size_t off = (size_t)ten * NELE + (size_t)rel * 1024;
        const size_t si = (size_t)threadIdx.x * 4;
        float4 v = *(const float4*)&s[si];
        uint32_t h01, l01, h23, l23;
        pack_hilo_h(v.x, v.y, h01, l01);
        pack_hilo_h(v.z, v.w, h23, l23);
        *(uint2*)&inh[off + si] = make_uint2(h01, h23);
        *(uint2*)&inl[off + si] = make_uint2(l01, l23);
    } else {
        int id = bx - 3 * IN_BLKS;
        int ten = id / W_BLKS, rel = id % W_BLKS;
        const float* s = ((ten == 0) ? Wq : (ten == 1) ? Wk : (ten == 2) ? Wv : Wo)
                         + (size_t)rel * 1024;
        size_t off = (size_t)ten * DD + (size_t)rel * 1024;
        const size_t si = (size_t)threadIdx.x * 4;
        float4 v = *(const float4*)&s[si];
        __half2 h01 = __floats2half2_rn(v.x, v.y);
        __half2 h23 = __floats2half2_rn(v.z, v.w);
        *(uint2*)&wh[off + si] = make_uint2(*(uint32_t*)&h01, *(uint32_t*)&h23);
    }
}

// ---------------------------------------------------------------------------
// GEMM, fp16 2-term (A = hi+lo fp16, W single fp16): R = (A@W + bias)*scale.
// blockIdx.z: 0..2 = GEMM problems, 3..6 = co-scheduled bias+mask CTAs.
// ---------------------------------------------------------------------------
#define AKP 40
#define BNP 136
#define AS (128*AKP)
#define BS (32*BNP)
#define GSMEM ((4*AS + 2*BS) * 2)   // 58368 bytes

__global__ __launch_bounds__(256, 2) void gemm_planes(
    const __half* __restrict__ Ah_, const __half* __restrict__ Al_,
    const __half* __restrict__ Wh_,
    size_t aStride, size_t wStride,
    const float* __restrict__ b0v, const float* __restrict__ b1v, const float* __restrict__ b2v,
    float* __restrict__ C0,
    __half* __restrict__ H0, __half* __restrict__ H1, __half* __restrict__ H2,
    int M, int N, int K, float scale0, int fp16_out,
    const float* __restrict__ tmat, const float* __restrict__ dmat,
    const int*   __restrict__ mask,
    const float* __restrict__ tm_w, const float* __restrict__ tm_b,
    const float* __restrict__ dm_w, const float* __restrict__ dm_b,
    const float* __restrict__ td_w, const float* __restrict__ td_b)
{
    extern __shared__ __half gsm[];

    const int t = threadIdx.x;

    // =================== bias + mask CTAs (z >= 3) ===================
    if (blockIdx.z >= 3) {
        const int cta = (blockIdx.z - 3) * 128 + blockIdx.y * 4 + blockIdx.x; // 0..511
        const float tdb = td_b[0] * LOG2E;
        const float E = 2.718281828459045f;
        const int bz = g_bzero;
        const float Ct = g_Ct, Cd = g_Cd;

        float* sp = (float*)gsm;   // [5][64] fallback params
        if (!bz) {
            if (t < 64) {
                sp[0*64 + t] = tm_w[t];
                sp[1*64 + t] = tm_b[t];
                sp[2*64 + t] = dm_w[t];
                sp[3*64 + t] = dm_b[t];
                sp[4*64 + t] = td_w[t] * 0.5f * LOG2E;
            }
            __syncthreads();
        }

        #pragma unroll 2
        for (int i = 0; i < 8; i++) {
            const size_t base = (((size_t)cta * 8 + i) * 256 + t) * 4;
            float4 u  = *(const float4*)(tmat + base);
            float4 w4 = *(const float4*)(dmat + base);
            int4   mk = *(const int4*)(mask + base);

            float tv[4] = { 1.f / __logf(E + u.x), 1.f / __logf(E + u.y),
                            1.f / __logf(E + u.z), 1.f / __logf(E + u.w) };
            float dv[4] = { 1.f / __logf(E + w4.x), 1.f / __logf(E + w4.y),
                            1.f / __logf(E + w4.z), 1.f / __logf(E + w4.w) };
            float acc[4];
            if (bz) {
                #pragma unroll
                for (int e = 0; e < 4; e++)
                    acc[e] = fmaf(tv[e], Ct, fmaf(dv[e], Cd, tdb));
            } else {
                #pragma unroll
                for (int e = 0; e < 4; e++) acc[e] = tdb;
                #pragma unroll 8
                for (int m = 0; m < 64; m++) {
                    const float tw = sp[0*64 + m], tb = sp[1*64 + m];
                    const float dw = sp[2*64 + m], db = sp[3*64 + m];
                    const float ww = sp[4*64 + m];
                    #pragma unroll
                    for (int e = 0; e < 4; e++) {
                        float rt = fmaxf(tv[e] * tw + tb, 0.f);
                        float rd = fmaxf(dv[e] * dw + db, 0.f);
                        acc[e] += ww * (rt + rd);
                    }
                }
            }
            float4 o;
            o.x = (mk.x == 1) ? -1.5e9f : acc[0];
            o.y = (mk.y == 1) ? -1.5e9f : acc[1];
            o.z = (mk.z == 1) ? -1.5e9f : acc[2];
            o.w = (mk.w == 1) ? -1.5e9f : acc[3];
            *(float4*)(g_bias + base) = o;
        }
        return;
    }

    // =================== GEMM CTAs (z < 3) ===================
    __half* Ahs = gsm;                 // [2][AS]
    __half* Als = gsm + 2 * AS;        // [2][AS]
    __half* Bhs = gsm + 4 * AS;        // [2][BS]

    const int z = blockIdx.z;
    const __half* Ah = Ah_ + (size_t)z * aStride;
    const __half* Al = Al_ + (size_t)z * aStride;
    const __half* Wh = Wh_ + (size_t)z * wStride;
    const float* bias = (z == 0) ? b0v : (z == 1) ? b1v : b2v;
    __half* Ho = (z == 0) ? H0 : (z == 1) ? H1 : H2;
    const float osc = (z == 0) ? scale0 : 1.f;

    const int lane = t & 31, wid = t >> 5;
    const int warp_m = wid & 3, warp_n = wid >> 2;
    const int m_w = warp_m * 32, n_w = warp_n * 64;
    const int bm = blockIdx.y * 128, bn = blockIdx.x * 128;
    const int gid = lane >> 2, tig = lane & 3;
    const int m_idx = lane >> 3, rin = lane & 7;

    float acc[2][8][4];
    #pragma unroll
    for (int mt = 0; mt < 2; mt++)
        #pragma unroll
        for (int nt = 0; nt < 8; nt++)
            #pragma unroll
            for (int e = 0; e < 4; e++) acc[mt][nt][e] = 0.f;

    const int c0 = t, c1 = t + 256;

    auto issue = [&](int st, int k0) {
        #pragma unroll
        for (int r = 0; r < 2; r++) {
            int c = (r == 0) ? c0 : c1;
            int arow = c >> 2, ak = (c & 3) * 8;
            size_t ga = (size_t)(bm + arow) * K + k0 + ak;
            cpa16((uint32_t)__cvta_generic_to_shared(&Ahs[st * AS + arow * AKP + ak]), &Ah[ga]);
            cpa16((uint32_t)__cvta_generic_to_shared(&Als[st * AS + arow * AKP + ak]), &Al[ga]);
            int krow = c >> 4, nc = (c & 15) * 8;
            size_t gb = (size_t)(k0 + krow) * N + bn + nc;
            cpa16((uint32_t)__cvta_generic_to_shared(&Bhs[st * BS + krow * BNP + nc]), &Wh[gb]);
        }
    };

    issue(0, 0);
    cp_commit();

    const int NIT = K / 32;
    for (int it = 0; it < NIT; it++) {
        const int st = it & 1;
        if (it + 1 < NIT) {
            issue(st ^ 1, (it + 1) * 32);
            cp_commit();
            cp_wait<1>();
        } else {
            cp_wait<0>();
        }
        __syncthreads();

        #pragma unroll
        for (int kb = 0; kb < 32; kb += 16) {
            uint32_t af[2][2][4];
            #pragma unroll
            for (int mt = 0; mt < 2; mt++) {
                const int arow = m_w + mt * 16 + (lane & 15);
                const int acol = kb + ((lane >> 4) << 3);
                ldsm_x4(af[mt][0][0], af[mt][0][1], af[mt][0][2], af[mt][0][3],
                        (uint32_t)__cvta_generic_to_shared(&Ahs[st * AS + arow * AKP + acol]));
                ldsm_x4(af[mt][1][0], af[mt][1][1], af[mt][1][2], af[mt][1][3],
                        (uint32_t)__cvta_generic_to_shared(&Als[st * AS + arow * AKP + acol]));
            }
            #pragma unroll
            for (int p = 0; p < 4; p++) {
                const int brow = kb + ((m_idx & 1) << 3) + rin;
                const int bcol = n_w + p * 16 + ((m_idx >> 1) << 3);
                uint32_t bh0, bh1, bh2, bh3;
                ldsm_x4_t(bh0, bh1, bh2, bh3,
                    (uint32_t)__cvta_generic_to_shared(&Bhs[st * BS + brow * BNP + bcol]));
                #pragma unroll
                for (int mt = 0; mt < 2; mt++) {
                    mma_f16(acc[mt][2*p], af[mt][0][0], af[mt][0][1],
                            af[mt][0][2], af[mt][0][3], bh0, bh1);
                    mma_f16(acc[mt][2*p], af[mt][1][0], af[mt][1][1],
                            af[mt][1][2], af[mt][1][3], bh0, bh1);
                    mma_f16(acc[mt][2*p+1], af[mt][0][0], af[mt][0][1],
                            af[mt][0][2], af[mt][0][3], bh2, bh3);
                    mma_f16(acc[mt][2*p+1], af[mt][1][0], af[mt][1][1],
                            af[mt][1][2], af[mt][1][3], bh2, bh3);
                }
            }
        }
        __syncthreads();
    }

    // ---- epilogue
    #pragma unroll
    for (int mt = 0; mt < 2; mt++) {
        const int row0 = bm + m_w + mt * 16 + gid;
        #pragma unroll
        for (int nt = 0; nt < 8; nt++) {
            const int col = bn + n_w + nt * 8 + tig * 2;
            float2 bb = *(const float2*)&bias[col];
            float v0 = (acc[mt][nt][0] + bb.x) * osc;
            float v1 = (acc[mt][nt][1] + bb.y) * osc;
            float v2 = (acc[mt][nt][2] + bb.x) * osc;
            float v3 = (acc[mt][nt][3] + bb.y) * osc;
            if (fp16_out) {
                __half2 h01 = __floats2half2_rn(v0, v1);
                __half2 h23 = __floats2half2_rn(v2, v3);
                *(__half2*)&Ho[(size_t)row0 * N + col]       = h01;
                *(__half2*)&Ho[(size_t)(row0 + 8) * N + col] = h23;
            } else {
                *(float2*)&C0[(size_t)row0 * N + col]       = make_float2(v0, v1);
                *(float2*)&C0[(size_t)(row0 + 8) * N + col] = make_float2(v2, v3);
            }
        }
    }
}

// ---------------------------------------------------------------------------
// Prep: detect all-zero biases; precompute collapsed coefficients (log2 domain)
// ---------------------------------------------------------------------------
__global__ void prep_kernel(const float* __restrict__ tm_w, const float* __restrict__ tm_b,
                            const float* __restrict__ dm_w, const float* __restrict__ dm_b,
                            const float* __restrict__ td_w)
{
    const int l = threadIdx.x;   // 32 threads
    float ct = 0.f, cd = 0.f;
    bool z = true;
    #pragma unroll
    for (int m = l; m < 64; m += 32) {
        z = z && (tm_b[m] == 0.f) && (dm_b[m] == 0.f);
        ct += (0.5f * LOG2E) * td_w[m] * fmaxf(tm_w[m], 0.f);
        cd += (0.5f * LOG2E) * td_w[m] * fmaxf(dm_w[m], 0.f);
    }
    unsigned bz = __ballot_sync(0xffffffffu, z);
    #pragma unroll
    for (int o = 16; o; o >>= 1) {
        ct += __shfl_xor_sync(0xffffffffu, ct, o);
        cd += __shfl_xor_sync(0xffffffffu, cd, o);
    }
    if (l == 0) { g_Ct = ct; g_Cd = cd; g_bzero = (bz == 0xffffffffu); }
}

// ---------------------------------------------------------------------------
// Flash attention, pure fp16 TC, log2-domain softmax, smem-staged bias.
// 5 effective planes -> 54 KB/CTA, 4 CTAs/SM. Epilogue -> fp16 hi/lo planes.
// ---------------------------------------------------------------------------
#define PS 72
#define PE (64*PS)             // 4608 halves per plane
#define BSS 68                 // bias smem row stride (floats)
#define KV0 8704               // halves; bias buffer = 64*68 floats = 8704 halves
#define SMEM_ATTN ((KV0 + 4*PE)*2)   // 54272 bytes

__global__ __launch_bounds__(128, 4) void attn_f16()
{
    extern __shared__ __half sm[];
    float* biasS = (float*)sm;   // overlays Q plane after prologue

    const int qt = blockIdx.x, h = blockIdx.y, b = blockIdx.z;
    const int t = threadIdx.x;
    const int w = t >> 5, lane = t & 31;
    const int gid = lane >> 2, tig = lane & 3;
    const int q0 = qt * 64, hoff = h * DK_;
    const int tr = w * 16 + gid;
    const int m_idx = lane >> 3, rin = lane & 7;

    // ---- prologue: Q plane (offset 0) + K/V tile0 (buf0 at KV0, KV0+PE)
    #pragma unroll
    for (int i = 0; i < 4; i++) {
        int c = t + i * 128;
        int row = c >> 3, col = (c & 7) * 8;
        size_t gq = (size_t)(b * S_ + q0 + row) * D_ + hoff + col;
        size_t gk = (size_t)(b * S_ + row) * D_ + hoff + col;
        uint32_t so = row * PS + col;
        cpa16((uint32_t)__cvta_generic_to_shared(&sm[so]),            &g_qh[gq]);
        cpa16((uint32_t)__cvta_generic_to_shared(&sm[KV0 + so]),      &g_kh[gk]);
        cpa16((uint32_t)__cvta_generic_to_shared(&sm[KV0 + PE + so]), &g_vh[gk]);
    }
    cp_commit();
    cp_wait<0>();
    __syncthreads();

    // ---- Q fragments, loop-invariant
    uint32_t qf[4][4];
    #pragma unroll
    for (int d8 = 0; d8 < 4; d8++) {
        uint32_t a = (uint32_t)__cvta_generic_to_shared(
            &sm[(w * 16 + (lane & 15)) * PS + d8 * 16 + ((lane >> 4) << 3)]);
        ldsm_x4(qf[d8][0], qf[d8][1], qf[d8][2], qf[d8][3], a);
    }
    __syncthreads();   // Q plane now dead -> becomes the bias buffer

    float m0 = -1e30f, m1 = -1e30f, l0 = 0.f, l1 = 0.f;
    float oacc[8][4];
    #pragma unroll
    for (int nt = 0; nt < 8; nt++)
        #pragma unroll
        for (int e = 0; e < 4; e++) oacc[nt][e] = 0.f;

    for (int kt = 0; kt < 16; kt++) {
        const int buf = kt & 1;

        // ---- issue bias(kt) copy (group B_kt)
        #pragma unroll
        for (int i = 0; i < 8; i++) {
            int idx = t + i * 128;
            int row = idx >> 4, c4 = (idx & 15) << 2;
            cpa16((uint32_t)__cvta_generic_to_shared(&biasS[row * BSS + c4]),
                  &g_bias[((size_t)(b * S_ + q0 + row)) * S_ + kt * 64 + c4]);
        }
        cp_commit();

        // ---- issue KV(kt+1), wait KV(kt)
        if (kt < 15) {
            const int k1 = (kt + 1) * 64;
            const int KBn = KV0 + (buf ^ 1) * 2 * PE;
            #pragma unroll
            for (int i = 0; i < 4; i++) {
                int c = t + i * 128;
                int row = c >> 3, col = (c & 7) * 8;
                size_t g = (size_t)(b * S_ + k1 + row) * D_ + hoff + col;
                uint32_t so = row * PS + col;
                cpa16((uint32_t)__cvta_generic_to_shared(&sm[KBn + so]),      &g_kh[g]);
                cpa16((uint32_t)__cvta_generic_to_shared(&sm[KBn + PE + so]), &g_vh[g]);
            }
            cp_commit();
            cp_wait<2>();
        } else {
            cp_wait<1>();
        }
        __syncthreads();

        const int KB = KV0 + buf * 2 * PE;   // K plane; V = KB + PE

        // ---- scores S = Q @ K^T (log2-domain), single-term fp16
        float sacc[8][4];
        #pragma unroll
        for (int nt = 0; nt < 8; nt++)
            #pragma unroll
            for (int e = 0; e < 4; e++) sacc[nt][e] = 0.f;

        #pragma unroll
        for (int d8 = 0; d8 < 4; d8++) {
            #pragma unroll
            for (int p = 0; p < 4; p++) {
                uint32_t boff = (p * 16 + ((m_idx & 1) << 3) + rin) * PS
                              + d8 * 16 + ((m_idx >> 1) << 3);
                uint32_t kh0, kh1, kh2, kh3;
                ldsm_x4(kh0, kh1, kh2, kh3,
                        (uint32_t)__cvta_generic_to_shared(&sm[KB + boff]));
                mma_f16(sacc[2*p],   qf[d8][0], qf[d8][1], qf[d8][2], qf[d8][3], kh0, kh2);
                mma_f16(sacc[2*p+1], qf[d8][0], qf[d8][1], qf[d8][2], qf[d8][3], kh1, kh3);
            }
        }

        // ---- bias now resident in smem
        if (kt < 15) { cp_wait<1>(); } else { cp_wait<0>(); }
        __syncthreads();

        float mx0 = -1e30f, mx1 = -1e30f;
        #pragma unroll
        for (int nt = 0; nt < 8; nt++) {
            float2 ba = *(const float2*)&biasS[tr * BSS + nt * 8 + tig * 2];
            float2 bb = *(const float2*)&biasS[(tr + 8) * BSS + nt * 8 + tig * 2];
            sacc[nt][0] += ba.x;
            sacc[nt][1] += ba.y;
            sacc[nt][2] += bb.x;
            sacc[nt][3] += bb.y;
            mx0 = fmaxf(mx0, fmaxf(sacc[nt][0], sacc[nt][1]));
            mx1 = fmaxf(mx1, fmaxf(sacc[nt][2], sacc[nt][3]));
        }
        mx0 = fmaxf(mx0, __shfl_xor_sync(0xffffffffu, mx0, 1));
        mx0 = fmaxf(mx0, __shfl_xor_sync(0xffffffffu, mx0, 2));
        mx1 = fmaxf(mx1, __shfl_xor_sync(0xffffffffu, mx1, 1));
        mx1 = fmaxf(mx1, __shfl_xor_sync(0xffffffffu, mx1, 2));

        const float mn0 = fmaxf(m0, mx0), mn1 = fmaxf(m1, mx1);
        const float c0 = ex2f(m0 - mn0), c1 = ex2f(m1 - mn1);
        m0 = mn0; m1 = mn1;

        float rs0 = 0.f, rs1 = 0.f;
        #pragma unroll
        for (int nt = 0; nt < 8; nt++) {
            sacc[nt][0] = ex2f(sacc[nt][0] - mn0);
            sacc[nt][1] = ex2f(sacc[nt][1] - mn0);
            sacc[nt][2] = ex2f(sacc[nt][2] - mn1);
            sacc[nt][3] = ex2f(sacc[nt][3] - mn1);
            rs0 += sacc[nt][0] + sacc[nt][1];
            rs1 += sacc[nt][2] + sacc[nt][3];
        }
        rs0 += __shfl_xor_sync(0xffffffffu, rs0, 1);
        rs0 += __shfl_xor_sync(0xffffffffu, rs0, 2);
        rs1 += __shfl_xor_sync(0xffffffffu, rs1, 1);
        rs1 += __shfl_xor_sync(0xffffffffu, rs1, 2);

        l0 = l0 * c0 + rs0;
        l1 = l1 * c1 + rs1;
        #pragma unroll
        for (int nt = 0; nt < 8; nt++) {
            oacc[nt][0] *= c0; oacc[nt][1] *= c0;
            oacc[nt][2] *= c1; oacc[nt][3] *= c1;
        }

        // ---- pack P into fp16 A-fragments (registers only)
        uint32_t pa[4][4];
        #pragma unroll
        for (int j8 = 0; j8 < 4; j8++) {
            const float* sA = sacc[2 * j8];
            const float* sB = sacc[2 * j8 + 1];
            __half2 hh;
            hh = __floats2half2_rn(sA[0], sA[1]); pa[j8][0] = *(uint32_t*)&hh;
            hh = __floats2half2_rn(sA[2], sA[3]); pa[j8][1] = *(uint32_t*)&hh;
            hh = __floats2half2_rn(sB[0], sB[1]); pa[j8][2] = *(uint32_t*)&hh;
            hh = __floats2half2_rn(sB[2], sB[3]); pa[j8][3] = *(uint32_t*)&hh;
        }

        // ---- O += P @ V : single-term fp16, V via ldmatrix.x4.trans
        #pragma unroll
        for (int j8 = 0; j8 < 4; j8++) {
            #pragma unroll
            for (int p = 0; p < 4; p++) {
                uint32_t boff = (j8 * 16 + ((m_idx & 1) << 3) + rin) * PS
                              + p * 16 + ((m_idx >> 1) << 3);
                uint32_t vh0, vh1, vh2, vh3;
                ldsm_x4_t(vh0, vh1, vh2, vh3,
                          (uint32_t)__cvta_generic_to_shared(&sm[KB + PE + boff]));
                mma_f16(oacc[2*p],   pa[j8][0], pa[j8][1], pa[j8][2], pa[j8][3], vh0, vh1);
                mma_f16(oacc[2*p+1], pa[j8][0], pa[j8][1], pa[j8][2], pa[j8][3], vh2, vh3);
            }
        }
        __syncthreads();
    }

    // ---- epilogue: normalize, write fp16 hi/lo planes [B,S,D]
    const float inv0 = 1.f / l0, inv1 = 1.f / l1;
    const size_t o0 = (size_t)(b * S_ + q0 + tr) * D_ + hoff;
    const size_t o1 = o0 + (size_t)8 * D_;
    #pragma unroll
    for (int nt = 0; nt < 8; nt++) {
        const int coff = nt * 8 + tig * 2;
        uint32_t h01, l01, h23, l23;
        pack_hilo_h(oacc[nt][0] * inv0, oacc[nt][1] * inv0, h01, l01);
        pack_hilo_h(oacc[nt][2] * inv1, oacc[nt][3] * inv1, h23, l23);
        *(uint32_t*)&g_oh[o0 + coff] = h01;
        *(uint32_t*)&g_ol[o0 + coff] = l01;
        *(uint32_t*)&g_oh[o1 + coff] = h23;
        *(uint32_t*)&g_ol[o1 + coff] = l23;
    }
}

// ---------------------------------------------------------------------------
extern "C" void kernel_launch(void* const* d_in, const int* in_sizes, int n_in,
                              void* d_out, int out_size)
{
    const float* Q     = (const float*)d_in[0];
    const float* K     = (const float*)d_in[1];
    const float* V     = (const float*)d_in[2];
    const float* tmat  = (const float*)d_in[3];
    const float* dmat  = (const float*)d_in[4];
    const int*   mask  = (const int*)  d_in[5];
    const float* Wq    = (const float*)d_in[6];
    const float* bq    = (const float*)d_in[7];
    const float* Wk    = (const float*)d_in[8];
    const float* bk    = (const float*)d_in[9];
    const float* Wv    = (const float*)d_in[10];
    const float* bv    = (const float*)d_in[11];
    const float* Wo    = (const float*)d_in[12];
    const float* bo    = (const float*)d_in[13];
    const float* tm_w  = (const float*)d_in[14];
    const float* tm_b  = (const float*)d_in[15];
    const float* dm_w  = (const float*)d_in[16];
    const float* dm_b  = (const float*)d_in[17];
    const float* td_w  = (const float*)d_in[18];
    const float* td_b  = (const float*)d_in[19];
    float* out = (float*)d_out;

    __half *inh, *inl, *wh, *oh, *ol, *qh, *kh, *vh;
    cudaGetSymbolAddress((void**)&inh, g_in_h);
    cudaGetSymbolAddress((void**)&inl, g_in_l);
    cudaGetSymbolAddress((void**)&wh,  g_w_h);
    cudaGetSymbolAddress((void**)&oh,  g_oh);
    cudaGetSymbolAddress((void**)&ol,  g_ol);
    cudaGetSymbolAddress((void**)&qh,  g_qh);
    cudaGetSymbolAddress((void**)&kh,  g_kh);
    cudaGetSymbolAddress((void**)&vh,  g_vh);

    prep_kernel<<<1, 32>>>(tm_w, tm_b, dm_w, dm_b, td_w);

    // one launch: split inputs (fp16 hi/lo) + weights (fp16)
    split_all<<<3 * IN_BLKS + 4 * W_BLKS, 256>>>(
        Q, K, V, Wq, Wk, Wv, Wo, inh, inl, wh);

    cudaFuncSetAttribute(gemm_planes,
                         cudaFuncAttributeMaxDynamicSharedMemorySize, GSMEM);

    // fused Q/K/V projections (z=0..2) + bias/mask CTAs (z=3..6) in ONE launch
    gemm_planes<<<dim3(D_ / 128, MTOT / 128, 7), 256, GSMEM>>>(
        inh, inl, wh, (size_t)NELE, (size_t)DD,
        bq, bk, bv,
        out /*unused*/, qh, kh, vh,
        MTOT, D_, D_, 0.125f * LOG2E, 1,
        tmat, dmat, mask, tm_w, tm_b, dm_w, dm_b, td_w, td_b);

    cudaFuncSetAttribute(attn_f16,
                         cudaFuncAttributeMaxDynamicSharedMemorySize, SMEM_ATTN);
    attn_f16<<<dim3(S_ / 64, H_, B_), 128, SMEM_ATTN>>>();

    // output projection: fp16 hi/lo planes in (attn output), fp32 out
    gemm_planes<<<dim3(D_ / 128, MTOT / 128, 1), 256, GSMEM>>>(
        oh, ol, wh + (size_t)3 * DD, 0, 0,
        bo, bo, bo,
        out, qh, kh, vh,
        MTOT, D_, D_, 1.f, 0,
        tmat, dmat, mask, tm_w, tm_b, dm_w, dm_b, td_w, td_b);
}

// round 13
// speedup vs baseline: 2.0468x; 1.1642x over previous
#include <cuda_runtime.h>
#include <cuda_bf16.h>
#include <cuda_fp16.h>
#include <cstdint>

#define B_  4
#define S_  1024
#define D_  512
#define H_  8
#define DK_ 64
#define MTOT (B_*S_)          // 4096 rows
#define NELE (B_*S_*D_)       // 2,097,152
#define DD   (D_*D_)
#define LOG2E 1.4426950408889634f

// Scratch (static device globals — allowed; no cudaMalloc anywhere)
__device__ __half g_in_h[(size_t)3*NELE];   // Q,K,V inputs fp16 (single plane)
__device__ __half g_w_h[4*DD];              // Wq,Wk,Wv,Wo fp16
__device__ __half g_oh[NELE], g_ol[NELE];   // attn out fp16 hi/lo
__device__ __half g_qh[NELE];   // projected Q (pre-scaled by log2e/8), fp16
__device__ __half g_kh[NELE];   // projected K, fp16
__device__ __half g_vh[NELE];   // projected V, fp16
__device__ float g_bias[(size_t)B_*S_*S_];  // bias*log2e, mask folded as -1.5e9
__device__ float g_Ct, g_Cd;
__device__ int   g_bzero;

// ---------------------------------------------------------------------------
// helpers
// ---------------------------------------------------------------------------
__device__ __forceinline__ float ex2f(float x) {
    float r; asm("ex2.approx.f32 %0, %1;" : "=f"(r) : "f"(x)); return r;
}

__device__ __forceinline__ void mma_f16(float c[4],
    uint32_t a0, uint32_t a1, uint32_t a2, uint32_t a3,
    uint32_t b0, uint32_t b1)
{
    asm volatile(
        "mma.sync.aligned.m16n8k16.row.col.f32.f16.f16.f32 "
        "{%0,%1,%2,%3},{%4,%5,%6,%7},{%8,%9},{%0,%1,%2,%3};"
        : "+f"(c[0]), "+f"(c[1]), "+f"(c[2]), "+f"(c[3])
        : "r"(a0), "r"(a1), "r"(a2), "r"(a3), "r"(b0), "r"(b1));
}

__device__ __forceinline__ void ldsm_x4(uint32_t& r0, uint32_t& r1,
                                        uint32_t& r2, uint32_t& r3, uint32_t addr)
{
    asm volatile("ldmatrix.sync.aligned.m8n8.x4.shared.b16 {%0,%1,%2,%3}, [%4];"
        : "=r"(r0), "=r"(r1), "=r"(r2), "=r"(r3) : "r"(addr));
}

__device__ __forceinline__ void ldsm_x4_t(uint32_t& r0, uint32_t& r1,
                                          uint32_t& r2, uint32_t& r3, uint32_t addr)
{
    asm volatile("ldmatrix.sync.aligned.m8n8.x4.trans.shared.b16 {%0,%1,%2,%3}, [%4];"
        : "=r"(r0), "=r"(r1), "=r"(r2), "=r"(r3) : "r"(addr));
}

__device__ __forceinline__ void cpa16(uint32_t dst, const void* src) {
    asm volatile("cp.async.cg.shared.global [%0], [%1], 16;" :: "r"(dst), "l"(src));
}
__device__ __forceinline__ void cp_commit() {
    asm volatile("cp.async.commit_group;");
}
template<int N> __device__ __forceinline__ void cp_wait() {
    asm volatile("cp.async.wait_group %0;" :: "n"(N));
}

// fp16 hi/lo split pack of a float pair
__device__ __forceinline__ void pack_hilo_h(float x, float y, uint32_t& hi, uint32_t& lo) {
    __half2 h = __floats2half2_rn(x, y);
    float2 f = __half22float2(h);
    __half2 l = __floats2half2_rn(x - f.x, y - f.y);
    hi = *reinterpret_cast<uint32_t*>(&h);
    lo = *reinterpret_cast<uint32_t*>(&l);
}

// ---------------------------------------------------------------------------
// Split fp32 tensors -> single fp16 plane. Last block also runs the prep
// (bias-zero detection + collapsed coefficients).
// ---------------------------------------------------------------------------
#define IN_BLKS (NELE/1024)      // 2048 per tensor
#define W_BLKS  (DD/1024)        // 256 per tensor
#define SPLIT_BLKS (3*IN_BLKS + 4*W_BLKS + 1)

__global__ __launch_bounds__(256) void split_all(
    const float* __restrict__ Q, const float* __restrict__ K, const float* __restrict__ V,
    const float* __restrict__ Wq, const float* __restrict__ Wk,
    const float* __restrict__ Wv, const float* __restrict__ Wo,
    __half* __restrict__ inh, __half* __restrict__ wh,
    const float* __restrict__ tm_w, const float* __restrict__ tm_b,
    const float* __restrict__ dm_w, const float* __restrict__ dm_b,
    const float* __restrict__ td_w)
{
    const int bx = blockIdx.x;
    if (bx == SPLIT_BLKS - 1) {               // prep block
        const int l = threadIdx.x;
        if (l < 32) {
            float ct = 0.f, cd = 0.f;
            bool z = true;
            #pragma unroll
            for (int m = l; m < 64; m += 32) {
                z = z && (tm_b[m] == 0.f) && (dm_b[m] == 0.f);
                ct += (0.5f * LOG2E) * td_w[m] * fmaxf(tm_w[m], 0.f);
                cd += (0.5f * LOG2E) * td_w[m] * fmaxf(dm_w[m], 0.f);
            }
            unsigned bz = __ballot_sync(0xffffffffu, z);
            #pragma unroll
            for (int o = 16; o; o >>= 1) {
                ct += __shfl_xor_sync(0xffffffffu, ct, o);
                cd += __shfl_xor_sync(0xffffffffu, cd, o);
            }
            if (l == 0) { g_Ct = ct; g_Cd = cd; g_bzero = (bz == 0xffffffffu); }
        }
        return;
    }

    const float* s;
    __half* dst;
    size_t off;
    if (bx < 3 * IN_BLKS) {
        int ten = bx / IN_BLKS, rel = bx % IN_BLKS;
        s = ((ten == 0) ? Q : (ten == 1) ? K : V) + (size_t)rel * 1024;
        off = (size_t)ten * NELE + (size_t)rel * 1024;
        dst = inh;
    } else {
        int id = bx - 3 * IN_BLKS;
        int ten = id / W_BLKS, rel = id % W_BLKS;
        s = ((ten == 0) ? Wq : (ten == 1) ? Wk : (ten == 2) ? Wv : Wo)
            + (size_t)rel * 1024;
        off = (size_t)ten * DD + (size_t)rel * 1024;
        dst = wh;
    }
    const size_t si = (size_t)threadIdx.x * 4;
    float4 v = *(const float4*)&s[si];
    __half2 h01 = __floats2half2_rn(v.x, v.y);
    __half2 h23 = __floats2half2_rn(v.z, v.w);
    *(uint2*)&dst[off + si] = make_uint2(*(uint32_t*)&h01, *(uint32_t*)&h23);
}

// ---------------------------------------------------------------------------
// Templated GEMM: tile MT x 128, A fp16 (optionally + lo plane if TWO).
// MT=128: 8 warps as 4m x 2n (warp 32x64). MT=64: 8 warps as 2m x 4n (32x32).
// For MT=128, blockIdx.z in 3..6 runs co-scheduled bias+mask CTAs.
// ---------------------------------------------------------------------------
#define AKP 40
#define BNP 136
#define BS (32*BNP)

template<int MT, bool TWO>
__global__ __launch_bounds__(256, 2) void gemm_planes(
    const __half* __restrict__ Ah_, const __half* __restrict__ Al_,
    const __half* __restrict__ Wh_,
    size_t aStride, size_t wStride,
    const float* __restrict__ b0v, const float* __restrict__ b1v, const float* __restrict__ b2v,
    float* __restrict__ C0,
    __half* __restrict__ H0, __half* __restrict__ H1, __half* __restrict__ H2,
    int M, int N, int K, float scale0, int fp16_out,
    const float* __restrict__ tmat, const float* __restrict__ dmat,
    const int*   __restrict__ mask,
    const float* __restrict__ tm_w, const float* __restrict__ tm_b,
    const float* __restrict__ dm_w, const float* __restrict__ dm_b,
    const float* __restrict__ td_w, const float* __restrict__ td_b)
{
    extern __shared__ __half gsm[];
    const int t = threadIdx.x;

    // =================== bias + mask CTAs (MT=128 launch only) ============
    if (MT == 128 && blockIdx.z >= 3) {
        const int cta = (blockIdx.z - 3) * 128 + blockIdx.y * 4 + blockIdx.x; // 0..511
        const float tdb = td_b[0] * LOG2E;
        const float E = 2.718281828459045f;
        const int bz = g_bzero;
        const float Ct = g_Ct, Cd = g_Cd;

        float* sp = (float*)gsm;
        if (!bz) {
            if (t < 64) {
                sp[0*64 + t] = tm_w[t];
                sp[1*64 + t] = tm_b[t];
                sp[2*64 + t] = dm_w[t];
                sp[3*64 + t] = dm_b[t];
                sp[4*64 + t] = td_w[t] * 0.5f * LOG2E;
            }
            __syncthreads();
        }

        #pragma unroll 2
        for (int i = 0; i < 8; i++) {
            const size_t base = (((size_t)cta * 8 + i) * 256 + t) * 4;
            float4 u  = *(const float4*)(tmat + base);
            float4 w4 = *(const float4*)(dmat + base);
            int4   mk = *(const int4*)(mask + base);

            float tv[4] = { 1.f / __logf(E + u.x), 1.f / __logf(E + u.y),
                            1.f / __logf(E + u.z), 1.f / __logf(E + u.w) };
            float dv[4] = { 1.f / __logf(E + w4.x), 1.f / __logf(E + w4.y),
                            1.f / __logf(E + w4.z), 1.f / __logf(E + w4.w) };
            float acc[4];
            if (bz) {
                #pragma unroll
                for (int e = 0; e < 4; e++)
                    acc[e] = fmaf(tv[e], Ct, fmaf(dv[e], Cd, tdb));
            } else {
                #pragma unroll
                for (int e = 0; e < 4; e++) acc[e] = tdb;
                #pragma unroll 8
                for (int m = 0; m < 64; m++) {
                    const float tw = sp[0*64 + m], tb = sp[1*64 + m];
                    const float dw = sp[2*64 + m], db = sp[3*64 + m];
                    const float ww = sp[4*64 + m];
                    #pragma unroll
                    for (int e = 0; e < 4; e++) {
                        float rt = fmaxf(tv[e] * tw + tb, 0.f);
                        float rd = fmaxf(dv[e] * dw + db, 0.f);
                        acc[e] += ww * (rt + rd);
                    }
                }
            }
            float4 o;
            o.x = (mk.x == 1) ? -1.5e9f : acc[0];
            o.y = (mk.y == 1) ? -1.5e9f : acc[1];
            o.z = (mk.z == 1) ? -1.5e9f : acc[2];
            o.w = (mk.w == 1) ? -1.5e9f : acc[3];
            *(float4*)(g_bias + base) = o;
        }
        return;
    }

    // =================== GEMM CTAs ===================
    constexpr int AS = MT * AKP;
    constexpr int WM = (MT == 128) ? 4 : 2;      // m-warps
    constexpr int NP = WM;                        // 16-wide n p-tiles per warp
    __half* Ahs = gsm;                            // [2][AS]
    __half* Als = TWO ? gsm + 2 * AS : nullptr;   // [2][AS]
    __half* Bhs = gsm + (TWO ? 4 : 2) * AS;       // [2][BS]

    const int z = blockIdx.z;
    const __half* Ah = Ah_ + (size_t)z * aStride;
    const __half* Al = TWO ? (Al_ + (size_t)z * aStride) : nullptr;
    const __half* Wh = Wh_ + (size_t)z * wStride;
    const float* bias = (z == 0) ? b0v : (z == 1) ? b1v : b2v;
    __half* Ho = (z == 0) ? H0 : (z == 1) ? H1 : H2;
    const float osc = (z == 0) ? scale0 : 1.f;

    const int lane = t & 31, wid = t >> 5;
    const int warp_m = wid & (WM - 1), warp_n = wid / WM;
    const int m_w = warp_m * 32, n_w = warp_n * (16 * WM);
    const int bm = blockIdx.y * MT, bn = blockIdx.x * 128;
    const int gid = lane >> 2, tig = lane & 3;
    const int m_idx = lane >> 3, rin = lane & 7;

    float acc[2][2 * NP][4];
    #pragma unroll
    for (int mt = 0; mt < 2; mt++)
        #pragma unroll
        for (int nt = 0; nt < 2 * NP; nt++)
            #pragma unroll
            for (int e = 0; e < 4; e++) acc[mt][nt][e] = 0.f;

    auto issue = [&](int st, int k0) {
        // A: MT*4 chunks of 8 halves
        #pragma unroll
        for (int r = 0; r < MT / 64; r++) {
            int c = t + r * 256;
            int arow = c >> 2, ak = (c & 3) * 8;
            size_t ga = (size_t)(bm + arow) * K + k0 + ak;
            cpa16((uint32_t)__cvta_generic_to_shared(&Ahs[st * AS + arow * AKP + ak]), &Ah[ga]);
            if (TWO)
                cpa16((uint32_t)__cvta_generic_to_shared(&Als[st * AS + arow * AKP + ak]), &Al[ga]);
        }
        // B: 512 chunks, 2 per thread
        #pragma unroll
        for (int r = 0; r < 2; r++) {
            int c = t + r * 256;
            int krow = c >> 4, nc = (c & 15) * 8;
            size_t gb = (size_t)(k0 + krow) * N + bn + nc;
            cpa16((uint32_t)__cvta_generic_to_shared(&Bhs[st * BS + krow * BNP + nc]), &Wh[gb]);
        }
    };

    issue(0, 0);
    cp_commit();

    const int NIT = K / 32;
    for (int it = 0; it < NIT; it++) {
        const int st = it & 1;
        if (it + 1 < NIT) {
            issue(st ^ 1, (it + 1) * 32);
            cp_commit();
            cp_wait<1>();
        } else {
            cp_wait<0>();
        }
        __syncthreads();

        #pragma unroll
        for (int kb = 0; kb < 32; kb += 16) {
            uint32_t af[2][2][4];
            #pragma unroll
            for (int mt = 0; mt < 2; mt++) {
                const int arow = m_w + mt * 16 + (lane & 15);
                const int acol = kb + ((lane >> 4) << 3);
                ldsm_x4(af[mt][0][0], af[mt][0][1], af[mt][0][2], af[mt][0][3],
                        (uint32_t)__cvta_generic_to_shared(&Ahs[st * AS + arow * AKP + acol]));
                if (TWO)
                    ldsm_x4(af[mt][1][0], af[mt][1][1], af[mt][1][2], af[mt][1][3],
                            (uint32_t)__cvta_generic_to_shared(&Als[st * AS + arow * AKP + acol]));
            }
            #pragma unroll
            for (int p = 0; p < NP; p++) {
                const int brow = kb + ((m_idx & 1) << 3) + rin;
                const int bcol = n_w + p * 16 + ((m_idx >> 1) << 3);
                uint32_t bh0, bh1, bh2, bh3;
                ldsm_x4_t(bh0, bh1, bh2, bh3,
                    (uint32_t)__cvta_generic_to_shared(&Bhs[st * BS + brow * BNP + bcol]));
                #pragma unroll
                for (int mt = 0; mt < 2; mt++) {
                    mma_f16(acc[mt][2*p], af[mt][0][0], af[mt][0][1],
                            af[mt][0][2], af[mt][0][3], bh0, bh1);
                    mma_f16(acc[mt][2*p+1], af[mt][0][0], af[mt][0][1],
                            af[mt][0][2], af[mt][0][3], bh2, bh3);
                    if (TWO) {
                        mma_f16(acc[mt][2*p], af[mt][1][0], af[mt][1][1],
                                af[mt][1][2], af[mt][1][3], bh0, bh1);
                        mma_f16(acc[mt][2*p+1], af[mt][1][0], af[mt][1][1],
                                af[mt][1][2], af[mt][1][3], bh2, bh3);
                    }
                }
            }
        }
        __syncthreads();
    }

    // ---- epilogue
    #pragma unroll
    for (int mt = 0; mt < 2; mt++) {
        const int row0 = bm + m_w + mt * 16 + gid;
        #pragma unroll
        for (int nt = 0; nt < 2 * NP; nt++) {
            const int col = bn + n_w + nt * 8 + tig * 2;
            float2 bb = *(const float2*)&bias[col];
            float v0 = (acc[mt][nt][0] + bb.x) * osc;
            float v1 = (acc[mt][nt][1] + bb.y) * osc;
            float v2 = (acc[mt][nt][2] + bb.x) * osc;
            float v3 = (acc[mt][nt][3] + bb.y) * osc;
            if (fp16_out) {
                __half2 h01 = __floats2half2_rn(v0, v1);
                __half2 h23 = __floats2half2_rn(v2, v3);
                *(__half2*)&Ho[(size_t)row0 * N + col]       = h01;
                *(__half2*)&Ho[(size_t)(row0 + 8) * N + col] = h23;
            } else {
                *(float2*)&C0[(size_t)row0 * N + col]       = make_float2(v0, v1);
                *(float2*)&C0[(size_t)(row0 + 8) * N + col] = make_float2(v2, v3);
            }
        }
    }
}

#define GSMEM_QKV ((2*(128*AKP) + 2*BS) * 2)   // single A plane
#define GSMEM_O   ((4*(64*AKP)  + 2*BS) * 2)   // hi/lo A planes, MT=64

// ---------------------------------------------------------------------------
// Flash attention, pure fp16 TC, log2-domain softmax, smem-staged bias
// (unchanged from R11).
// ---------------------------------------------------------------------------
#define PS 72
#define PE (64*PS)
#define BSS 68
#define KV0 8704
#define SMEM_ATTN ((KV0 + 4*PE)*2)   // 54272 bytes

__global__ __launch_bounds__(128, 4) void attn_f16()
{
    extern __shared__ __half sm[];
    float* biasS = (float*)sm;

    const int qt = blockIdx.x, h = blockIdx.y, b = blockIdx.z;
    const int t = threadIdx.x;
    const int w = t >> 5, lane = t & 31;
    const int gid = lane >> 2, tig = lane & 3;
    const int q0 = qt * 64, hoff = h * DK_;
    const int tr = w * 16 + gid;
    const int m_idx = lane >> 3, rin = lane & 7;

    #pragma unroll
    for (int i = 0; i < 4; i++) {
        int c = t + i * 128;
        int row = c >> 3, col = (c & 7) * 8;
        size_t gq = (size_t)(b * S_ + q0 + row) * D_ + hoff + col;
        size_t gk = (size_t)(b * S_ + row) * D_ + hoff + col;
        uint32_t so = row * PS + col;
        cpa16((uint32_t)__cvta_generic_to_shared(&sm[so]),            &g_qh[gq]);
        cpa16((uint32_t)__cvta_generic_to_shared(&sm[KV0 + so]),      &g_kh[gk]);
        cpa16((uint32_t)__cvta_generic_to_shared(&sm[KV0 + PE + so]), &g_vh[gk]);
    }
    cp_commit();
    cp_wait<0>();
    __syncthreads();

    uint32_t qf[4][4];
    #pragma unroll
    for (int d8 = 0; d8 < 4; d8++) {
        uint32_t a = (uint32_t)__cvta_generic_to_shared(
            &sm[(w * 16 + (lane & 15)) * PS + d8 * 16 + ((lane >> 4) << 3)]);
        ldsm_x4(qf[d8][0], qf[d8][1], qf[d8][2], qf[d8][3], a);
    }
    __syncthreads();   // Q plane dead -> bias buffer

    float m0 = -1e30f, m1 = -1e30f, l0 = 0.f, l1 = 0.f;
    float oacc[8][4];
    #pragma unroll
    for (int nt = 0; nt < 8; nt++)
        #pragma unroll
        for (int e = 0; e < 4; e++) oacc[nt][e] = 0.f;

    for (int kt = 0; kt < 16; kt++) {
        const int buf = kt & 1;

        #pragma unroll
        for (int i = 0; i < 8; i++) {
            int idx = t + i * 128;
            int row = idx >> 4, c4 = (idx & 15) << 2;
            cpa16((uint32_t)__cvta_generic_to_shared(&biasS[row * BSS + c4]),
                  &g_bias[((size_t)(b * S_ + q0 + row)) * S_ + kt * 64 + c4]);
        }
        cp_commit();

        if (kt < 15) {
            const int k1 = (kt + 1) * 64;
            const int KBn = KV0 + (buf ^ 1) * 2 * PE;
            #pragma unroll
            for (int i = 0; i < 4; i++) {
                int c = t + i * 128;
                int row = c >> 3, col = (c & 7) * 8;
                size_t g = (size_t)(b * S_ + k1 + row) * D_ + hoff + col;
                uint32_t so = row * PS + col;
                cpa16((uint32_t)__cvta_generic_to_shared(&sm[KBn + so]),      &g_kh[g]);
                cpa16((uint32_t)__cvta_generic_to_shared(&sm[KBn + PE + so]), &g_vh[g]);
            }
            cp_commit();
            cp_wait<2>();
        } else {
            cp_wait<1>();
        }
        __syncthreads();

        const int KB = KV0 + buf * 2 * PE;

        float sacc[8][4];
        #pragma unroll
        for (int nt = 0; nt < 8; nt++)
            #pragma unroll
            for (int e = 0; e < 4; e++) sacc[nt][e] = 0.f;

        #pragma unroll
        for (int d8 = 0; d8 < 4; d8++) {
            #pragma unroll
            for (int p = 0; p < 4; p++) {
                uint32_t boff = (p * 16 + ((m_idx & 1) << 3) + rin) * PS
                              + d8 * 16 + ((m_idx >> 1) << 3);
                uint32_t kh0, kh1, kh2, kh3;
                ldsm_x4(kh0, kh1, kh2, kh3,
                        (uint32_t)__cvta_generic_to_shared(&sm[KB + boff]));
                mma_f16(sacc[2*p],   qf[d8][0], qf[d8][1], qf[d8][2], qf[d8][3], kh0, kh2);
                mma_f16(sacc[2*p+1], qf[d8][0], qf[d8][1], qf[d8][2], qf[d8][3], kh1, kh3);
            }
        }

        if (kt < 15) { cp_wait<1>(); } else { cp_wait<0>(); }
        __syncthreads();

        float mx0 = -1e30f, mx1 = -1e30f;
        #pragma unroll
        for (int nt = 0; nt < 8; nt++) {
            float2 ba = *(const float2*)&biasS[tr * BSS + nt * 8 + tig * 2];
            float2 bb = *(const float2*)&biasS[(tr + 8) * BSS + nt * 8 + tig * 2];
            sacc[nt][0] += ba.x;
            sacc[nt][1] += ba.y;
            sacc[nt][2] += bb.x;
            sacc[nt][3] += bb.y;
            mx0 = fmaxf(mx0, fmaxf(sacc[nt][0], sacc[nt][1]));
            mx1 = fmaxf(mx1, fmaxf(sacc[nt][2], sacc[nt][3]));
        }
        mx0 = fmaxf(mx0, __shfl_xor_sync(0xffffffffu, mx0, 1));
        mx0 = fmaxf(mx0, __shfl_xor_sync(0xffffffffu, mx0, 2));
        mx1 = fmaxf(mx1, __shfl_xor_sync(0xffffffffu, mx1, 1));
        mx1 = fmaxf(mx1, __shfl_xor_sync(0xffffffffu, mx1, 2));

        const float mn0 = fmaxf(m0, mx0), mn1 = fmaxf(m1, mx1);
        const float c0 = ex2f(m0 - mn0), c1 = ex2f(m1 - mn1);
        m0 = mn0; m1 = mn1;

        float rs0 = 0.f, rs1 = 0.f;
        #pragma unroll
        for (int nt = 0; nt < 8; nt++) {
            sacc[nt][0] = ex2f(sacc[nt][0] - mn0);
            sacc[nt][1] = ex2f(sacc[nt][1] - mn0);
            sacc[nt][2] = ex2f(sacc[nt][2] - mn1);
            sacc[nt][3] = ex2f(sacc[nt][3] - mn1);
            rs0 += sacc[nt][0] + sacc[nt][1];
            rs1 += sacc[nt][2] + sacc[nt][3];
        }
        rs0 += __shfl_xor_sync(0xffffffffu, rs0, 1);
        rs0 += __shfl_xor_sync(0xffffffffu, rs0, 2);
        rs1 += __shfl_xor_sync(0xffffffffu, rs1, 1);
        rs1 += __shfl_xor_sync(0xffffffffu, rs1, 2);

        l0 = l0 * c0 + rs0;
        l1 = l1 * c1 + rs1;
        #pragma unroll
        for (int nt = 0; nt < 8; nt++) {
            oacc[nt][0] *= c0; oacc[nt][1] *= c0;
            oacc[nt][2] *= c1; oacc[nt][3] *= c1;
        }

        uint32_t pa[4][4];
        #pragma unroll
        for (int j8 = 0; j8 < 4; j8++) {
            const float* sA = sacc[2 * j8];
            const float* sB = sacc[2 * j8 + 1];
            __half2 hh;
            hh = __floats2half2_rn(sA[0], sA[1]); pa[j8][0] = *(uint32_t*)&hh;
            hh = __floats2half2_rn(sA[2], sA[3]); pa[j8][1] = *(uint32_t*)&hh;
            hh = __floats2half2_rn(sB[0], sB[1]); pa[j8][2] = *(uint32_t*)&hh;
            hh = __floats2half2_rn(sB[2], sB[3]); pa[j8][3] = *(uint32_t*)&hh;
        }

        #pragma unroll
        for (int j8 = 0; j8 < 4; j8++) {
            #pragma unroll
            for (int p = 0; p < 4; p++) {
                uint32_t boff = (j8 * 16 + ((m_idx & 1) << 3) + rin) * PS
                              + p * 16 + ((m_idx >> 1) << 3);
                uint32_t vh0, vh1, vh2, vh3;
                ldsm_x4_t(vh0, vh1, vh2, vh3,
                          (uint32_t)__cvta_generic_to_shared(&sm[KB + PE + boff]));
                mma_f16(oacc[2*p],   pa[j8][0], pa[j8][1], pa[j8][2], pa[j8][3], vh0, vh1);
                mma_f16(oacc[2*p+1], pa[j8][0], pa[j8][1], pa[j8][2], pa[j8][3], vh2, vh3);
            }
        }
        __syncthreads();
    }

    const float inv0 = 1.f / l0, inv1 = 1.f / l1;
    const size_t o0 = (size_t)(b * S_ + q0 + tr) * D_ + hoff;
    const size_t o1 = o0 + (size_t)8 * D_;
    #pragma unroll
    for (int nt = 0; nt < 8; nt++) {
        const int coff = nt * 8 + tig * 2;
        uint32_t h01, l01, h23, l23;
        pack_hilo_h(oacc[nt][0] * inv0, oacc[nt][1] * inv0, h01, l01);
        pack_hilo_h(oacc[nt][2] * inv1, oacc[nt][3] * inv1, h23, l23);
        *(uint32_t*)&g_oh[o0 + coff] = h01;
        *(uint32_t*)&g_ol[o0 + coff] = l01;
        *(uint32_t*)&g_oh[o1 + coff] = h23;
        *(uint32_t*)&g_ol[o1 + coff] = l23;
    }
}

// ---------------------------------------------------------------------------
extern "C" void kernel_launch(void* const* d_in, const int* in_sizes, int n_in,
                              void* d_out, int out_size)
{
    const float* Q     = (const float*)d_in[0];
    const float* K     = (const float*)d_in[1];
    const float* V     = (const float*)d_in[2];
    const float* tmat  = (const float*)d_in[3];
    const float* dmat  = (const float*)d_in[4];
    const int*   mask  = (const int*)  d_in[5];
    const float* Wq    = (const float*)d_in[6];
    const float* bq    = (const float*)d_in[7];
    const float* Wk    = (const float*)d_in[8];
    const float* bk    = (const float*)d_in[9];
    const float* Wv    = (const float*)d_in[10];
    const float* bv    = (const float*)d_in[11];
    const float* Wo    = (const float*)d_in[12];
    const float* bo    = (const float*)d_in[13];
    const float* tm_w  = (const float*)d_in[14];
    const float* tm_b  = (const float*)d_in[15];
    const float* dm_w  = (const float*)d_in[16];
    const float* dm_b  = (const float*)d_in[17];
    const float* td_w  = (const float*)d_in[18];
    const float* td_b  = (const float*)d_in[19];
    float* out = (float*)d_out;

    __half *inh, *wh, *oh, *ol, *qh, *kh, *vh;
    cudaGetSymbolAddress((void**)&inh, g_in_h);
    cudaGetSymbolAddress((void**)&wh,  g_w_h);
    cudaGetSymbolAddress((void**)&oh,  g_oh);
    cudaGetSymbolAddress((void**)&ol,  g_ol);
    cudaGetSymbolAddress((void**)&qh,  g_qh);
    cudaGetSymbolAddress((void**)&kh,  g_kh);
    cudaGetSymbolAddress((void**)&vh,  g_vh);

    // split inputs/weights to fp16 + prep coefficients, one launch
    split_all<<<SPLIT_BLKS, 256>>>(
        Q, K, V, Wq, Wk, Wv, Wo, inh, wh, tm_w, tm_b, dm_w, dm_b, td_w);

    cudaFuncSetAttribute(gemm_planes<128, false>,
                         cudaFuncAttributeMaxDynamicSharedMemorySize, GSMEM_QKV);
    cudaFuncSetAttribute(gemm_planes<64, true>,
                         cudaFuncAttributeMaxDynamicSharedMemorySize, GSMEM_O);

    // fused Q/K/V projections (z=0..2) + bias/mask CTAs (z=3..6) in ONE launch
    gemm_planes<128, false><<<dim3(D_ / 128, MTOT / 128, 7), 256, GSMEM_QKV>>>(
        inh, nullptr, wh, (size_t)NELE, (size_t)DD,
        bq, bk, bv,
        out /*unused*/, qh, kh, vh,
        MTOT, D_, D_, 0.125f * LOG2E, 1,
        tmat, dmat, mask, tm_w, tm_b, dm_w, dm_b, td_w, td_b);

    cudaFuncSetAttribute(attn_f16,
                         cudaFuncAttributeMaxDynamicSharedMemorySize, SMEM_ATTN);
    attn_f16<<<dim3(S_ / 64, H_, B_), 128, SMEM_ATTN>>>();

    // output projection: fp16 hi/lo A (attn out), 64x128 tiles -> 256 CTAs
    gemm_planes<64, true><<<dim3(D_ / 128, MTOT / 64, 1), 256, GSMEM_O>>>(
        oh, ol, wh + (size_t)3 * DD, 0, 0,
        bo, bo, bo,
        out, qh, kh, vh,
        MTOT, D_, D_, 1.f, 0,
        tmat, dmat, mask, tm_w, tm_b, dm_w, dm_b, td_w, td_b);
}